// round 6
// baseline (speedup 1.0000x reference)
#include <cuda_runtime.h>
#include <cuda_fp16.h>
#include <cstdint>
#include <math.h>

#define B_ 8
#define C_ 2048
#define F_ 512
#define THRESH 0.005f

// ---- scratch (device globals: no allocation allowed) ----
__device__ char   g_A[(size_t)B_ * C_ * C_];       // binary adjacency (s8 0/1, k-permuted)
__device__ float  g_invn[B_ * C_];
__device__ float  g_deg[B_ * C_];
__device__ float  g_dinv[B_ * C_];
__device__ float  g_colmax[B_ * F_];
__device__ __half g_xhi[(size_t)B_ * C_ * F_];
__device__ __half g_xlo[(size_t)B_ * C_ * F_];
__device__ char   g_l0[(size_t)B_ * F_ * C_];      // h' limb0 s8, [b][f][perm(c)]
__device__ char   g_l1[(size_t)B_ * F_ * C_];      // h' limb1 s8
__device__ __half g_lx_hi[(size_t)B_ * C_ * F_];   // L@h split
__device__ __half g_lx_lo[(size_t)B_ * C_ * F_];
__device__ float  g_h2[(size_t)B_ * C_ * F_];      // hidden activations

// =============================== helpers ===============================
__device__ __forceinline__ uint32_t smem_u32(const void* p) {
    uint32_t a;
    asm("{ .reg .u64 t; cvta.to.shared.u64 t, %1; cvt.u32.u64 %0, t; }" : "=r"(a) : "l"(p));
    return a;
}
#define CP_COMMIT() asm volatile("cp.async.commit_group;" ::: "memory")
#define CP_WAIT1()  asm volatile("cp.async.wait_group 1;" ::: "memory")
#define CP_WAIT0()  asm volatile("cp.async.wait_group 0;" ::: "memory")

__device__ __forceinline__ void mma_f16(float c[4], const uint32_t a[4], const uint32_t b[2]) {
    asm volatile(
        "mma.sync.aligned.m16n8k16.row.col.f32.f16.f16.f32 "
        "{%0,%1,%2,%3}, {%4,%5,%6,%7}, {%8,%9}, {%0,%1,%2,%3};"
        : "+f"(c[0]), "+f"(c[1]), "+f"(c[2]), "+f"(c[3])
        : "r"(a[0]), "r"(a[1]), "r"(a[2]), "r"(a[3]), "r"(b[0]), "r"(b[1]));
}
__device__ __forceinline__ void mma_s8(int c[4], const uint32_t a[4], const uint32_t b[2]) {
    asm volatile(
        "mma.sync.aligned.m16n8k32.row.col.s32.s8.s8.s32 "
        "{%0,%1,%2,%3}, {%4,%5,%6,%7}, {%8,%9}, {%0,%1,%2,%3};"
        : "+r"(c[0]), "+r"(c[1]), "+r"(c[2]), "+r"(c[3])
        : "r"(a[0]), "r"(a[1]), "r"(a[2]), "r"(a[3]), "r"(b[0]), "r"(b[1]));
}
__device__ __forceinline__ void ldsm4(uint32_t r[4], uint32_t addr) {
    asm volatile("ldmatrix.sync.aligned.m8n8.x4.shared.b16 {%0,%1,%2,%3}, [%4];"
        : "=r"(r[0]), "=r"(r[1]), "=r"(r[2]), "=r"(r[3]) : "r"(addr));
}
__device__ __forceinline__ void lds64(uint32_t& lo, uint32_t& hi, uint32_t addr) {
    asm volatile("ld.shared.v2.b32 {%0,%1}, [%2];" : "=r"(lo), "=r"(hi) : "r"(addr));
}
// k-permutation within a 32-block: original k -> position, so that positions
// 8t..8t+3 hold k=4t..4t+3 and 8t+4..8t+7 hold k=16+4t..19+4t.
__device__ __forceinline__ int kperm32(int w) {
    return ((w >> 2) & 3) * 8 + ((w >> 4) & 1) * 4 + (w & 3);
}

// ====================== fp16 mma GEMM (128x128 tile, KC=32) ======================
// MODE 0: GRAM (symmetric blocks) acc = xhi·xhiT + xhi·xloT + xlo·xhiT
//         epi: binarize; write A as s8 (k-permuted) tile + mirror; degree atomics
// MODE 2: HW   acc = 3-pass split; epi: relu(+bias) -> fp32
#define KC 32
#define TPAD 40
#define TEH (128 * TPAD)

template <int MODE>
__global__ __launch_bounds__(256, 2) void mma_gemm(
    const __half* __restrict__ a0, const __half* __restrict__ a1,
    const __half* __restrict__ b0, const __half* __restrict__ b1,
    int lda, int ldb, int K,
    size_t aBatch, size_t bBatch,
    const float* __restrict__ aux, int auxBatch,
    void* __restrict__ out0,
    int ldo, size_t oBatch,
    float* __restrict__ deg)
{
    constexpr int NOPS = 4;

    int m0, n0, b = blockIdx.z;
    if (MODE == 0) {
        int idx = blockIdx.x, bi = 0;
        while (idx >= (C_ / 128 - bi)) { idx -= (C_ / 128 - bi); bi++; }
        m0 = bi * 128; n0 = (bi + idx) * 128;
    } else {
        m0 = blockIdx.y * 128; n0 = blockIdx.x * 128;
    }

    int tid = threadIdx.x, wid = tid >> 5, lane = tid & 31;
    int wm = wid & 1, wn = wid >> 1;          // warp tile 64x32
    int g = lane >> 2, t = lane & 3;

    const __half* ops[NOPS];
    int ldv[NOPS];
    ops[0] = a0 + (size_t)b * aBatch + (size_t)m0 * lda; ldv[0] = lda;
    ops[1] = a1 + (size_t)b * aBatch + (size_t)m0 * lda; ldv[1] = lda;
    ops[2] = b0 + (size_t)b * bBatch + (size_t)n0 * ldb; ldv[2] = ldb;
    ops[3] = b1 + (size_t)b * bBatch + (size_t)n0 * ldb; ldv[3] = ldb;

    extern __shared__ __half sm[];
    uint32_t smb = smem_u32(sm);

    auto load_tile = [&](int op, int buf, int k0) {
        uint32_t st = smb + (uint32_t)((buf * NOPS + op) * TEH) * 2u;
        const __half* src = ops[op] + k0;
        int ld = ldv[op];
#pragma unroll
        for (int i2 = 0; i2 < 2; i2++) {
            int idx = tid + i2 * 256;
            int row = idx >> 2, seg = idx & 3;
            const __half* gp = src + (size_t)row * ld + seg * 8;
            uint32_t sa = st + (uint32_t)(row * TPAD + seg * 8) * 2u;
            asm volatile("cp.async.cg.shared.global [%0], [%1], 16;" :: "r"(sa), "l"(gp) : "memory");
        }
    };

    float acc[4][4][4];
#pragma unroll
    for (int i = 0; i < 4; i++)
#pragma unroll
        for (int j = 0; j < 4; j++)
#pragma unroll
            for (int r = 0; r < 4; r++) acc[i][j][r] = 0.f;

    int a_row = ((lane >> 3) & 1) * 8 + (lane & 7);
    int a_kc  = (lane >> 4) * 8;
    int b_row = ((lane >> 4) & 1) * 8 + (lane & 7);
    int b_kc  = ((lane >> 3) & 1) * 8;

    uint32_t afr[2][4][4];
    uint32_t bfr[4][2];

    const int NC = K / KC;
    for (int op = 0; op < NOPS; op++) load_tile(op, 0, 0);
    CP_COMMIT();

    for (int c = 0; c < NC; c++) {
        int buf = c & 1;
        if (c + 1 < NC) {
            for (int op = 0; op < NOPS; op++) load_tile(op, (c + 1) & 1, (c + 1) * KC);
            CP_COMMIT();
            CP_WAIT1();
        } else {
            CP_WAIT0();
        }
        __syncthreads();
#pragma unroll
        for (int ks = 0; ks < 2; ks++) {
            int kk = ks * 16;
            uint32_t ab0 = smb + (uint32_t)((buf * NOPS + 0) * TEH + (wm * 64 + a_row) * TPAD + kk + a_kc) * 2u;
#pragma unroll
            for (int i = 0; i < 4; i++) ldsm4(afr[0][i], ab0 + (uint32_t)(i * 16 * TPAD) * 2u);
            uint32_t ab1 = smb + (uint32_t)((buf * NOPS + 1) * TEH + (wm * 64 + a_row) * TPAD + kk + a_kc) * 2u;
#pragma unroll
            for (int i = 0; i < 4; i++) ldsm4(afr[1][i], ab1 + (uint32_t)(i * 16 * TPAD) * 2u);
            uint32_t bb0 = smb + (uint32_t)((buf * NOPS + 2) * TEH + (wn * 32 + b_row) * TPAD + kk + b_kc) * 2u;
            ldsm4(&bfr[0][0], bb0);
            ldsm4(&bfr[2][0], bb0 + (uint32_t)(16 * TPAD) * 2u);
#pragma unroll
            for (int i = 0; i < 4; i++)
#pragma unroll
                for (int j = 0; j < 4; j++) mma_f16(acc[i][j], afr[0][i], bfr[j]);
#pragma unroll
            for (int i = 0; i < 4; i++)
#pragma unroll
                for (int j = 0; j < 4; j++) mma_f16(acc[i][j], afr[1][i], bfr[j]);
            uint32_t bb1 = smb + (uint32_t)((buf * NOPS + 3) * TEH + (wn * 32 + b_row) * TPAD + kk + b_kc) * 2u;
            ldsm4(&bfr[0][0], bb1);
            ldsm4(&bfr[2][0], bb1 + (uint32_t)(16 * TPAD) * 2u);
#pragma unroll
            for (int i = 0; i < 4; i++)
#pragma unroll
                for (int j = 0; j < 4; j++) mma_f16(acc[i][j], afr[0][i], bfr[j]);
        }
        __syncthreads();
    }

    // ------------------------------- epilogues -------------------------------
    if (MODE == 0) {
        const float* inb = aux + (size_t)b * auxBatch;
        char* Ab = (char*)out0 + (size_t)b * oBatch;
        float* degb = deg + (size_t)b * C_;
        float v[4][4][4];
        int offc = wn * 32;                    // 32-aligned base of this warp's cols
#pragma unroll
        for (int i = 0; i < 4; i++) {
            int r0 = m0 + wm * 64 + i * 16 + g;
            float rs0 = inb[r0], rs1 = inb[r0 + 8];
#pragma unroll
            for (int j = 0; j < 4; j++) {
                int cl = n0 + wn * 32 + j * 8 + t * 2;
                float j0 = inb[cl], j1 = inb[cl + 1];
                v[i][j][0] = (acc[i][j][0] * rs0 * j0 > THRESH) ? 1.f : 0.f;
                v[i][j][1] = (acc[i][j][1] * rs0 * j1 > THRESH) ? 1.f : 0.f;
                v[i][j][2] = (acc[i][j][2] * rs1 * j0 > THRESH) ? 1.f : 0.f;
                v[i][j][3] = (acc[i][j][3] * rs1 * j1 > THRESH) ? 1.f : 0.f;
                int pc = n0 + offc + kperm32(j * 8 + t * 2);
                unsigned short w0 = (unsigned short)((v[i][j][0] != 0.f ? 1u : 0u) |
                                                     ((v[i][j][1] != 0.f ? 1u : 0u) << 8));
                unsigned short w1 = (unsigned short)((v[i][j][2] != 0.f ? 1u : 0u) |
                                                     ((v[i][j][3] != 0.f ? 1u : 0u) << 8));
                *(unsigned short*)(Ab + (size_t)r0 * ldo + pc)       = w0;
                *(unsigned short*)(Ab + (size_t)(r0 + 8) * ldo + pc) = w1;
            }
        }
        // degrees: row sums
#pragma unroll
        for (int i = 0; i < 4; i++) {
            float s0 = 0.f, s1 = 0.f;
#pragma unroll
            for (int j = 0; j < 4; j++) {
                s0 += v[i][j][0] + v[i][j][1];
                s1 += v[i][j][2] + v[i][j][3];
            }
            s0 += __shfl_xor_sync(0xFFFFFFFFu, s0, 1); s0 += __shfl_xor_sync(0xFFFFFFFFu, s0, 2);
            s1 += __shfl_xor_sync(0xFFFFFFFFu, s1, 1); s1 += __shfl_xor_sync(0xFFFFFFFFu, s1, 2);
            if (t == 0) {
                atomicAdd(&degb[m0 + wm * 64 + i * 16 + g], s0);
                atomicAdd(&degb[m0 + wm * 64 + i * 16 + g + 8], s1);
            }
        }
        if (m0 != n0) {
            // degrees: column sums
#pragma unroll
            for (int j = 0; j < 4; j++) {
                float c0 = 0.f, c1 = 0.f;
#pragma unroll
                for (int i = 0; i < 4; i++) {
                    c0 += v[i][j][0] + v[i][j][2];
                    c1 += v[i][j][1] + v[i][j][3];
                }
                c0 += __shfl_xor_sync(0xFFFFFFFFu, c0, 4); c0 += __shfl_xor_sync(0xFFFFFFFFu, c0, 8); c0 += __shfl_xor_sync(0xFFFFFFFFu, c0, 16);
                c1 += __shfl_xor_sync(0xFFFFFFFFu, c1, 4); c1 += __shfl_xor_sync(0xFFFFFFFFu, c1, 8); c1 += __shfl_xor_sync(0xFFFFFFFFu, c1, 16);
                if (lane < 4) {
                    atomicAdd(&degb[n0 + wn * 32 + j * 8 + t * 2], c0);
                    atomicAdd(&degb[n0 + wn * 32 + j * 8 + t * 2 + 1], c1);
                }
            }
            // mirror write via smem stage
            float* stage = (float*)sm;
#pragma unroll
            for (int i = 0; i < 4; i++) {
                int rr = wm * 64 + i * 16 + g;
#pragma unroll
                for (int j = 0; j < 4; j++) {
                    int cc = wn * 32 + j * 8 + t * 2;
                    stage[rr * 129 + cc]           = v[i][j][0];
                    stage[rr * 129 + cc + 1]       = v[i][j][1];
                    stage[(rr + 8) * 129 + cc]     = v[i][j][2];
                    stage[(rr + 8) * 129 + cc + 1] = v[i][j][3];
                }
            }
            __syncthreads();
#pragma unroll
            for (int q = 0; q < 16; q++) {
                int idx = tid + q * 256;               // 0..4095
                int r = idx >> 5;
                int c4 = (idx & 31) * 4;               // 0..124, 4-aligned
                uint32_t w = (stage[(c4 + 0) * 129 + r] != 0.f ? 1u : 0u)
                           | (stage[(c4 + 1) * 129 + r] != 0.f ? 1u : 0u) << 8
                           | (stage[(c4 + 2) * 129 + r] != 0.f ? 1u : 0u) << 16
                           | (stage[(c4 + 3) * 129 + r] != 0.f ? 1u : 0u) << 24;
                int blkbase = c4 & ~31;
                int pc4 = blkbase + (((c4 & 31) >> 2) & 3) * 8 + (((c4 & 31) >> 4) & 1) * 4;
                *(uint32_t*)(Ab + (size_t)(n0 + r) * ldo + m0 + pc4) = w;
            }
        }
    } else {
        float bias = aux[0];
        float* o = (float*)out0;
#pragma unroll
        for (int i = 0; i < 4; i++) {
            int r0 = m0 + wm * 64 + i * 16 + g;
#pragma unroll
            for (int j = 0; j < 4; j++) {
                int cl = n0 + wn * 32 + j * 8 + t * 2;
                float v00 = fmaxf(acc[i][j][0] + bias, 0.f);
                float v01 = fmaxf(acc[i][j][1] + bias, 0.f);
                float v10 = fmaxf(acc[i][j][2] + bias, 0.f);
                float v11 = fmaxf(acc[i][j][3] + bias, 0.f);
                *(float2*)(o + (size_t)r0 * ldo + cl)       = make_float2(v00, v01);
                *(float2*)(o + (size_t)(r0 + 8) * ldo + cl) = make_float2(v10, v11);
            }
        }
    }
}

// ====================== IMMA A@h' kernel (CTA 128x64, warp 32x32) ======================
// out[m,f] = dinv[m] * (cmax_f/127) * (acc0[m,f] + acc1[m,f]/252), split fp16 hi/lo.
__global__ __launch_bounds__(256, 2) void imma_ah(
    const char* __restrict__ Aadj, const char* __restrict__ l0g, const char* __restrict__ l1g,
    const float* __restrict__ dinv, const float* __restrict__ colmax,
    __half* __restrict__ ohi, __half* __restrict__ olo)
{
    int b = blockIdx.z, m0 = blockIdx.y * 128, n0 = blockIdx.x * 64;
    const char* Ab = Aadj + ((size_t)b * C_ + m0) * (size_t)C_;
    const char* Bl0 = l0g + ((size_t)b * F_ + n0) * (size_t)C_;
    const char* Bl1 = l1g + ((size_t)b * F_ + n0) * (size_t)C_;
    int tid = threadIdx.x, wid = tid >> 5, lane = tid & 31;
    int wm = wid & 3, wn = wid >> 2;          // warp tile 32x32 at (wm*32, wn*32)
    int g = lane >> 2, t = lane & 3;

    __shared__ __align__(16) char sm[2 * 8192];   // per buf: A 4096 | B0 2048 | B1 2048
    uint32_t smb = smem_u32(sm);

    auto load_tile = [&](int buf, int k0) {
        uint32_t base = smb + (uint32_t)buf * 8192u;
        {   // A: 128 rows x 32B
            int row = tid >> 1, half = (tid & 1) * 16;
            const char* gp = Ab + (size_t)row * C_ + k0 + half;
            uint32_t sa = base + (uint32_t)(row * 32 + half);
            asm volatile("cp.async.cg.shared.global [%0], [%1], 16;" :: "r"(sa), "l"(gp) : "memory");
        }
        {   // B limbs: 64 rows x 32B each
            int r2 = tid & 127;
            int row = r2 >> 1, half = (r2 & 1) * 16;
            const char* gp = (tid < 128 ? Bl0 : Bl1) + (size_t)row * C_ + k0 + half;
            uint32_t sa = base + 4096u + (tid < 128 ? 0u : 2048u) + (uint32_t)(row * 32 + half);
            asm volatile("cp.async.cg.shared.global [%0], [%1], 16;" :: "r"(sa), "l"(gp) : "memory");
        }
    };

    int acc[2][2][4][4];                       // [limb][mtile][ntile][4]
#pragma unroll
    for (int l = 0; l < 2; l++)
#pragma unroll
        for (int i = 0; i < 2; i++)
#pragma unroll
            for (int j = 0; j < 4; j++)
#pragma unroll
                for (int r = 0; r < 4; r++) acc[l][i][j][r] = 0;

    const int NC = C_ / 32;                    // 64
    load_tile(0, 0);
    CP_COMMIT();

    for (int c = 0; c < NC; c++) {
        int buf = c & 1;
        if (c + 1 < NC) {
            load_tile(buf ^ 1, (c + 1) * 32);
            CP_COMMIT();
            CP_WAIT1();
        } else {
            CP_WAIT0();
        }
        __syncthreads();
        uint32_t base = smb + (uint32_t)buf * 8192u;

        uint32_t af[2][4];
#pragma unroll
        for (int i = 0; i < 2; i++) {
            int row = wm * 32 + i * 16 + g;
            lds64(af[i][0], af[i][2], base + (uint32_t)(row * 32 + 8 * t));
            lds64(af[i][1], af[i][3], base + (uint32_t)((row + 8) * 32 + 8 * t));
        }
#pragma unroll
        for (int l = 0; l < 2; l++) {
            uint32_t bb = base + 4096u + (uint32_t)l * 2048u;
            uint32_t bf[4][2];
#pragma unroll
            for (int j = 0; j < 4; j++) {
                int row = wn * 32 + j * 8 + g;
                lds64(bf[j][0], bf[j][1], bb + (uint32_t)(row * 32 + 8 * t));
            }
#pragma unroll
            for (int i = 0; i < 2; i++)
#pragma unroll
                for (int j = 0; j < 4; j++) mma_s8(acc[l][i][j], af[i], bf[j]);
        }
        __syncthreads();
    }

    // epilogue: combine limbs, scale, split fp16 hi/lo
    const float* db = dinv + b * C_;
    const float* cm = colmax + b * F_;
    const float inv252 = 1.f / 252.f, inv127 = 1.f / 127.f;
#pragma unroll
    for (int i = 0; i < 2; i++) {
        int r0 = m0 + wm * 32 + i * 16 + g;
        float d0 = db[r0], d1 = db[r0 + 8];
#pragma unroll
        for (int j = 0; j < 4; j++) {
            int col = n0 + wn * 32 + j * 8 + t * 2;
            float cs0 = cm[col] * inv127, cs1 = cm[col + 1] * inv127;
            float v00 = ((float)acc[0][i][j][0] + (float)acc[1][i][j][0] * inv252) * cs0 * d0;
            float v01 = ((float)acc[0][i][j][1] + (float)acc[1][i][j][1] * inv252) * cs1 * d0;
            float v10 = ((float)acc[0][i][j][2] + (float)acc[1][i][j][2] * inv252) * cs0 * d1;
            float v11 = ((float)acc[0][i][j][3] + (float)acc[1][i][j][3] * inv252) * cs1 * d1;
            __half h00 = __float2half_rn(v00), h01 = __float2half_rn(v01);
            __half h10 = __float2half_rn(v10), h11 = __float2half_rn(v11);
            size_t o0 = ((size_t)b * C_ + r0) * F_ + col;
            size_t o1 = ((size_t)b * C_ + r0 + 8) * F_ + col;
            *(__half2*)(ohi + o0) = __halves2half2(h00, h01);
            *(__half2*)(ohi + o1) = __halves2half2(h10, h11);
            *(__half2*)(olo + o0) = __floats2half2_rn(v00 - __half2float(h00), v01 - __half2float(h01));
            *(__half2*)(olo + o1) = __floats2half2_rn(v10 - __half2float(h10), v11 - __half2float(h11));
        }
    }
}

// =============================== small kernels ==============================
__global__ void zero_kernel(float* __restrict__ p) {
    p[blockIdx.x * 256 + threadIdx.x] = 0.f;
}

__global__ void norm_kernel(const float* __restrict__ x, float* __restrict__ invn) {
    int row = blockIdx.x;
    const float* xr = x + (size_t)row * F_;
    float s = 0.f;
    for (int i = threadIdx.x; i < F_; i += 128) { float v = xr[i]; s += v * v; }
    __shared__ float red[128];
    red[threadIdx.x] = s; __syncthreads();
    for (int o = 64; o > 0; o >>= 1) {
        if (threadIdx.x < o) red[threadIdx.x] += red[threadIdx.x + o];
        __syncthreads();
    }
    if (threadIdx.x == 0) invn[row] = 1.0f / sqrtf(red[0]);
}

__global__ void split_kernel(const float* __restrict__ x,
                             __half* __restrict__ hi, __half* __restrict__ lo) {
    size_t i = (size_t)blockIdx.x * 256 + threadIdx.x;
    float v = x[i];
    __half h = __float2half_rn(v);
    hi[i] = h;
    lo[i] = __float2half_rn(v - __half2float(h));
}

__global__ void dinv_kernel(const float* __restrict__ deg, float* __restrict__ dinv) {
    int i = blockIdx.x * 256 + threadIdx.x;
    dinv[i] = 1.0f / sqrtf(deg[i]);
}

// per-(b,f) max over c of |h[b,c,f]| * dinv[b,c]  (segmented + atomicMax on int)
__global__ void colmax_kernel(const float* __restrict__ h, const float* __restrict__ dinv,
                              float* __restrict__ colmax) {
    int b = blockIdx.z;
    int f = blockIdx.x * 256 + threadIdx.x;
    int cseg = blockIdx.y * 256;
    const float* hb = h + ((size_t)b * C_ + cseg) * F_;
    const float* db = dinv + b * C_ + cseg;
    float m = 0.f;
    for (int c = 0; c < 256; c++)
        m = fmaxf(m, fabsf(hb[(size_t)c * F_ + f]) * db[c]);
    atomicMax((int*)(colmax + (size_t)b * F_ + f), __float_as_int(m));
}

// h[b,c,f] * dinv[b,c] -> quantized limbs, transposed + k-permuted: l0/l1[b][f][perm(c)]
__global__ void quant_transpose(const float* __restrict__ h, const float* __restrict__ dinv,
                                const float* __restrict__ colmax,
                                char* __restrict__ l0, char* __restrict__ l1) {
    __shared__ float tsm[32][33];
    int c0 = blockIdx.x * 32, f0 = blockIdx.y * 32, b = blockIdx.z;
    const float* hb = h + (size_t)b * C_ * F_;
    int tx = threadIdx.x, ty = threadIdx.y;
#pragma unroll
    for (int k = 0; k < 4; k++) {
        int c = c0 + ty + k * 8;
        tsm[tx][ty + k * 8] = hb[(size_t)c * F_ + f0 + tx] * dinv[b * C_ + c];
    }
    __syncthreads();
    int pc = kperm32(tx);
#pragma unroll
    for (int k = 0; k < 4; k++) {
        int f = f0 + ty + k * 8;
        float cmx = colmax[(size_t)b * F_ + f];
        float qs = cmx > 0.f ? 127.f / cmx : 0.f;
        float q = tsm[ty + k * 8][tx] * qs;
        float L0 = fminf(fmaxf(rintf(q), -127.f), 127.f);
        float L1 = rintf((q - L0) * 252.f);
        size_t o = ((size_t)b * F_ + f) * C_ + c0 + pc;
        l0[o] = (char)(int)L0;
        l1[o] = (char)(int)L1;
    }
}

// W[f,g] -> WT[g,f] split (fp16)
__global__ void wtrans_kernel(const float* __restrict__ W,
                              __half* __restrict__ hi, __half* __restrict__ lo) {
    __shared__ float tsm[32][33];
    int g0 = blockIdx.x * 32, f0 = blockIdx.y * 32;
#pragma unroll
    for (int k = 0; k < 4; k++) {
        int f = f0 + threadIdx.y + k * 8;
        tsm[threadIdx.x][threadIdx.y + k * 8] = W[(size_t)f * F_ + g0 + threadIdx.x];
    }
    __syncthreads();
#pragma unroll
    for (int k = 0; k < 4; k++) {
        int gg = g0 + threadIdx.y + k * 8;
        float v = tsm[threadIdx.y + k * 8][threadIdx.x];
        __half hh = __float2half_rn(v);
        size_t o = (size_t)gg * F_ + f0 + threadIdx.x;
        hi[o] = hh;
        lo[o] = __float2half_rn(v - __half2float(hh));
    }
}

__device__ __half g_WT_hi[F_ * F_];
__device__ __half g_WT_lo[F_ * F_];

// ============================================================================
extern "C" void kernel_launch(void* const* d_in, const int* in_sizes, int n_in,
                              void* d_out, int out_size) {
    const float* x  = (const float*)d_in[0];
    const float* W1 = (const float*)d_in[1];
    const float* b1 = (const float*)d_in[2];
    const float* W2 = (const float*)d_in[3];
    const float* b2 = (const float*)d_in[4];
    float* out = (float*)d_out;

    char *pA, *pl0, *pl1;
    __half *pxhi, *pxlo, *plxhi, *plxlo, *pWThi, *pWTlo;
    float *pinvn, *pdeg, *pdinv, *ph2, *pcmax;
    cudaGetSymbolAddress((void**)&pA,    g_A);
    cudaGetSymbolAddress((void**)&pinvn, g_invn);
    cudaGetSymbolAddress((void**)&pdeg,  g_deg);
    cudaGetSymbolAddress((void**)&pdinv, g_dinv);
    cudaGetSymbolAddress((void**)&pcmax, g_colmax);
    cudaGetSymbolAddress((void**)&pxhi,  g_xhi);
    cudaGetSymbolAddress((void**)&pxlo,  g_xlo);
    cudaGetSymbolAddress((void**)&pl0,   g_l0);
    cudaGetSymbolAddress((void**)&pl1,   g_l1);
    cudaGetSymbolAddress((void**)&plxhi, g_lx_hi);
    cudaGetSymbolAddress((void**)&plxlo, g_lx_lo);
    cudaGetSymbolAddress((void**)&ph2,   g_h2);
    cudaGetSymbolAddress((void**)&pWThi, g_WT_hi);
    cudaGetSymbolAddress((void**)&pWTlo, g_WT_lo);

    const int smem4 = 4 * 2 * TEH * 2;
    cudaFuncSetAttribute(mma_gemm<0>, cudaFuncAttributeMaxDynamicSharedMemorySize, smem4);
    cudaFuncSetAttribute(mma_gemm<2>, cudaFuncAttributeMaxDynamicSharedMemorySize, smem4);

    const int NBLK = C_ / 128;
    const int NTRI = NBLK * (NBLK + 1) / 2;

    // ---- Laplacian ----
    zero_kernel<<<(B_ * C_) / 256, 256>>>(pdeg);
    norm_kernel<<<B_ * C_, 128>>>(x, pinvn);
    split_kernel<<<(B_ * C_ * F_) / 256, 256>>>(x, pxhi, pxlo);
    mma_gemm<0><<<dim3(NTRI, 1, B_), 256, smem4>>>(
        pxhi, pxlo, pxhi, pxlo, F_, F_, F_,
        (size_t)C_ * F_, (size_t)C_ * F_, pinvn, C_,
        pA, C_, (size_t)C_ * C_, pdeg);
    dinv_kernel<<<(B_ * C_) / 256, 256>>>(pdeg, pdinv);

    // ---- layer 1 ----
    zero_kernel<<<(B_ * F_) / 256, 256>>>(pcmax);
    colmax_kernel<<<dim3(F_ / 256, C_ / 256, B_), 256>>>(x, pdinv, pcmax);
    quant_transpose<<<dim3(C_ / 32, F_ / 32, B_), dim3(32, 8)>>>(x, pdinv, pcmax, pl0, pl1);
    imma_ah<<<dim3(F_ / 64, C_ / 128, B_), 256>>>(pA, pl0, pl1, pdinv, pcmax, plxhi, plxlo);
    wtrans_kernel<<<dim3(F_ / 32, F_ / 32), dim3(32, 8)>>>(W1, pWThi, pWTlo);
    mma_gemm<2><<<dim3(F_ / 128, (B_ * C_) / 128, 1), 256, smem4>>>(
        plxhi, plxlo, pWThi, pWTlo, F_, F_, F_,
        0, 0, b1, 0,
        ph2, F_, 0, nullptr);

    // ---- layer 2 ----
    zero_kernel<<<(B_ * F_) / 256, 256>>>(pcmax);
    colmax_kernel<<<dim3(F_ / 256, C_ / 256, B_), 256>>>(ph2, pdinv, pcmax);
    quant_transpose<<<dim3(C_ / 32, F_ / 32, B_), dim3(32, 8)>>>(ph2, pdinv, pcmax, pl0, pl1);
    imma_ah<<<dim3(F_ / 64, C_ / 128, B_), 256>>>(pA, pl0, pl1, pdinv, pcmax, plxhi, plxlo);
    wtrans_kernel<<<dim3(F_ / 32, F_ / 32), dim3(32, 8)>>>(W2, pWThi, pWTlo);
    mma_gemm<2><<<dim3(F_ / 128, (B_ * C_) / 128, 1), 256, smem4>>>(
        plxhi, plxlo, pWThi, pWTlo, F_, F_, F_,
        0, 0, b2, 0,
        out, F_, 0, nullptr);
}

// round 7
// speedup vs baseline: 3.0345x; 3.0345x over previous
#include <cuda_runtime.h>
#include <cuda_fp16.h>
#include <cstdint>
#include <math.h>

#define B_ 8
#define C_ 2048
#define F_ 512
#define THRESH 0.005f

// ---- scratch (device globals: no allocation allowed) ----
__device__ __half g_A[(size_t)B_ * C_ * C_];       // binary adjacency (fp16 0/1)
__device__ float  g_invn[B_ * C_];
__device__ float  g_deg[B_ * C_];
__device__ float  g_dinv[B_ * C_];
__device__ __half g_xhi[(size_t)B_ * C_ * F_];
__device__ __half g_xlo[(size_t)B_ * C_ * F_];
__device__ __half g_hT_hi[(size_t)B_ * F_ * C_];   // (dinv*h)^T split
__device__ __half g_hT_lo[(size_t)B_ * F_ * C_];
__device__ __half g_lx_hi[(size_t)B_ * C_ * F_];   // L@h split
__device__ __half g_lx_lo[(size_t)B_ * C_ * F_];
__device__ float  g_h2[(size_t)B_ * C_ * F_];      // hidden activations
__device__ __half g_WT_hi[F_ * F_];
__device__ __half g_WT_lo[F_ * F_];

// =============================== helpers ===============================
__device__ __forceinline__ uint32_t smem_u32(const void* p) {
    uint32_t a;
    asm("{ .reg .u64 t; cvta.to.shared.u64 t, %1; cvt.u32.u64 %0, t; }" : "=r"(a) : "l"(p));
    return a;
}
#define CP_COMMIT() asm volatile("cp.async.commit_group;" ::: "memory")
#define CP_WAIT1()  asm volatile("cp.async.wait_group 1;" ::: "memory")
#define CP_WAIT0()  asm volatile("cp.async.wait_group 0;" ::: "memory")

__device__ __forceinline__ void mma_f16(float c[4], const uint32_t a[4], const uint32_t b[2]) {
    asm volatile(
        "mma.sync.aligned.m16n8k16.row.col.f32.f16.f16.f32 "
        "{%0,%1,%2,%3}, {%4,%5,%6,%7}, {%8,%9}, {%0,%1,%2,%3};"
        : "+f"(c[0]), "+f"(c[1]), "+f"(c[2]), "+f"(c[3])
        : "r"(a[0]), "r"(a[1]), "r"(a[2]), "r"(a[3]), "r"(b[0]), "r"(b[1]));
}
__device__ __forceinline__ void ldsm4(uint32_t r[4], uint32_t addr) {
    asm volatile("ldmatrix.sync.aligned.m8n8.x4.shared.b16 {%0,%1,%2,%3}, [%4];"
        : "=r"(r[0]), "=r"(r[1]), "=r"(r[2]), "=r"(r[3]) : "r"(addr));
}
// swizzled byte offset inside one 128x32-half tile (64B rows, 4 x 16B segs)
__device__ __forceinline__ uint32_t swz(int row, int seg) {
    return (uint32_t)(row * 64 + ((seg ^ ((row >> 1) & 3)) << 4));
}

// ====================== fp16 mma GEMM (128x128 tile, KC=32, 3-stage) ======================
// All operands row-major with K contiguous: Aop[m][k] (lda), Bop[n][k] (ldb).
// MODE 0: GRAM (symmetric blocks) acc = xhi·xhiT + xhi·xloT + xlo·xhiT
//         epi: binarize; write A tile + mirror; degree atomics
// MODE 1: AH   acc = A·hThiT + A·hTloT ; epi: *dinv[m], split -> fp16 hi/lo
// MODE 2: HW   acc = 3-pass split      ; epi: relu(+bias) -> fp32
#define KC 32
#define NST 3
#define TILEB 8192                 // bytes per tile (128 rows x 64B)

template <int MODE>
__global__ __launch_bounds__(256, 2) void mma_gemm(
    const __half* __restrict__ a0, const __half* __restrict__ a1,
    const __half* __restrict__ b0, const __half* __restrict__ b1,
    int lda, int ldb, int K,
    size_t aBatch, size_t bBatch,
    const float* __restrict__ aux, int auxBatch,
    void* __restrict__ out0, void* __restrict__ out1,
    int ldo, size_t oBatch,
    float* __restrict__ deg)
{
    constexpr int NA = (MODE == 1) ? 1 : 2;
    constexpr int NOPS = NA + 2;

    int m0, n0, b = blockIdx.z;
    if (MODE == 0) {
        int idx = blockIdx.x, bi = 0;
        while (idx >= (C_ / 128 - bi)) { idx -= (C_ / 128 - bi); bi++; }
        m0 = bi * 128; n0 = (bi + idx) * 128;
    } else {
        m0 = blockIdx.y * 128; n0 = blockIdx.x * 128;
    }

    int tid = threadIdx.x, wid = tid >> 5, lane = tid & 31;
    int wm = wid & 1, wn = wid >> 1;          // warp tile 64x32
    int g = lane >> 2, t = lane & 3;

    const __half* ops[NOPS];
    int ldv[NOPS];
    ops[0] = a0 + (size_t)b * aBatch + (size_t)m0 * lda; ldv[0] = lda;
    if (NA == 2) { ops[1] = a1 + (size_t)b * aBatch + (size_t)m0 * lda; ldv[1] = lda; }
    ops[NA]     = b0 + (size_t)b * bBatch + (size_t)n0 * ldb; ldv[NA] = ldb;
    ops[NA + 1] = b1 + (size_t)b * bBatch + (size_t)n0 * ldb; ldv[NA + 1] = ldb;

    extern __shared__ __half sm[];
    uint32_t smb = smem_u32(sm);

    auto load_tile = [&](int op, int buf, int k0) {
        uint32_t st = smb + (uint32_t)(buf * NOPS + op) * TILEB;
        const __half* src = ops[op] + k0;
        int ld = ldv[op];
#pragma unroll
        for (int i2 = 0; i2 < 2; i2++) {
            int idx = tid + i2 * 256;            // 0..511
            int row = idx >> 2, seg = idx & 3;
            const __half* gp = src + (size_t)row * ld + seg * 8;
            uint32_t sa = st + swz(row, seg);
            asm volatile("cp.async.cg.shared.global [%0], [%1], 16;" :: "r"(sa), "l"(gp) : "memory");
        }
    };

    float acc[4][4][4];
#pragma unroll
    for (int i = 0; i < 4; i++)
#pragma unroll
        for (int j = 0; j < 4; j++)
#pragma unroll
            for (int r = 0; r < 4; r++) acc[i][j][r] = 0.f;

    // ldmatrix lane->(row, seg-half) offsets
    int a_row = ((lane >> 3) & 1) * 8 + (lane & 7);
    int a_sg  = lane >> 4;                 // 0/1
    int b_row = ((lane >> 4) & 1) * 8 + (lane & 7);
    int b_sg  = (lane >> 3) & 1;           // 0/1

    uint32_t afr[NA][4][4];
    uint32_t bfr0[4][2], bfr1[4][2];

    const int NC = K / KC;
    for (int op = 0; op < NOPS; op++) load_tile(op, 0, 0);
    CP_COMMIT();
    if (NC > 1) {
        for (int op = 0; op < NOPS; op++) load_tile(op, 1, KC);
        CP_COMMIT();
    }

    for (int c = 0; c < NC; c++) {
        int buf = c % NST;
        if (c + 1 < NC) { CP_WAIT1(); } else { CP_WAIT0(); }
        __syncthreads();
        if (c + 2 < NC) {
            for (int op = 0; op < NOPS; op++) load_tile(op, (c + 2) % NST, (c + 2) * KC);
            CP_COMMIT();
        }
        uint32_t tb = smb + (uint32_t)(buf * NOPS) * TILEB;
#pragma unroll
        for (int ks = 0; ks < 2; ks++) {
            int segA = 2 * ks + a_sg;
            int segB = 2 * ks + b_sg;
#pragma unroll
            for (int i = 0; i < 4; i++)
                ldsm4(afr[0][i], tb + swz(wm * 64 + i * 16 + a_row, segA));
            if (MODE != 1) {
#pragma unroll
                for (int i = 0; i < 4; i++)
                    ldsm4(afr[NA - 1][i], tb + TILEB + swz(wm * 64 + i * 16 + a_row, segA));
            }
            uint32_t tB0 = tb + (uint32_t)NA * TILEB;
            ldsm4(&bfr0[0][0], tB0 + swz(wn * 32 + b_row, segB));
            ldsm4(&bfr0[2][0], tB0 + swz(wn * 32 + 16 + b_row, segB));
            uint32_t tB1 = tB0 + TILEB;
            ldsm4(&bfr1[0][0], tB1 + swz(wn * 32 + b_row, segB));
            ldsm4(&bfr1[2][0], tB1 + swz(wn * 32 + 16 + b_row, segB));
#pragma unroll
            for (int i = 0; i < 4; i++)
#pragma unroll
                for (int j = 0; j < 4; j++) mma_f16(acc[i][j], afr[0][i], bfr0[j]);
            if (MODE != 1) {
#pragma unroll
                for (int i = 0; i < 4; i++)
#pragma unroll
                    for (int j = 0; j < 4; j++) mma_f16(acc[i][j], afr[NA - 1][i], bfr0[j]);
            }
#pragma unroll
            for (int i = 0; i < 4; i++)
#pragma unroll
                for (int j = 0; j < 4; j++) mma_f16(acc[i][j], afr[0][i], bfr1[j]);
        }
    }

    // ------------------------------- epilogues -------------------------------
    if (MODE == 0) {
        const float* inb = aux + (size_t)b * auxBatch;
        __half* Ab = (__half*)out0 + (size_t)b * oBatch;
        float* degb = deg + (size_t)b * C_;
        float v[4][4][4];
#pragma unroll
        for (int i = 0; i < 4; i++) {
            int r0 = m0 + wm * 64 + i * 16 + g;
            float rs0 = inb[r0], rs1 = inb[r0 + 8];
#pragma unroll
            for (int j = 0; j < 4; j++) {
                int cl = n0 + wn * 32 + j * 8 + t * 2;
                float j0 = inb[cl], j1 = inb[cl + 1];
                v[i][j][0] = (acc[i][j][0] * rs0 * j0 > THRESH) ? 1.f : 0.f;
                v[i][j][1] = (acc[i][j][1] * rs0 * j1 > THRESH) ? 1.f : 0.f;
                v[i][j][2] = (acc[i][j][2] * rs1 * j0 > THRESH) ? 1.f : 0.f;
                v[i][j][3] = (acc[i][j][3] * rs1 * j1 > THRESH) ? 1.f : 0.f;
                *(__half2*)(Ab + (size_t)r0 * ldo + cl)       = __floats2half2_rn(v[i][j][0], v[i][j][1]);
                *(__half2*)(Ab + (size_t)(r0 + 8) * ldo + cl) = __floats2half2_rn(v[i][j][2], v[i][j][3]);
            }
        }
        // degrees: row sums
#pragma unroll
        for (int i = 0; i < 4; i++) {
            float s0 = 0.f, s1 = 0.f;
#pragma unroll
            for (int j = 0; j < 4; j++) {
                s0 += v[i][j][0] + v[i][j][1];
                s1 += v[i][j][2] + v[i][j][3];
            }
            s0 += __shfl_xor_sync(0xFFFFFFFFu, s0, 1); s0 += __shfl_xor_sync(0xFFFFFFFFu, s0, 2);
            s1 += __shfl_xor_sync(0xFFFFFFFFu, s1, 1); s1 += __shfl_xor_sync(0xFFFFFFFFu, s1, 2);
            if (t == 0) {
                atomicAdd(&degb[m0 + wm * 64 + i * 16 + g], s0);
                atomicAdd(&degb[m0 + wm * 64 + i * 16 + g + 8], s1);
            }
        }
        if (m0 != n0) {
            // degrees: column sums
#pragma unroll
            for (int j = 0; j < 4; j++) {
                float c0 = 0.f, c1 = 0.f;
#pragma unroll
                for (int i = 0; i < 4; i++) {
                    c0 += v[i][j][0] + v[i][j][2];
                    c1 += v[i][j][1] + v[i][j][3];
                }
                c0 += __shfl_xor_sync(0xFFFFFFFFu, c0, 4); c0 += __shfl_xor_sync(0xFFFFFFFFu, c0, 8); c0 += __shfl_xor_sync(0xFFFFFFFFu, c0, 16);
                c1 += __shfl_xor_sync(0xFFFFFFFFu, c1, 4); c1 += __shfl_xor_sync(0xFFFFFFFFu, c1, 8); c1 += __shfl_xor_sync(0xFFFFFFFFu, c1, 16);
                if (lane < 4) {
                    atomicAdd(&degb[n0 + wn * 32 + j * 8 + t * 2], c0);
                    atomicAdd(&degb[n0 + wn * 32 + j * 8 + t * 2 + 1], c1);
                }
            }
            // mirror write via smem stage (tiles are dead after this barrier)
            __syncthreads();
            float* stage = (float*)sm;                 // 128 x 129 floats
#pragma unroll
            for (int i = 0; i < 4; i++) {
                int rr = wm * 64 + i * 16 + g;
#pragma unroll
                for (int j = 0; j < 4; j++) {
                    int cc = wn * 32 + j * 8 + t * 2;
                    stage[rr * 129 + cc]           = v[i][j][0];
                    stage[rr * 129 + cc + 1]       = v[i][j][1];
                    stage[(rr + 8) * 129 + cc]     = v[i][j][2];
                    stage[(rr + 8) * 129 + cc + 1] = v[i][j][3];
                }
            }
            __syncthreads();
#pragma unroll
            for (int q = 0; q < 16; q++) {
                int idx = tid + q * 256;               // 0..4095
                int r = idx >> 5;
                int c4 = (idx & 31) * 4;
                float f0 = stage[(c4 + 0) * 129 + r];
                float f1 = stage[(c4 + 1) * 129 + r];
                float f2 = stage[(c4 + 2) * 129 + r];
                float f3 = stage[(c4 + 3) * 129 + r];
                __half* dst = Ab + (size_t)(n0 + r) * ldo + m0 + c4;
                ((__half2*)dst)[0] = __floats2half2_rn(f0, f1);
                ((__half2*)dst)[1] = __floats2half2_rn(f2, f3);
            }
        }
    } else if (MODE == 1) {
        const float* db = aux + (size_t)b * auxBatch;
        __half* o0 = (__half*)out0 + (size_t)b * oBatch;
        __half* o1 = (__half*)out1 + (size_t)b * oBatch;
#pragma unroll
        for (int i = 0; i < 4; i++) {
            int r0 = m0 + wm * 64 + i * 16 + g;
            float rs0 = db[r0], rs1 = db[r0 + 8];
#pragma unroll
            for (int j = 0; j < 4; j++) {
                int cl = n0 + wn * 32 + j * 8 + t * 2;
                float v00 = acc[i][j][0] * rs0, v01 = acc[i][j][1] * rs0;
                float v10 = acc[i][j][2] * rs1, v11 = acc[i][j][3] * rs1;
                __half h00 = __float2half_rn(v00), h01 = __float2half_rn(v01);
                __half h10 = __float2half_rn(v10), h11 = __float2half_rn(v11);
                *(__half2*)(o0 + (size_t)r0 * ldo + cl)       = __halves2half2(h00, h01);
                *(__half2*)(o0 + (size_t)(r0 + 8) * ldo + cl) = __halves2half2(h10, h11);
                *(__half2*)(o1 + (size_t)r0 * ldo + cl) =
                    __floats2half2_rn(v00 - __half2float(h00), v01 - __half2float(h01));
                *(__half2*)(o1 + (size_t)(r0 + 8) * ldo + cl) =
                    __floats2half2_rn(v10 - __half2float(h10), v11 - __half2float(h11));
            }
        }
    } else {
        float bias = aux[0];
        float* o = (float*)out0;
#pragma unroll
        for (int i = 0; i < 4; i++) {
            int r0 = m0 + wm * 64 + i * 16 + g;
#pragma unroll
            for (int j = 0; j < 4; j++) {
                int cl = n0 + wn * 32 + j * 8 + t * 2;
                float v00 = fmaxf(acc[i][j][0] + bias, 0.f);
                float v01 = fmaxf(acc[i][j][1] + bias, 0.f);
                float v10 = fmaxf(acc[i][j][2] + bias, 0.f);
                float v11 = fmaxf(acc[i][j][3] + bias, 0.f);
                *(float2*)(o + (size_t)r0 * ldo + cl)       = make_float2(v00, v01);
                *(float2*)(o + (size_t)(r0 + 8) * ldo + cl) = make_float2(v10, v11);
            }
        }
    }
}

// =============================== small kernels ==============================
__global__ void zero_kernel(float* __restrict__ p) {
    p[blockIdx.x * 256 + threadIdx.x] = 0.f;
}

__global__ void norm_kernel(const float* __restrict__ x, float* __restrict__ invn) {
    int row = blockIdx.x;
    const float* xr = x + (size_t)row * F_;
    float s = 0.f;
    for (int i = threadIdx.x; i < F_; i += 128) { float v = xr[i]; s += v * v; }
    __shared__ float red[128];
    red[threadIdx.x] = s; __syncthreads();
    for (int o = 64; o > 0; o >>= 1) {
        if (threadIdx.x < o) red[threadIdx.x] += red[threadIdx.x + o];
        __syncthreads();
    }
    if (threadIdx.x == 0) invn[row] = 1.0f / sqrtf(red[0]);
}

__global__ void split_kernel(const float* __restrict__ x,
                             __half* __restrict__ hi, __half* __restrict__ lo) {
    size_t i = (size_t)blockIdx.x * 256 + threadIdx.x;
    float v = x[i];
    __half h = __float2half_rn(v);
    hi[i] = h;
    lo[i] = __float2half_rn(v - __half2float(h));
}

__global__ void dinv_kernel(const float* __restrict__ deg, float* __restrict__ dinv) {
    int i = blockIdx.x * 256 + threadIdx.x;
    dinv[i] = 1.0f / sqrtf(deg[i]);
}

// h[b,c,f] * dinv[b,c] -> transposed split hT_hi/lo [b,f,c] (fp16)
__global__ void scale_transpose(const float* __restrict__ h, const float* __restrict__ dinv,
                                __half* __restrict__ thi, __half* __restrict__ tlo) {
    __shared__ float tsm[32][33];
    int c0 = blockIdx.x * 32, f0 = blockIdx.y * 32, b = blockIdx.z;
    const float* hb = h + (size_t)b * C_ * F_;
#pragma unroll
    for (int k = 0; k < 4; k++) {
        int c = c0 + threadIdx.y + k * 8;
        float v = hb[(size_t)c * F_ + f0 + threadIdx.x] * dinv[b * C_ + c];
        tsm[threadIdx.x][threadIdx.y + k * 8] = v;
    }
    __syncthreads();
#pragma unroll
    for (int k = 0; k < 4; k++) {
        int f = f0 + threadIdx.y + k * 8;
        float v = tsm[threadIdx.y + k * 8][threadIdx.x];
        __half hh = __float2half_rn(v);
        size_t o = (size_t)b * F_ * C_ + (size_t)f * C_ + c0 + threadIdx.x;
        thi[o] = hh;
        tlo[o] = __float2half_rn(v - __half2float(hh));
    }
}

// W[f,g] -> WT[g,f] split (fp16)
__global__ void wtrans_kernel(const float* __restrict__ W,
                              __half* __restrict__ hi, __half* __restrict__ lo) {
    __shared__ float tsm[32][33];
    int g0 = blockIdx.x * 32, f0 = blockIdx.y * 32;
#pragma unroll
    for (int k = 0; k < 4; k++) {
        int f = f0 + threadIdx.y + k * 8;
        tsm[threadIdx.x][threadIdx.y + k * 8] = W[(size_t)f * F_ + g0 + threadIdx.x];
    }
    __syncthreads();
#pragma unroll
    for (int k = 0; k < 4; k++) {
        int gg = g0 + threadIdx.y + k * 8;
        float v = tsm[threadIdx.y + k * 8][threadIdx.x];
        __half hh = __float2half_rn(v);
        size_t o = (size_t)gg * F_ + f0 + threadIdx.x;
        hi[o] = hh;
        lo[o] = __float2half_rn(v - __half2float(hh));
    }
}

// ============================================================================
extern "C" void kernel_launch(void* const* d_in, const int* in_sizes, int n_in,
                              void* d_out, int out_size) {
    const float* x  = (const float*)d_in[0];
    const float* W1 = (const float*)d_in[1];
    const float* b1 = (const float*)d_in[2];
    const float* W2 = (const float*)d_in[3];
    const float* b2 = (const float*)d_in[4];
    float* out = (float*)d_out;

    __half *pA, *pxhi, *pxlo, *phThi, *phTlo, *plxhi, *plxlo, *pWThi, *pWTlo;
    float *pinvn, *pdeg, *pdinv, *ph2;
    cudaGetSymbolAddress((void**)&pA,    g_A);
    cudaGetSymbolAddress((void**)&pinvn, g_invn);
    cudaGetSymbolAddress((void**)&pdeg,  g_deg);
    cudaGetSymbolAddress((void**)&pdinv, g_dinv);
    cudaGetSymbolAddress((void**)&pxhi,  g_xhi);
    cudaGetSymbolAddress((void**)&pxlo,  g_xlo);
    cudaGetSymbolAddress((void**)&phThi, g_hT_hi);
    cudaGetSymbolAddress((void**)&phTlo, g_hT_lo);
    cudaGetSymbolAddress((void**)&plxhi, g_lx_hi);
    cudaGetSymbolAddress((void**)&plxlo, g_lx_lo);
    cudaGetSymbolAddress((void**)&ph2,   g_h2);
    cudaGetSymbolAddress((void**)&pWThi, g_WT_hi);
    cudaGetSymbolAddress((void**)&pWTlo, g_WT_lo);

    const int smem4 = 4 * NST * TILEB;   // 98304 B (GRAM / HW)
    const int smem3 = 3 * NST * TILEB;   // 73728 B (AH)
    cudaFuncSetAttribute(mma_gemm<0>, cudaFuncAttributeMaxDynamicSharedMemorySize, smem4);
    cudaFuncSetAttribute(mma_gemm<1>, cudaFuncAttributeMaxDynamicSharedMemorySize, smem3);
    cudaFuncSetAttribute(mma_gemm<2>, cudaFuncAttributeMaxDynamicSharedMemorySize, smem4);

    const int NBLK = C_ / 128;                       // 16
    const int NTRI = NBLK * (NBLK + 1) / 2;          // 136

    // ---- Laplacian ----
    zero_kernel<<<(B_ * C_) / 256, 256>>>(pdeg);
    norm_kernel<<<B_ * C_, 128>>>(x, pinvn);
    split_kernel<<<(B_ * C_ * F_) / 256, 256>>>(x, pxhi, pxlo);
    mma_gemm<0><<<dim3(NTRI, 1, B_), 256, smem4>>>(
        pxhi, pxlo, pxhi, pxlo, F_, F_, F_,
        (size_t)C_ * F_, (size_t)C_ * F_, pinvn, C_,
        pA, nullptr, C_, (size_t)C_ * C_, pdeg);
    dinv_kernel<<<(B_ * C_) / 256, 256>>>(pdeg, pdinv);

    // ---- layer 1 ----
    scale_transpose<<<dim3(C_ / 32, F_ / 32, B_), dim3(32, 8)>>>(x, pdinv, phThi, phTlo);
    mma_gemm<1><<<dim3(F_ / 128, C_ / 128, B_), 256, smem3>>>(
        pA, nullptr, phThi, phTlo, C_, C_, C_,
        (size_t)C_ * C_, (size_t)F_ * C_, pdinv, C_,
        plxhi, plxlo, F_, (size_t)C_ * F_, nullptr);
    wtrans_kernel<<<dim3(F_ / 32, F_ / 32), dim3(32, 8)>>>(W1, pWThi, pWTlo);
    mma_gemm<2><<<dim3(F_ / 128, (B_ * C_) / 128, 1), 256, smem4>>>(
        plxhi, plxlo, pWThi, pWTlo, F_, F_, F_,
        0, 0, b1, 0,
        ph2, nullptr, F_, 0, nullptr);

    // ---- layer 2 ----
    scale_transpose<<<dim3(C_ / 32, F_ / 32, B_), dim3(32, 8)>>>(ph2, pdinv, phThi, phTlo);
    mma_gemm<1><<<dim3(F_ / 128, C_ / 128, B_), 256, smem3>>>(
        pA, nullptr, phThi, phTlo, C_, C_, C_,
        (size_t)C_ * C_, (size_t)F_ * C_, pdinv, C_,
        plxhi, plxlo, F_, (size_t)C_ * F_, nullptr);
    wtrans_kernel<<<dim3(F_ / 32, F_ / 32), dim3(32, 8)>>>(W2, pWThi, pWTlo);
    mma_gemm<2><<<dim3(F_ / 128, (B_ * C_) / 128, 1), 256, smem4>>>(
        plxhi, plxlo, pWThi, pWTlo, F_, F_, F_,
        0, 0, b2, 0,
        out, nullptr, F_, 0, nullptr);
}

// round 8
// speedup vs baseline: 3.2574x; 1.0735x over previous
#include <cuda_runtime.h>
#include <cuda_fp16.h>
#include <cstdint>
#include <math.h>

#define B_ 8
#define C_ 2048
#define F_ 512
#define THRESH 0.005f

// ---- scratch (device globals: no allocation allowed) ----
__device__ __half g_A[(size_t)B_ * C_ * C_];       // binary adjacency (fp16 0/1)
__device__ float  g_invn[B_ * C_];
__device__ float  g_deg[B_ * C_];
__device__ float  g_dinv[B_ * C_];
__device__ __half g_xhi[(size_t)B_ * C_ * F_];
__device__ __half g_xlo[(size_t)B_ * C_ * F_];
__device__ __half g_hT_hi[(size_t)B_ * F_ * C_];   // (dinv*h)^T split
__device__ __half g_hT_lo[(size_t)B_ * F_ * C_];
__device__ __half g_lx_hi[(size_t)B_ * C_ * F_];   // L@h split
__device__ __half g_lx_lo[(size_t)B_ * C_ * F_];
__device__ float  g_h2[(size_t)B_ * C_ * F_];      // hidden activations
__device__ __half g_WT_hi[F_ * F_];
__device__ __half g_WT_lo[F_ * F_];

// =============================== helpers ===============================
__device__ __forceinline__ uint32_t smem_u32(const void* p) {
    uint32_t a;
    asm("{ .reg .u64 t; cvta.to.shared.u64 t, %1; cvt.u32.u64 %0, t; }" : "=r"(a) : "l"(p));
    return a;
}
#define CP_COMMIT() asm volatile("cp.async.commit_group;" ::: "memory")
#define CP_WAIT1()  asm volatile("cp.async.wait_group 1;" ::: "memory")
#define CP_WAIT0()  asm volatile("cp.async.wait_group 0;" ::: "memory")

__device__ __forceinline__ void mma_f16(float c[4], const uint32_t a[4], const uint32_t b[2]) {
    asm volatile(
        "mma.sync.aligned.m16n8k16.row.col.f32.f16.f16.f32 "
        "{%0,%1,%2,%3}, {%4,%5,%6,%7}, {%8,%9}, {%0,%1,%2,%3};"
        : "+f"(c[0]), "+f"(c[1]), "+f"(c[2]), "+f"(c[3])
        : "r"(a[0]), "r"(a[1]), "r"(a[2]), "r"(a[3]), "r"(b[0]), "r"(b[1]));
}
__device__ __forceinline__ void ldsm4(uint32_t r[4], uint32_t addr) {
    asm volatile("ldmatrix.sync.aligned.m8n8.x4.shared.b16 {%0,%1,%2,%3}, [%4];"
        : "=r"(r[0]), "=r"(r[1]), "=r"(r[2]), "=r"(r[3]) : "r"(addr));
}
// swizzled byte offset inside one 128-row tile; KCC = K-chunk width (32 or 64 halves)
template <int KCC>
__device__ __forceinline__ uint32_t swz(int row, int seg) {
    if (KCC == 64) return (uint32_t)(row * 128 + ((seg ^ (row & 7)) << 4));
    return (uint32_t)(row * 64 + ((seg ^ ((row >> 1) & 3)) << 4));
}

// ====================== fp16 mma GEMM (128x128 tile) ======================
// All operands row-major with K contiguous: Aop[m][k] (lda), Bop[n][k] (ldb).
// MODE 0: GRAM (symmetric blocks, KC32/3-stage) acc = xhi·xhiT + xhi·xloT + xlo·xhiT
// MODE 1: AH   (KC64/2-stage) acc = A·hThiT + A·hTloT ; epi: *dinv[m], split hi/lo
// MODE 2: HW   (KC32/3-stage) acc = 3-pass split      ; epi: relu(+bias) -> fp32

template <int MODE>
__global__ __launch_bounds__(256, 2) void mma_gemm(
    const __half* __restrict__ a0, const __half* __restrict__ a1,
    const __half* __restrict__ b0, const __half* __restrict__ b1,
    int lda, int ldb, int K,
    size_t aBatch, size_t bBatch,
    const float* __restrict__ aux, int auxBatch,
    void* __restrict__ out0, void* __restrict__ out1,
    int ldo, size_t oBatch,
    float* __restrict__ deg)
{
    constexpr int NA   = (MODE == 1) ? 1 : 2;
    constexpr int NOPS = NA + 2;
    constexpr int KCC  = (MODE == 1) ? 64 : 32;
    constexpr int NSTG = (MODE == 1) ? 2 : 3;
    constexpr int TB   = 128 * KCC * 2;          // tile bytes
    constexpr int NKS  = KCC / 16;

    int m0, n0, b = blockIdx.z;
    if (MODE == 0) {
        int idx = blockIdx.x, bi = 0;
        while (idx >= (C_ / 128 - bi)) { idx -= (C_ / 128 - bi); bi++; }
        m0 = bi * 128; n0 = (bi + idx) * 128;
    } else {
        m0 = blockIdx.y * 128; n0 = blockIdx.x * 128;
    }

    int tid = threadIdx.x, wid = tid >> 5, lane = tid & 31;
    int wm = wid & 1, wn = wid >> 1;          // warp tile 64x32
    int g = lane >> 2, t = lane & 3;

    const __half* ops[NOPS];
    int ldv[NOPS];
    ops[0] = a0 + (size_t)b * aBatch + (size_t)m0 * lda; ldv[0] = lda;
    if (NA == 2) { ops[1] = a1 + (size_t)b * aBatch + (size_t)m0 * lda; ldv[1] = lda; }
    ops[NA]     = b0 + (size_t)b * bBatch + (size_t)n0 * ldb; ldv[NA] = ldb;
    ops[NA + 1] = b1 + (size_t)b * bBatch + (size_t)n0 * ldb; ldv[NA + 1] = ldb;

    extern __shared__ __half sm[];
    uint32_t smb = smem_u32(sm);

    auto load_tile = [&](int op, int buf, int k0) {
        uint32_t st = smb + (uint32_t)(buf * NOPS + op) * TB;
        const __half* src = ops[op] + k0;
        int ld = ldv[op];
        constexpr int ITER = (128 * KCC / 8) / 256;   // 16B transfers / 256 thr
#pragma unroll
        for (int i2 = 0; i2 < ITER; i2++) {
            int idx = tid + i2 * 256;
            int row, seg;
            if (KCC == 64) { row = idx >> 3; seg = idx & 7; }
            else           { row = idx >> 2; seg = idx & 3; }
            const __half* gp = src + (size_t)row * ld + seg * 8;
            uint32_t sa = st + swz<KCC>(row, seg);
            asm volatile("cp.async.cg.shared.global [%0], [%1], 16;" :: "r"(sa), "l"(gp) : "memory");
        }
    };

    float acc[4][4][4];
#pragma unroll
    for (int i = 0; i < 4; i++)
#pragma unroll
        for (int j = 0; j < 4; j++)
#pragma unroll
            for (int r = 0; r < 4; r++) acc[i][j][r] = 0.f;

    // ldmatrix lane->(row, seg-half) offsets
    int a_row = ((lane >> 3) & 1) * 8 + (lane & 7);
    int a_sg  = lane >> 4;                 // 0/1
    int b_row = ((lane >> 4) & 1) * 8 + (lane & 7);
    int b_sg  = (lane >> 3) & 1;           // 0/1

    uint32_t afr[NA][4][4];
    uint32_t bfr0[4][2], bfr1[4][2];

    auto compute = [&](int buf) {
        uint32_t tb = smb + (uint32_t)(buf * NOPS) * TB;
#pragma unroll
        for (int ks = 0; ks < NKS; ks++) {
            int segA = 2 * ks + a_sg;
            int segB = 2 * ks + b_sg;
#pragma unroll
            for (int i = 0; i < 4; i++)
                ldsm4(afr[0][i], tb + swz<KCC>(wm * 64 + i * 16 + a_row, segA));
            if (MODE != 1) {
#pragma unroll
                for (int i = 0; i < 4; i++)
                    ldsm4(afr[NA - 1][i], tb + TB + swz<KCC>(wm * 64 + i * 16 + a_row, segA));
            }
            uint32_t tB0 = tb + (uint32_t)NA * TB;
            ldsm4(&bfr0[0][0], tB0 + swz<KCC>(wn * 32 + b_row, segB));
            ldsm4(&bfr0[2][0], tB0 + swz<KCC>(wn * 32 + 16 + b_row, segB));
            uint32_t tB1 = tB0 + TB;
            ldsm4(&bfr1[0][0], tB1 + swz<KCC>(wn * 32 + b_row, segB));
            ldsm4(&bfr1[2][0], tB1 + swz<KCC>(wn * 32 + 16 + b_row, segB));
#pragma unroll
            for (int i = 0; i < 4; i++)
#pragma unroll
                for (int j = 0; j < 4; j++) mma_f16(acc[i][j], afr[0][i], bfr0[j]);
            if (MODE != 1) {
#pragma unroll
                for (int i = 0; i < 4; i++)
#pragma unroll
                    for (int j = 0; j < 4; j++) mma_f16(acc[i][j], afr[NA - 1][i], bfr0[j]);
            }
#pragma unroll
            for (int i = 0; i < 4; i++)
#pragma unroll
                for (int j = 0; j < 4; j++) mma_f16(acc[i][j], afr[0][i], bfr1[j]);
        }
    };

    const int NC = K / KCC;
    if (NSTG == 3) {
        for (int op = 0; op < NOPS; op++) load_tile(op, 0, 0);
        CP_COMMIT();
        if (NC > 1) {
            for (int op = 0; op < NOPS; op++) load_tile(op, 1, KCC);
            CP_COMMIT();
        }
        for (int c = 0; c < NC; c++) {
            if (c + 1 < NC) { CP_WAIT1(); } else { CP_WAIT0(); }
            __syncthreads();
            if (c + 2 < NC) {
                for (int op = 0; op < NOPS; op++) load_tile(op, (c + 2) % 3, (c + 2) * KCC);
                CP_COMMIT();
            }
            compute(c % 3);
        }
    } else {
        for (int op = 0; op < NOPS; op++) load_tile(op, 0, 0);
        CP_COMMIT();
        for (int c = 0; c < NC; c++) {
            CP_WAIT0();
            __syncthreads();
            if (c + 1 < NC) {
                for (int op = 0; op < NOPS; op++) load_tile(op, (c + 1) & 1, (c + 1) * KCC);
                CP_COMMIT();
            }
            compute(c & 1);
        }
    }

    // ------------------------------- epilogues -------------------------------
    if (MODE == 0) {
        const float* inb = aux + (size_t)b * auxBatch;
        __half* Ab = (__half*)out0 + (size_t)b * oBatch;
        float* degb = deg + (size_t)b * C_;
        float v[4][4][4];
#pragma unroll
        for (int i = 0; i < 4; i++) {
            int r0 = m0 + wm * 64 + i * 16 + g;
            float rs0 = inb[r0], rs1 = inb[r0 + 8];
#pragma unroll
            for (int j = 0; j < 4; j++) {
                int cl = n0 + wn * 32 + j * 8 + t * 2;
                float j0 = inb[cl], j1 = inb[cl + 1];
                v[i][j][0] = (acc[i][j][0] * rs0 * j0 > THRESH) ? 1.f : 0.f;
                v[i][j][1] = (acc[i][j][1] * rs0 * j1 > THRESH) ? 1.f : 0.f;
                v[i][j][2] = (acc[i][j][2] * rs1 * j0 > THRESH) ? 1.f : 0.f;
                v[i][j][3] = (acc[i][j][3] * rs1 * j1 > THRESH) ? 1.f : 0.f;
                *(__half2*)(Ab + (size_t)r0 * ldo + cl)       = __floats2half2_rn(v[i][j][0], v[i][j][1]);
                *(__half2*)(Ab + (size_t)(r0 + 8) * ldo + cl) = __floats2half2_rn(v[i][j][2], v[i][j][3]);
            }
        }
        // degrees: row sums
#pragma unroll
        for (int i = 0; i < 4; i++) {
            float s0 = 0.f, s1 = 0.f;
#pragma unroll
            for (int j = 0; j < 4; j++) {
                s0 += v[i][j][0] + v[i][j][1];
                s1 += v[i][j][2] + v[i][j][3];
            }
            s0 += __shfl_xor_sync(0xFFFFFFFFu, s0, 1); s0 += __shfl_xor_sync(0xFFFFFFFFu, s0, 2);
            s1 += __shfl_xor_sync(0xFFFFFFFFu, s1, 1); s1 += __shfl_xor_sync(0xFFFFFFFFu, s1, 2);
            if (t == 0) {
                atomicAdd(&degb[m0 + wm * 64 + i * 16 + g], s0);
                atomicAdd(&degb[m0 + wm * 64 + i * 16 + g + 8], s1);
            }
        }
        if (m0 != n0) {
            // degrees: column sums
#pragma unroll
            for (int j = 0; j < 4; j++) {
                float c0 = 0.f, c1 = 0.f;
#pragma unroll
                for (int i = 0; i < 4; i++) {
                    c0 += v[i][j][0] + v[i][j][2];
                    c1 += v[i][j][1] + v[i][j][3];
                }
                c0 += __shfl_xor_sync(0xFFFFFFFFu, c0, 4); c0 += __shfl_xor_sync(0xFFFFFFFFu, c0, 8); c0 += __shfl_xor_sync(0xFFFFFFFFu, c0, 16);
                c1 += __shfl_xor_sync(0xFFFFFFFFu, c1, 4); c1 += __shfl_xor_sync(0xFFFFFFFFu, c1, 8); c1 += __shfl_xor_sync(0xFFFFFFFFu, c1, 16);
                if (lane < 4) {
                    atomicAdd(&degb[n0 + wn * 32 + j * 8 + t * 2], c0);
                    atomicAdd(&degb[n0 + wn * 32 + j * 8 + t * 2 + 1], c1);
                }
            }
            // mirror write via smem stage (tiles dead after this barrier)
            __syncthreads();
            float* stage = (float*)sm;                 // 128 x 129 floats
#pragma unroll
            for (int i = 0; i < 4; i++) {
                int rr = wm * 64 + i * 16 + g;
#pragma unroll
                for (int j = 0; j < 4; j++) {
                    int cc = wn * 32 + j * 8 + t * 2;
                    stage[rr * 129 + cc]           = v[i][j][0];
                    stage[rr * 129 + cc + 1]       = v[i][j][1];
                    stage[(rr + 8) * 129 + cc]     = v[i][j][2];
                    stage[(rr + 8) * 129 + cc + 1] = v[i][j][3];
                }
            }
            __syncthreads();
#pragma unroll
            for (int q = 0; q < 16; q++) {
                int idx = tid + q * 256;               // 0..4095
                int r = idx >> 5;
                int c4 = (idx & 31) * 4;
                float f0 = stage[(c4 + 0) * 129 + r];
                float f1 = stage[(c4 + 1) * 129 + r];
                float f2 = stage[(c4 + 2) * 129 + r];
                float f3 = stage[(c4 + 3) * 129 + r];
                __half* dst = Ab + (size_t)(n0 + r) * ldo + m0 + c4;
                ((__half2*)dst)[0] = __floats2half2_rn(f0, f1);
                ((__half2*)dst)[1] = __floats2half2_rn(f2, f3);
            }
        }
    } else if (MODE == 1) {
        const float* db = aux + (size_t)b * auxBatch;
        __half* o0 = (__half*)out0 + (size_t)b * oBatch;
        __half* o1 = (__half*)out1 + (size_t)b * oBatch;
#pragma unroll
        for (int i = 0; i < 4; i++) {
            int r0 = m0 + wm * 64 + i * 16 + g;
            float rs0 = db[r0], rs1 = db[r0 + 8];
#pragma unroll
            for (int j = 0; j < 4; j++) {
                int cl = n0 + wn * 32 + j * 8 + t * 2;
                float v00 = acc[i][j][0] * rs0, v01 = acc[i][j][1] * rs0;
                float v10 = acc[i][j][2] * rs1, v11 = acc[i][j][3] * rs1;
                __half h00 = __float2half_rn(v00), h01 = __float2half_rn(v01);
                __half h10 = __float2half_rn(v10), h11 = __float2half_rn(v11);
                *(__half2*)(o0 + (size_t)r0 * ldo + cl)       = __halves2half2(h00, h01);
                *(__half2*)(o0 + (size_t)(r0 + 8) * ldo + cl) = __halves2half2(h10, h11);
                *(__half2*)(o1 + (size_t)r0 * ldo + cl) =
                    __floats2half2_rn(v00 - __half2float(h00), v01 - __half2float(h01));
                *(__half2*)(o1 + (size_t)(r0 + 8) * ldo + cl) =
                    __floats2half2_rn(v10 - __half2float(h10), v11 - __half2float(h11));
            }
        }
    } else {
        float bias = aux[0];
        float* o = (float*)out0;
#pragma unroll
        for (int i = 0; i < 4; i++) {
            int r0 = m0 + wm * 64 + i * 16 + g;
#pragma unroll
            for (int j = 0; j < 4; j++) {
                int cl = n0 + wn * 32 + j * 8 + t * 2;
                float v00 = fmaxf(acc[i][j][0] + bias, 0.f);
                float v01 = fmaxf(acc[i][j][1] + bias, 0.f);
                float v10 = fmaxf(acc[i][j][2] + bias, 0.f);
                float v11 = fmaxf(acc[i][j][3] + bias, 0.f);
                *(float2*)(o + (size_t)r0 * ldo + cl)       = make_float2(v00, v01);
                *(float2*)(o + (size_t)(r0 + 8) * ldo + cl) = make_float2(v10, v11);
            }
        }
    }
}

// =============================== small kernels ==============================
__global__ void zero_kernel(float* __restrict__ p) {
    p[blockIdx.x * 256 + threadIdx.x] = 0.f;
}

// fused: row inv-norms + fp16 hi/lo split of x (single pass over x)
__global__ void norm_split(const float* __restrict__ x, float* __restrict__ invn,
                           __half* __restrict__ hi, __half* __restrict__ lo) {
    int row = blockIdx.x;                  // B_*C_ rows, 128 threads
    const float* xr = x + (size_t)row * F_;
    float4 v = ((const float4*)xr)[threadIdx.x];
    float s = v.x * v.x + v.y * v.y + v.z * v.z + v.w * v.w;
#pragma unroll
    for (int o = 16; o > 0; o >>= 1) s += __shfl_xor_sync(0xFFFFFFFFu, s, o);
    __shared__ float red[4];
    if ((threadIdx.x & 31) == 0) red[threadIdx.x >> 5] = s;
    __syncthreads();
    if (threadIdx.x == 0)
        invn[row] = 1.0f / sqrtf(red[0] + red[1] + red[2] + red[3]);

    __half h0 = __float2half_rn(v.x), h1 = __float2half_rn(v.y);
    __half h2 = __float2half_rn(v.z), h3 = __float2half_rn(v.w);
    size_t o = (size_t)row * F_ + threadIdx.x * 4;
    *(__half2*)(hi + o)     = __halves2half2(h0, h1);
    *(__half2*)(hi + o + 2) = __halves2half2(h2, h3);
    *(__half2*)(lo + o)     = __floats2half2_rn(v.x - __half2float(h0), v.y - __half2float(h1));
    *(__half2*)(lo + o + 2) = __floats2half2_rn(v.z - __half2float(h2), v.w - __half2float(h3));
}

__global__ void dinv_kernel(const float* __restrict__ deg, float* __restrict__ dinv) {
    int i = blockIdx.x * 256 + threadIdx.x;
    dinv[i] = 1.0f / sqrtf(deg[i]);
}

// h[b,c,f] * dinv[b,c] -> transposed split hT_hi/lo [b,f,c] (fp16)
__global__ void scale_transpose(const float* __restrict__ h, const float* __restrict__ dinv,
                                __half* __restrict__ thi, __half* __restrict__ tlo) {
    __shared__ float tsm[32][33];
    int c0 = blockIdx.x * 32, f0 = blockIdx.y * 32, b = blockIdx.z;
    const float* hb = h + (size_t)b * C_ * F_;
#pragma unroll
    for (int k = 0; k < 4; k++) {
        int c = c0 + threadIdx.y + k * 8;
        float v = hb[(size_t)c * F_ + f0 + threadIdx.x] * dinv[b * C_ + c];
        tsm[threadIdx.x][threadIdx.y + k * 8] = v;
    }
    __syncthreads();
#pragma unroll
    for (int k = 0; k < 4; k++) {
        int f = f0 + threadIdx.y + k * 8;
        float v = tsm[threadIdx.y + k * 8][threadIdx.x];
        __half hh = __float2half_rn(v);
        size_t o = (size_t)b * F_ * C_ + (size_t)f * C_ + c0 + threadIdx.x;
        thi[o] = hh;
        tlo[o] = __float2half_rn(v - __half2float(hh));
    }
}

// W[f,g] -> WT[g,f] split (fp16)
__global__ void wtrans_kernel(const float* __restrict__ W,
                              __half* __restrict__ hi, __half* __restrict__ lo) {
    __shared__ float tsm[32][33];
    int g0 = blockIdx.x * 32, f0 = blockIdx.y * 32;
#pragma unroll
    for (int k = 0; k < 4; k++) {
        int f = f0 + threadIdx.y + k * 8;
        tsm[threadIdx.x][threadIdx.y + k * 8] = W[(size_t)f * F_ + g0 + threadIdx.x];
    }
    __syncthreads();
#pragma unroll
    for (int k = 0; k < 4; k++) {
        int gg = g0 + threadIdx.y + k * 8;
        float v = tsm[threadIdx.y + k * 8][threadIdx.x];
        __half hh = __float2half_rn(v);
        size_t o = (size_t)gg * F_ + f0 + threadIdx.x;
        hi[o] = hh;
        lo[o] = __float2half_rn(v - __half2float(hh));
    }
}

// ============================================================================
extern "C" void kernel_launch(void* const* d_in, const int* in_sizes, int n_in,
                              void* d_out, int out_size) {
    const float* x  = (const float*)d_in[0];
    const float* W1 = (const float*)d_in[1];
    const float* b1 = (const float*)d_in[2];
    const float* W2 = (const float*)d_in[3];
    const float* b2 = (const float*)d_in[4];
    float* out = (float*)d_out;

    __half *pA, *pxhi, *pxlo, *phThi, *phTlo, *plxhi, *plxlo, *pWThi, *pWTlo;
    float *pinvn, *pdeg, *pdinv, *ph2;
    cudaGetSymbolAddress((void**)&pA,    g_A);
    cudaGetSymbolAddress((void**)&pinvn, g_invn);
    cudaGetSymbolAddress((void**)&pdeg,  g_deg);
    cudaGetSymbolAddress((void**)&pdinv, g_dinv);
    cudaGetSymbolAddress((void**)&pxhi,  g_xhi);
    cudaGetSymbolAddress((void**)&pxlo,  g_xlo);
    cudaGetSymbolAddress((void**)&phThi, g_hT_hi);
    cudaGetSymbolAddress((void**)&phTlo, g_hT_lo);
    cudaGetSymbolAddress((void**)&plxhi, g_lx_hi);
    cudaGetSymbolAddress((void**)&plxlo, g_lx_lo);
    cudaGetSymbolAddress((void**)&ph2,   g_h2);
    cudaGetSymbolAddress((void**)&pWThi, g_WT_hi);
    cudaGetSymbolAddress((void**)&pWTlo, g_WT_lo);

    const int smem0 = 4 * 3 * (128 * 32 * 2);   // 98304 B (GRAM)
    const int smem1 = 3 * 2 * (128 * 64 * 2);   // 98304 B (AH, KC=64)
    const int smem2 = 4 * 3 * (128 * 32 * 2);   // 98304 B (HW)
    cudaFuncSetAttribute(mma_gemm<0>, cudaFuncAttributeMaxDynamicSharedMemorySize, smem0);
    cudaFuncSetAttribute(mma_gemm<1>, cudaFuncAttributeMaxDynamicSharedMemorySize, smem1);
    cudaFuncSetAttribute(mma_gemm<2>, cudaFuncAttributeMaxDynamicSharedMemorySize, smem2);

    const int NBLK = C_ / 128;                       // 16
    const int NTRI = NBLK * (NBLK + 1) / 2;          // 136

    // ---- Laplacian ----
    zero_kernel<<<(B_ * C_) / 256, 256>>>(pdeg);
    norm_split<<<B_ * C_, 128>>>(x, pinvn, pxhi, pxlo);
    mma_gemm<0><<<dim3(NTRI, 1, B_), 256, smem0>>>(
        pxhi, pxlo, pxhi, pxlo, F_, F_, F_,
        (size_t)C_ * F_, (size_t)C_ * F_, pinvn, C_,
        pA, nullptr, C_, (size_t)C_ * C_, pdeg);
    dinv_kernel<<<(B_ * C_) / 256, 256>>>(pdeg, pdinv);

    // ---- layer 1 ----
    scale_transpose<<<dim3(C_ / 32, F_ / 32, B_), dim3(32, 8)>>>(x, pdinv, phThi, phTlo);
    mma_gemm<1><<<dim3(F_ / 128, C_ / 128, B_), 256, smem1>>>(
        pA, nullptr, phThi, phTlo, C_, C_, C_,
        (size_t)C_ * C_, (size_t)F_ * C_, pdinv, C_,
        plxhi, plxlo, F_, (size_t)C_ * F_, nullptr);
    wtrans_kernel<<<dim3(F_ / 32, F_ / 32), dim3(32, 8)>>>(W1, pWThi, pWTlo);
    mma_gemm<2><<<dim3(F_ / 128, (B_ * C_) / 128, 1), 256, smem2>>>(
        plxhi, plxlo, pWThi, pWTlo, F_, F_, F_,
        0, 0, b1, 0,
        ph2, nullptr, F_, 0, nullptr);

    // ---- layer 2 ----
    scale_transpose<<<dim3(C_ / 32, F_ / 32, B_), dim3(32, 8)>>>(ph2, pdinv, phThi, phTlo);
    mma_gemm<1><<<dim3(F_ / 128, C_ / 128, B_), 256, smem1>>>(
        pA, nullptr, phThi, phTlo, C_, C_, C_,
        (size_t)C_ * C_, (size_t)F_ * C_, pdinv, C_,
        plxhi, plxlo, F_, (size_t)C_ * F_, nullptr);
    wtrans_kernel<<<dim3(F_ / 32, F_ / 32), dim3(32, 8)>>>(W2, pWThi, pWTlo);
    mma_gemm<2><<<dim3(F_ / 128, (B_ * C_) / 128, 1), 256, smem2>>>(
        plxhi, plxlo, pWThi, pWTlo, F_, F_, F_,
        0, 0, b2, 0,
        out, nullptr, F_, 0, nullptr);
}

// round 9
// speedup vs baseline: 3.3539x; 1.0296x over previous
#include <cuda_runtime.h>
#include <cuda_fp16.h>
#include <cstdint>
#include <math.h>

#define B_ 8
#define C_ 2048
#define F_ 512
#define THRESH 0.005f

// ---- scratch (device globals: no allocation allowed) ----
__device__ __half g_A[(size_t)B_ * C_ * C_];       // binary adjacency (fp16 0/1)
__device__ float  g_invn[B_ * C_];
__device__ float  g_deg[B_ * C_];
__device__ float  g_dinv[B_ * C_];
__device__ __half g_xhi[(size_t)B_ * C_ * F_];
__device__ __half g_xlo[(size_t)B_ * C_ * F_];
__device__ __half g_gT_hi[(size_t)B_ * F_ * C_];   // (dinv*(h@W))^T split
__device__ __half g_gT_lo[(size_t)B_ * F_ * C_];
__device__ __half g_h2_hi[(size_t)B_ * C_ * F_];   // hidden activations split
__device__ __half g_h2_lo[(size_t)B_ * C_ * F_];
__device__ __half g_WT_hi[F_ * F_];
__device__ __half g_WT_lo[F_ * F_];

// =============================== helpers ===============================
__device__ __forceinline__ uint32_t smem_u32(const void* p) {
    uint32_t a;
    asm("{ .reg .u64 t; cvta.to.shared.u64 t, %1; cvt.u32.u64 %0, t; }" : "=r"(a) : "l"(p));
    return a;
}
#define CP_COMMIT() asm volatile("cp.async.commit_group;" ::: "memory")
#define CP_WAIT1()  asm volatile("cp.async.wait_group 1;" ::: "memory")
#define CP_WAIT0()  asm volatile("cp.async.wait_group 0;" ::: "memory")

__device__ __forceinline__ void mma_f16(float c[4], const uint32_t a[4], const uint32_t b[2]) {
    asm volatile(
        "mma.sync.aligned.m16n8k16.row.col.f32.f16.f16.f32 "
        "{%0,%1,%2,%3}, {%4,%5,%6,%7}, {%8,%9}, {%0,%1,%2,%3};"
        : "+f"(c[0]), "+f"(c[1]), "+f"(c[2]), "+f"(c[3])
        : "r"(a[0]), "r"(a[1]), "r"(a[2]), "r"(a[3]), "r"(b[0]), "r"(b[1]));
}
__device__ __forceinline__ void ldsm4(uint32_t r[4], uint32_t addr) {
    asm volatile("ldmatrix.sync.aligned.m8n8.x4.shared.b16 {%0,%1,%2,%3}, [%4];"
        : "=r"(r[0]), "=r"(r[1]), "=r"(r[2]), "=r"(r[3]) : "r"(addr));
}
// swizzled byte offset inside one 128-row tile; KCC = K-chunk width (32 or 64 halves)
template <int KCC>
__device__ __forceinline__ uint32_t swz(int row, int seg) {
    if (KCC == 64) return (uint32_t)(row * 128 + ((seg ^ (row & 7)) << 4));
    return (uint32_t)(row * 64 + ((seg ^ ((row >> 1) & 3)) << 4));
}

// ====================== fp16 mma GEMM (128x128 tile) ======================
// All operands row-major with K contiguous: Aop[m][k] (lda), Bop[n][k] (ldb).
// MODE 0: GRAM (symmetric blocks, KC32/3st): binarize; A tile+mirror; deg atomics
// MODE 2: HWT  (KC32/3st) g = h@WT ; epi: *dinv[row], transpose-split -> gT hi/lo
// MODE 1: AH   (KC64/2st) A@gT     ; epi: relu(*dinv[m] + bias) -> split hi/lo
// MODE 3: AH   (KC64/2st) A@gT     ; epi: relu(*dinv[m] + bias) -> fp32

template <int MODE>
__global__ __launch_bounds__(256, 2) void mma_gemm(
    const __half* __restrict__ a0, const __half* __restrict__ a1,
    const __half* __restrict__ b0, const __half* __restrict__ b1,
    int lda, int ldb, int K,
    size_t aBatch, size_t bBatch,
    const float* __restrict__ aux, int auxBatch,
    const float* __restrict__ bias,
    void* __restrict__ out0, void* __restrict__ out1,
    int ldo, size_t oBatch,
    float* __restrict__ deg)
{
    constexpr int NA   = (MODE == 1 || MODE == 3) ? 1 : 2;
    constexpr int NOPS = NA + 2;
    constexpr int KCC  = (NA == 1) ? 64 : 32;
    constexpr int NSTG = (NA == 1) ? 2 : 3;
    constexpr int TB   = 128 * KCC * 2;          // tile bytes
    constexpr int NKS  = KCC / 16;

    int m0, n0, b = blockIdx.z;
    if (MODE == 0) {
        int idx = blockIdx.x, bi = 0;
        while (idx >= (C_ / 128 - bi)) { idx -= (C_ / 128 - bi); bi++; }
        m0 = bi * 128; n0 = (bi + idx) * 128;
    } else {
        m0 = blockIdx.y * 128; n0 = blockIdx.x * 128;
    }

    int tid = threadIdx.x, wid = tid >> 5, lane = tid & 31;
    int wm = wid & 1, wn = wid >> 1;          // warp tile 64x32
    int g = lane >> 2, t = lane & 3;

    const __half* ops[NOPS];
    int ldv[NOPS];
    ops[0] = a0 + (size_t)b * aBatch + (size_t)m0 * lda; ldv[0] = lda;
    if (NA == 2) { ops[1] = a1 + (size_t)b * aBatch + (size_t)m0 * lda; ldv[1] = lda; }
    ops[NA]     = b0 + (size_t)b * bBatch + (size_t)n0 * ldb; ldv[NA] = ldb;
    ops[NA + 1] = b1 + (size_t)b * bBatch + (size_t)n0 * ldb; ldv[NA + 1] = ldb;

    extern __shared__ __half sm[];
    uint32_t smb = smem_u32(sm);

    auto load_tile = [&](int op, int buf, int k0) {
        uint32_t st = smb + (uint32_t)(buf * NOPS + op) * TB;
        const __half* src = ops[op] + k0;
        int ld = ldv[op];
        constexpr int ITER = (128 * KCC / 8) / 256;
#pragma unroll
        for (int i2 = 0; i2 < ITER; i2++) {
            int idx = tid + i2 * 256;
            int row, seg;
            if (KCC == 64) { row = idx >> 3; seg = idx & 7; }
            else           { row = idx >> 2; seg = idx & 3; }
            const __half* gp = src + (size_t)row * ld + seg * 8;
            uint32_t sa = st + swz<KCC>(row, seg);
            asm volatile("cp.async.cg.shared.global [%0], [%1], 16;" :: "r"(sa), "l"(gp) : "memory");
        }
    };

    float acc[4][4][4];
#pragma unroll
    for (int i = 0; i < 4; i++)
#pragma unroll
        for (int j = 0; j < 4; j++)
#pragma unroll
            for (int r = 0; r < 4; r++) acc[i][j][r] = 0.f;

    int a_row = ((lane >> 3) & 1) * 8 + (lane & 7);
    int a_sg  = lane >> 4;
    int b_row = ((lane >> 4) & 1) * 8 + (lane & 7);
    int b_sg  = (lane >> 3) & 1;

    uint32_t afr[NA][4][4];
    uint32_t bfr0[4][2], bfr1[4][2];

    auto compute = [&](int buf) {
        uint32_t tb = smb + (uint32_t)(buf * NOPS) * TB;
#pragma unroll
        for (int ks = 0; ks < NKS; ks++) {
            int segA = 2 * ks + a_sg;
            int segB = 2 * ks + b_sg;
#pragma unroll
            for (int i = 0; i < 4; i++)
                ldsm4(afr[0][i], tb + swz<KCC>(wm * 64 + i * 16 + a_row, segA));
            if (NA == 2) {
#pragma unroll
                for (int i = 0; i < 4; i++)
                    ldsm4(afr[NA - 1][i], tb + TB + swz<KCC>(wm * 64 + i * 16 + a_row, segA));
            }
            uint32_t tB0 = tb + (uint32_t)NA * TB;
            ldsm4(&bfr0[0][0], tB0 + swz<KCC>(wn * 32 + b_row, segB));
            ldsm4(&bfr0[2][0], tB0 + swz<KCC>(wn * 32 + 16 + b_row, segB));
            uint32_t tB1 = tB0 + TB;
            ldsm4(&bfr1[0][0], tB1 + swz<KCC>(wn * 32 + b_row, segB));
            ldsm4(&bfr1[2][0], tB1 + swz<KCC>(wn * 32 + 16 + b_row, segB));
#pragma unroll
            for (int i = 0; i < 4; i++)
#pragma unroll
                for (int j = 0; j < 4; j++) mma_f16(acc[i][j], afr[0][i], bfr0[j]);
            if (NA == 2) {
#pragma unroll
                for (int i = 0; i < 4; i++)
#pragma unroll
                    for (int j = 0; j < 4; j++) mma_f16(acc[i][j], afr[NA - 1][i], bfr0[j]);
            }
#pragma unroll
            for (int i = 0; i < 4; i++)
#pragma unroll
                for (int j = 0; j < 4; j++) mma_f16(acc[i][j], afr[0][i], bfr1[j]);
        }
    };

    const int NC = K / KCC;
    if (NSTG == 3) {
        for (int op = 0; op < NOPS; op++) load_tile(op, 0, 0);
        CP_COMMIT();
        if (NC > 1) {
            for (int op = 0; op < NOPS; op++) load_tile(op, 1, KCC);
            CP_COMMIT();
        }
        for (int c = 0; c < NC; c++) {
            if (c + 1 < NC) { CP_WAIT1(); } else { CP_WAIT0(); }
            __syncthreads();
            if (c + 2 < NC) {
                for (int op = 0; op < NOPS; op++) load_tile(op, (c + 2) % 3, (c + 2) * KCC);
                CP_COMMIT();
            }
            compute(c % 3);
        }
    } else {
        for (int op = 0; op < NOPS; op++) load_tile(op, 0, 0);
        CP_COMMIT();
        for (int c = 0; c < NC; c++) {
            CP_WAIT0();
            __syncthreads();
            if (c + 1 < NC) {
                for (int op = 0; op < NOPS; op++) load_tile(op, (c + 1) & 1, (c + 1) * KCC);
                CP_COMMIT();
            }
            compute(c & 1);
        }
    }

    // ------------------------------- epilogues -------------------------------
    if (MODE == 0) {
        const float* inb = aux + (size_t)b * auxBatch;
        __half* Ab = (__half*)out0 + (size_t)b * oBatch;
        float* degb = deg + (size_t)b * C_;
        float v[4][4][4];
#pragma unroll
        for (int i = 0; i < 4; i++) {
            int r0 = m0 + wm * 64 + i * 16 + g;
            float rs0 = inb[r0], rs1 = inb[r0 + 8];
#pragma unroll
            for (int j = 0; j < 4; j++) {
                int cl = n0 + wn * 32 + j * 8 + t * 2;
                float j0 = inb[cl], j1 = inb[cl + 1];
                v[i][j][0] = (acc[i][j][0] * rs0 * j0 > THRESH) ? 1.f : 0.f;
                v[i][j][1] = (acc[i][j][1] * rs0 * j1 > THRESH) ? 1.f : 0.f;
                v[i][j][2] = (acc[i][j][2] * rs1 * j0 > THRESH) ? 1.f : 0.f;
                v[i][j][3] = (acc[i][j][3] * rs1 * j1 > THRESH) ? 1.f : 0.f;
                *(__half2*)(Ab + (size_t)r0 * ldo + cl)       = __floats2half2_rn(v[i][j][0], v[i][j][1]);
                *(__half2*)(Ab + (size_t)(r0 + 8) * ldo + cl) = __floats2half2_rn(v[i][j][2], v[i][j][3]);
            }
        }
#pragma unroll
        for (int i = 0; i < 4; i++) {
            float s0 = 0.f, s1 = 0.f;
#pragma unroll
            for (int j = 0; j < 4; j++) {
                s0 += v[i][j][0] + v[i][j][1];
                s1 += v[i][j][2] + v[i][j][3];
            }
            s0 += __shfl_xor_sync(0xFFFFFFFFu, s0, 1); s0 += __shfl_xor_sync(0xFFFFFFFFu, s0, 2);
            s1 += __shfl_xor_sync(0xFFFFFFFFu, s1, 1); s1 += __shfl_xor_sync(0xFFFFFFFFu, s1, 2);
            if (t == 0) {
                atomicAdd(&degb[m0 + wm * 64 + i * 16 + g], s0);
                atomicAdd(&degb[m0 + wm * 64 + i * 16 + g + 8], s1);
            }
        }
        if (m0 != n0) {
#pragma unroll
            for (int j = 0; j < 4; j++) {
                float c0 = 0.f, c1 = 0.f;
#pragma unroll
                for (int i = 0; i < 4; i++) {
                    c0 += v[i][j][0] + v[i][j][2];
                    c1 += v[i][j][1] + v[i][j][3];
                }
                c0 += __shfl_xor_sync(0xFFFFFFFFu, c0, 4); c0 += __shfl_xor_sync(0xFFFFFFFFu, c0, 8); c0 += __shfl_xor_sync(0xFFFFFFFFu, c0, 16);
                c1 += __shfl_xor_sync(0xFFFFFFFFu, c1, 4); c1 += __shfl_xor_sync(0xFFFFFFFFu, c1, 8); c1 += __shfl_xor_sync(0xFFFFFFFFu, c1, 16);
                if (lane < 4) {
                    atomicAdd(&degb[n0 + wn * 32 + j * 8 + t * 2], c0);
                    atomicAdd(&degb[n0 + wn * 32 + j * 8 + t * 2 + 1], c1);
                }
            }
            __syncthreads();
            float* stage = (float*)sm;                 // 128 x 129 floats
#pragma unroll
            for (int i = 0; i < 4; i++) {
                int rr = wm * 64 + i * 16 + g;
#pragma unroll
                for (int j = 0; j < 4; j++) {
                    int cc = wn * 32 + j * 8 + t * 2;
                    stage[rr * 129 + cc]           = v[i][j][0];
                    stage[rr * 129 + cc + 1]       = v[i][j][1];
                    stage[(rr + 8) * 129 + cc]     = v[i][j][2];
                    stage[(rr + 8) * 129 + cc + 1] = v[i][j][3];
                }
            }
            __syncthreads();
#pragma unroll
            for (int q = 0; q < 16; q++) {
                int idx = tid + q * 256;
                int r = idx >> 5;
                int c4 = (idx & 31) * 4;
                float f0 = stage[(c4 + 0) * 129 + r];
                float f1 = stage[(c4 + 1) * 129 + r];
                float f2 = stage[(c4 + 2) * 129 + r];
                float f3 = stage[(c4 + 3) * 129 + r];
                __half* dst = Ab + (size_t)(n0 + r) * ldo + m0 + c4;
                ((__half2*)dst)[0] = __floats2half2_rn(f0, f1);
                ((__half2*)dst)[1] = __floats2half2_rn(f2, f3);
            }
        }
    } else if (MODE == 2) {
        // g = h@WT row-scale by dinv[global row], transpose-split -> gT hi/lo [b][f][c]
        const float* db = aux;                       // flattened dinv, index m0+row
        __syncthreads();
        float* stage = (float*)sm;                   // 128 x 129 floats
#pragma unroll
        for (int i = 0; i < 4; i++) {
            int rr = wm * 64 + i * 16 + g;
            float d0 = db[m0 + rr], d1 = db[m0 + rr + 8];
#pragma unroll
            for (int j = 0; j < 4; j++) {
                int cc = wn * 32 + j * 8 + t * 2;
                stage[rr * 129 + cc]           = acc[i][j][0] * d0;
                stage[rr * 129 + cc + 1]       = acc[i][j][1] * d0;
                stage[(rr + 8) * 129 + cc]     = acc[i][j][2] * d1;
                stage[(rr + 8) * 129 + cc + 1] = acc[i][j][3] * d1;
            }
        }
        __syncthreads();
        int bb = m0 / C_;
        int cb = m0 % C_;
        __half* ghi = (__half*)out0;
        __half* glo = (__half*)out1;
#pragma unroll
        for (int q = 0; q < 16; q++) {
            int idx = tid + q * 256;
            int r = idx >> 5;                         // local f
            int c4 = (idx & 31) * 4;                  // local c, 4-aligned
            float f0 = stage[(c4 + 0) * 129 + r];
            float f1 = stage[(c4 + 1) * 129 + r];
            float f2 = stage[(c4 + 2) * 129 + r];
            float f3 = stage[(c4 + 3) * 129 + r];
            __half h0 = __float2half_rn(f0), h1 = __float2half_rn(f1);
            __half h2 = __float2half_rn(f2), h3 = __float2half_rn(f3);
            size_t o = ((size_t)bb * F_ + n0 + r) * C_ + cb + c4;
            ((__half2*)(ghi + o))[0] = __halves2half2(h0, h1);
            ((__half2*)(ghi + o))[1] = __halves2half2(h2, h3);
            ((__half2*)(glo + o))[0] = __floats2half2_rn(f0 - __half2float(h0), f1 - __half2float(h1));
            ((__half2*)(glo + o))[1] = __floats2half2_rn(f2 - __half2float(h2), f3 - __half2float(h3));
        }
    } else {
        // AH: v = relu(acc * dinv[m] + bias)
        const float* db = aux + (size_t)b * auxBatch;
        float bs = bias[0];
#pragma unroll
        for (int i = 0; i < 4; i++) {
            int r0 = m0 + wm * 64 + i * 16 + g;
            float rs0 = db[r0], rs1 = db[r0 + 8];
#pragma unroll
            for (int j = 0; j < 4; j++) {
                int cl = n0 + wn * 32 + j * 8 + t * 2;
                float v00 = fmaxf(acc[i][j][0] * rs0 + bs, 0.f);
                float v01 = fmaxf(acc[i][j][1] * rs0 + bs, 0.f);
                float v10 = fmaxf(acc[i][j][2] * rs1 + bs, 0.f);
                float v11 = fmaxf(acc[i][j][3] * rs1 + bs, 0.f);
                if (MODE == 1) {
                    __half* o0 = (__half*)out0 + (size_t)b * oBatch;
                    __half* o1 = (__half*)out1 + (size_t)b * oBatch;
                    __half h00 = __float2half_rn(v00), h01 = __float2half_rn(v01);
                    __half h10 = __float2half_rn(v10), h11 = __float2half_rn(v11);
                    *(__half2*)(o0 + (size_t)r0 * ldo + cl)       = __halves2half2(h00, h01);
                    *(__half2*)(o0 + (size_t)(r0 + 8) * ldo + cl) = __halves2half2(h10, h11);
                    *(__half2*)(o1 + (size_t)r0 * ldo + cl) =
                        __floats2half2_rn(v00 - __half2float(h00), v01 - __half2float(h01));
                    *(__half2*)(o1 + (size_t)(r0 + 8) * ldo + cl) =
                        __floats2half2_rn(v10 - __half2float(h10), v11 - __half2float(h11));
                } else {
                    float* o = (float*)out0 + (size_t)b * oBatch;
                    *(float2*)(o + (size_t)r0 * ldo + cl)       = make_float2(v00, v01);
                    *(float2*)(o + (size_t)(r0 + 8) * ldo + cl) = make_float2(v10, v11);
                }
            }
        }
    }
}

// =============================== small kernels ==============================
__global__ void zero_kernel(float* __restrict__ p) {
    p[blockIdx.x * 256 + threadIdx.x] = 0.f;
}

// fused: row inv-norms + fp16 hi/lo split of x
__global__ void norm_split(const float* __restrict__ x, float* __restrict__ invn,
                           __half* __restrict__ hi, __half* __restrict__ lo) {
    int row = blockIdx.x;
    const float* xr = x + (size_t)row * F_;
    float4 v = ((const float4*)xr)[threadIdx.x];
    float s = v.x * v.x + v.y * v.y + v.z * v.z + v.w * v.w;
#pragma unroll
    for (int o = 16; o > 0; o >>= 1) s += __shfl_xor_sync(0xFFFFFFFFu, s, o);
    __shared__ float red[4];
    if ((threadIdx.x & 31) == 0) red[threadIdx.x >> 5] = s;
    __syncthreads();
    if (threadIdx.x == 0)
        invn[row] = 1.0f / sqrtf(red[0] + red[1] + red[2] + red[3]);

    __half h0 = __float2half_rn(v.x), h1 = __float2half_rn(v.y);
    __half h2 = __float2half_rn(v.z), h3 = __float2half_rn(v.w);
    size_t o = (size_t)row * F_ + threadIdx.x * 4;
    *(__half2*)(hi + o)     = __halves2half2(h0, h1);
    *(__half2*)(hi + o + 2) = __halves2half2(h2, h3);
    *(__half2*)(lo + o)     = __floats2half2_rn(v.x - __half2float(h0), v.y - __half2float(h1));
    *(__half2*)(lo + o + 2) = __floats2half2_rn(v.z - __half2float(h2), v.w - __half2float(h3));
}

__global__ void dinv_kernel(const float* __restrict__ deg, float* __restrict__ dinv) {
    int i = blockIdx.x * 256 + threadIdx.x;
    dinv[i] = 1.0f / sqrtf(deg[i]);
}

// W[f,g] -> WT[g,f] split (fp16)
__global__ void wtrans_kernel(const float* __restrict__ W,
                              __half* __restrict__ hi, __half* __restrict__ lo) {
    __shared__ float tsm[32][33];
    int g0 = blockIdx.x * 32, f0 = blockIdx.y * 32;
#pragma unroll
    for (int k = 0; k < 4; k++) {
        int f = f0 + threadIdx.y + k * 8;
        tsm[threadIdx.x][threadIdx.y + k * 8] = W[(size_t)f * F_ + g0 + threadIdx.x];
    }
    __syncthreads();
#pragma unroll
    for (int k = 0; k < 4; k++) {
        int gg = g0 + threadIdx.y + k * 8;
        float v = tsm[threadIdx.y + k * 8][threadIdx.x];
        __half hh = __float2half_rn(v);
        size_t o = (size_t)gg * F_ + f0 + threadIdx.x;
        hi[o] = hh;
        lo[o] = __float2half_rn(v - __half2float(hh));
    }
}

// ============================================================================
extern "C" void kernel_launch(void* const* d_in, const int* in_sizes, int n_in,
                              void* d_out, int out_size) {
    const float* x  = (const float*)d_in[0];
    const float* W1 = (const float*)d_in[1];
    const float* b1 = (const float*)d_in[2];
    const float* W2 = (const float*)d_in[3];
    const float* b2 = (const float*)d_in[4];
    float* out = (float*)d_out;

    __half *pA, *pxhi, *pxlo, *pgThi, *pgTlo, *ph2hi, *ph2lo, *pWThi, *pWTlo;
    float *pinvn, *pdeg, *pdinv;
    cudaGetSymbolAddress((void**)&pA,    g_A);
    cudaGetSymbolAddress((void**)&pinvn, g_invn);
    cudaGetSymbolAddress((void**)&pdeg,  g_deg);
    cudaGetSymbolAddress((void**)&pdinv, g_dinv);
    cudaGetSymbolAddress((void**)&pxhi,  g_xhi);
    cudaGetSymbolAddress((void**)&pxlo,  g_xlo);
    cudaGetSymbolAddress((void**)&pgThi, g_gT_hi);
    cudaGetSymbolAddress((void**)&pgTlo, g_gT_lo);
    cudaGetSymbolAddress((void**)&ph2hi, g_h2_hi);
    cudaGetSymbolAddress((void**)&ph2lo, g_h2_lo);
    cudaGetSymbolAddress((void**)&pWThi, g_WT_hi);
    cudaGetSymbolAddress((void**)&pWTlo, g_WT_lo);

    const int smem0 = 4 * 3 * (128 * 32 * 2);   // 98304 B (GRAM / HWT)
    const int smem1 = 3 * 2 * (128 * 64 * 2);   // 98304 B (AH, KC=64)
    cudaFuncSetAttribute(mma_gemm<0>, cudaFuncAttributeMaxDynamicSharedMemorySize, smem0);
    cudaFuncSetAttribute(mma_gemm<1>, cudaFuncAttributeMaxDynamicSharedMemorySize, smem1);
    cudaFuncSetAttribute(mma_gemm<2>, cudaFuncAttributeMaxDynamicSharedMemorySize, smem0);
    cudaFuncSetAttribute(mma_gemm<3>, cudaFuncAttributeMaxDynamicSharedMemorySize, smem1);

    const int NBLK = C_ / 128;                       // 16
    const int NTRI = NBLK * (NBLK + 1) / 2;          // 136

    // ---- Laplacian ----
    zero_kernel<<<(B_ * C_) / 256, 256>>>(pdeg);
    norm_split<<<B_ * C_, 128>>>(x, pinvn, pxhi, pxlo);
    mma_gemm<0><<<dim3(NTRI, 1, B_), 256, smem0>>>(
        pxhi, pxlo, pxhi, pxlo, F_, F_, F_,
        (size_t)C_ * F_, (size_t)C_ * F_, pinvn, C_, nullptr,
        pA, nullptr, C_, (size_t)C_ * C_, pdeg);
    dinv_kernel<<<(B_ * C_) / 256, 256>>>(pdeg, pdinv);

    // ---- layer 1: relu(L @ (x @ W1) + b1) ----
    wtrans_kernel<<<dim3(F_ / 32, F_ / 32), dim3(32, 8)>>>(W1, pWThi, pWTlo);
    mma_gemm<2><<<dim3(F_ / 128, (B_ * C_) / 128, 1), 256, smem0>>>(
        pxhi, pxlo, pWThi, pWTlo, F_, F_, F_,
        0, 0, pdinv, 0, nullptr,
        pgThi, pgTlo, C_, 0, nullptr);
    mma_gemm<1><<<dim3(F_ / 128, C_ / 128, B_), 256, smem1>>>(
        pA, nullptr, pgThi, pgTlo, C_, C_, C_,
        (size_t)C_ * C_, (size_t)F_ * C_, pdinv, C_, b1,
        ph2hi, ph2lo, F_, (size_t)C_ * F_, nullptr);

    // ---- layer 2: relu(L @ (h2 @ W2) + b2) ----
    wtrans_kernel<<<dim3(F_ / 32, F_ / 32), dim3(32, 8)>>>(W2, pWThi, pWTlo);
    mma_gemm<2><<<dim3(F_ / 128, (B_ * C_) / 128, 1), 256, smem0>>>(
        ph2hi, ph2lo, pWThi, pWTlo, F_, F_, F_,
        0, 0, pdinv, 0, nullptr,
        pgThi, pgTlo, C_, 0, nullptr);
    mma_gemm<3><<<dim3(F_ / 128, C_ / 128, B_), 256, smem1>>>(
        pA, nullptr, pgThi, pgTlo, C_, C_, C_,
        (size_t)C_ * C_, (size_t)F_ * C_, pdinv, C_, b2,
        out, nullptr, F_, (size_t)C_ * F_, nullptr);
}

// round 10
// speedup vs baseline: 4.3753x; 1.3045x over previous
#include <cuda_runtime.h>
#include <cuda_fp16.h>
#include <cstdint>
#include <math.h>

#define B_ 8
#define C_ 2048
#define F_ 512
#define THRESH 0.005f

// ---- scratch (device globals: no allocation allowed) ----
__device__ __half g_A[(size_t)B_ * C_ * C_];       // binary adjacency (fp16 0/1)
__device__ float  g_invn[B_ * C_];
__device__ float  g_deg[B_ * C_];
__device__ float  g_dinv[B_ * C_];
__device__ __half g_xhi[(size_t)B_ * C_ * F_];
__device__ __half g_xlo[(size_t)B_ * C_ * F_];
__device__ __half g_gT[(size_t)B_ * F_ * C_];      // (dinv*(h@W))^T  fp16
__device__ __half g_h2_hi[(size_t)B_ * C_ * F_];   // hidden activations split
__device__ __half g_h2_lo[(size_t)B_ * C_ * F_];
__device__ __half g_WT_hi[F_ * F_];
__device__ __half g_WT_lo[F_ * F_];

// =============================== helpers ===============================
__device__ __forceinline__ uint32_t smem_u32(const void* p) {
    uint32_t a;
    asm("{ .reg .u64 t; cvta.to.shared.u64 t, %1; cvt.u32.u64 %0, t; }" : "=r"(a) : "l"(p));
    return a;
}
#define CP_COMMIT() asm volatile("cp.async.commit_group;" ::: "memory")
#define CP_WAIT1()  asm volatile("cp.async.wait_group 1;" ::: "memory")
#define CP_WAIT0()  asm volatile("cp.async.wait_group 0;" ::: "memory")

__device__ __forceinline__ void mma_f16(float c[4], const uint32_t a[4], const uint32_t b[2]) {
    asm volatile(
        "mma.sync.aligned.m16n8k16.row.col.f32.f16.f16.f32 "
        "{%0,%1,%2,%3}, {%4,%5,%6,%7}, {%8,%9}, {%0,%1,%2,%3};"
        : "+f"(c[0]), "+f"(c[1]), "+f"(c[2]), "+f"(c[3])
        : "r"(a[0]), "r"(a[1]), "r"(a[2]), "r"(a[3]), "r"(b[0]), "r"(b[1]));
}
__device__ __forceinline__ void ldsm4(uint32_t r[4], uint32_t addr) {
    asm volatile("ldmatrix.sync.aligned.m8n8.x4.shared.b16 {%0,%1,%2,%3}, [%4];"
        : "=r"(r[0]), "=r"(r[1]), "=r"(r[2]), "=r"(r[3]) : "r"(addr));
}
// swizzled byte offset inside one 128-row tile; KCC = K-chunk width (32 or 64 halves)
template <int KCC>
__device__ __forceinline__ uint32_t swz(int row, int seg) {
    if (KCC == 64) return (uint32_t)(row * 128 + ((seg ^ (row & 7)) << 4));
    return (uint32_t)(row * 64 + ((seg ^ ((row >> 1) & 3)) << 4));
}

// ====================== fp16 mma GEMM (128x128 tile) ======================
// All operands row-major with K contiguous: Aop[m][k] (lda), Bop[n][k] (ldb).
// MODE 0: GRAM (symmetric blocks, KC32): 3 passes; binarize; A tile+mirror; deg atomics
// MODE 2: HWT  (KC32) g = h@WT, 3 passes ; epi: *dinv[row], transpose -> gT fp16
// MODE 1: AH   (KC64) A@gT, 1 pass       ; epi: relu(*dinv[m]+bias) -> split hi/lo
// MODE 3: AH   (KC64) A@gT, 1 pass       ; epi: relu(*dinv[m]+bias) -> fp32

template <int MODE>
__global__ __launch_bounds__(256, 2) void mma_gemm(
    const __half* __restrict__ a0, const __half* __restrict__ a1,
    const __half* __restrict__ b0, const __half* __restrict__ b1,
    int lda, int ldb, int K,
    size_t aBatch, size_t bBatch,
    const float* __restrict__ aux, int auxBatch,
    const float* __restrict__ bias,
    void* __restrict__ out0, void* __restrict__ out1,
    int ldo, size_t oBatch,
    float* __restrict__ deg)
{
    constexpr bool ISAH = (MODE == 1 || MODE == 3);
    constexpr int NA   = ISAH ? 1 : 2;
    constexpr int NB   = ISAH ? 1 : 2;
    constexpr int NOPS = NA + NB;
    constexpr int KCC  = ISAH ? 64 : 32;
    constexpr int TB   = 128 * KCC * 2;          // tile bytes
    constexpr int NKS  = KCC / 16;

    int m0, n0, b = blockIdx.z;
    if (MODE == 0) {
        int idx = blockIdx.x, bi = 0;
        while (idx >= (C_ / 128 - bi)) { idx -= (C_ / 128 - bi); bi++; }
        m0 = bi * 128; n0 = (bi + idx) * 128;
    } else {
        m0 = blockIdx.y * 128; n0 = blockIdx.x * 128;
    }

    int tid = threadIdx.x, wid = tid >> 5, lane = tid & 31;
    int wm = wid & 1, wn = wid >> 1;          // warp tile 64x32
    int g = lane >> 2, t = lane & 3;

    const __half* ops[NOPS];
    int ldv[NOPS];
    ops[0] = a0 + (size_t)b * aBatch + (size_t)m0 * lda; ldv[0] = lda;
    if (NA == 2) { ops[1] = a1 + (size_t)b * aBatch + (size_t)m0 * lda; ldv[1] = lda; }
    ops[NA] = b0 + (size_t)b * bBatch + (size_t)n0 * ldb; ldv[NA] = ldb;
    if (NB == 2) { ops[NA + 1] = b1 + (size_t)b * bBatch + (size_t)n0 * ldb; ldv[NA + 1] = ldb; }

    extern __shared__ __half sm[];
    uint32_t smb = smem_u32(sm);

    auto load_tile = [&](int op, int buf, int k0) {
        uint32_t st = smb + (uint32_t)(buf * NOPS + op) * TB;
        const __half* src = ops[op] + k0;
        int ld = ldv[op];
        constexpr int ITER = (128 * KCC / 8) / 256;
#pragma unroll
        for (int i2 = 0; i2 < ITER; i2++) {
            int idx = tid + i2 * 256;
            int row, seg;
            if (KCC == 64) { row = idx >> 3; seg = idx & 7; }
            else           { row = idx >> 2; seg = idx & 3; }
            const __half* gp = src + (size_t)row * ld + seg * 8;
            uint32_t sa = st + swz<KCC>(row, seg);
            asm volatile("cp.async.cg.shared.global [%0], [%1], 16;" :: "r"(sa), "l"(gp) : "memory");
        }
    };

    float acc[4][4][4];
#pragma unroll
    for (int i = 0; i < 4; i++)
#pragma unroll
        for (int j = 0; j < 4; j++)
#pragma unroll
            for (int r = 0; r < 4; r++) acc[i][j][r] = 0.f;

    int a_row = ((lane >> 3) & 1) * 8 + (lane & 7);
    int a_sg  = lane >> 4;
    int b_row = ((lane >> 4) & 1) * 8 + (lane & 7);
    int b_sg  = (lane >> 3) & 1;

    uint32_t afr[NA][4][4];
    uint32_t bfr0[4][2], bfr1[4][2];

    auto compute = [&](int buf) {
        uint32_t tb = smb + (uint32_t)(buf * NOPS) * TB;
#pragma unroll
        for (int ks = 0; ks < NKS; ks++) {
            int segA = 2 * ks + a_sg;
            int segB = 2 * ks + b_sg;
#pragma unroll
            for (int i = 0; i < 4; i++)
                ldsm4(afr[0][i], tb + swz<KCC>(wm * 64 + i * 16 + a_row, segA));
            if (NA == 2) {
#pragma unroll
                for (int i = 0; i < 4; i++)
                    ldsm4(afr[NA - 1][i], tb + TB + swz<KCC>(wm * 64 + i * 16 + a_row, segA));
            }
            uint32_t tB0 = tb + (uint32_t)NA * TB;
            ldsm4(&bfr0[0][0], tB0 + swz<KCC>(wn * 32 + b_row, segB));
            ldsm4(&bfr0[2][0], tB0 + swz<KCC>(wn * 32 + 16 + b_row, segB));
            if (NB == 2) {
                uint32_t tB1 = tB0 + TB;
                ldsm4(&bfr1[0][0], tB1 + swz<KCC>(wn * 32 + b_row, segB));
                ldsm4(&bfr1[2][0], tB1 + swz<KCC>(wn * 32 + 16 + b_row, segB));
            }
#pragma unroll
            for (int i = 0; i < 4; i++)
#pragma unroll
                for (int j = 0; j < 4; j++) mma_f16(acc[i][j], afr[0][i], bfr0[j]);
            if (NA == 2) {
#pragma unroll
                for (int i = 0; i < 4; i++)
#pragma unroll
                    for (int j = 0; j < 4; j++) mma_f16(acc[i][j], afr[NA - 1][i], bfr0[j]);
            }
            if (NB == 2) {
#pragma unroll
                for (int i = 0; i < 4; i++)
#pragma unroll
                    for (int j = 0; j < 4; j++) mma_f16(acc[i][j], afr[0][i], bfr1[j]);
            }
        }
    };

    const int NC = K / KCC;
    for (int op = 0; op < NOPS; op++) load_tile(op, 0, 0);
    CP_COMMIT();
    if (NC > 1) {
        for (int op = 0; op < NOPS; op++) load_tile(op, 1, KCC);
        CP_COMMIT();
    }
    for (int c = 0; c < NC; c++) {
        if (c + 1 < NC) { CP_WAIT1(); } else { CP_WAIT0(); }
        __syncthreads();
        if (c + 2 < NC) {
            for (int op = 0; op < NOPS; op++) load_tile(op, (c + 2) % 3, (c + 2) * KCC);
            CP_COMMIT();
        }
        compute(c % 3);
    }

    // ------------------------------- epilogues -------------------------------
    if (MODE == 0) {
        const float* inb = aux + (size_t)b * auxBatch;
        __half* Ab = (__half*)out0 + (size_t)b * oBatch;
        float* degb = deg + (size_t)b * C_;
        float v[4][4][4];
#pragma unroll
        for (int i = 0; i < 4; i++) {
            int r0 = m0 + wm * 64 + i * 16 + g;
            float rs0 = inb[r0], rs1 = inb[r0 + 8];
#pragma unroll
            for (int j = 0; j < 4; j++) {
                int cl = n0 + wn * 32 + j * 8 + t * 2;
                float j0 = inb[cl], j1 = inb[cl + 1];
                v[i][j][0] = (acc[i][j][0] * rs0 * j0 > THRESH) ? 1.f : 0.f;
                v[i][j][1] = (acc[i][j][1] * rs0 * j1 > THRESH) ? 1.f : 0.f;
                v[i][j][2] = (acc[i][j][2] * rs1 * j0 > THRESH) ? 1.f : 0.f;
                v[i][j][3] = (acc[i][j][3] * rs1 * j1 > THRESH) ? 1.f : 0.f;
                *(__half2*)(Ab + (size_t)r0 * ldo + cl)       = __floats2half2_rn(v[i][j][0], v[i][j][1]);
                *(__half2*)(Ab + (size_t)(r0 + 8) * ldo + cl) = __floats2half2_rn(v[i][j][2], v[i][j][3]);
            }
        }
#pragma unroll
        for (int i = 0; i < 4; i++) {
            float s0 = 0.f, s1 = 0.f;
#pragma unroll
            for (int j = 0; j < 4; j++) {
                s0 += v[i][j][0] + v[i][j][1];
                s1 += v[i][j][2] + v[i][j][3];
            }
            s0 += __shfl_xor_sync(0xFFFFFFFFu, s0, 1); s0 += __shfl_xor_sync(0xFFFFFFFFu, s0, 2);
            s1 += __shfl_xor_sync(0xFFFFFFFFu, s1, 1); s1 += __shfl_xor_sync(0xFFFFFFFFu, s1, 2);
            if (t == 0) {
                atomicAdd(&degb[m0 + wm * 64 + i * 16 + g], s0);
                atomicAdd(&degb[m0 + wm * 64 + i * 16 + g + 8], s1);
            }
        }
        if (m0 != n0) {
#pragma unroll
            for (int j = 0; j < 4; j++) {
                float c0 = 0.f, c1 = 0.f;
#pragma unroll
                for (int i = 0; i < 4; i++) {
                    c0 += v[i][j][0] + v[i][j][2];
                    c1 += v[i][j][1] + v[i][j][3];
                }
                c0 += __shfl_xor_sync(0xFFFFFFFFu, c0, 4); c0 += __shfl_xor_sync(0xFFFFFFFFu, c0, 8); c0 += __shfl_xor_sync(0xFFFFFFFFu, c0, 16);
                c1 += __shfl_xor_sync(0xFFFFFFFFu, c1, 4); c1 += __shfl_xor_sync(0xFFFFFFFFu, c1, 8); c1 += __shfl_xor_sync(0xFFFFFFFFu, c1, 16);
                if (lane < 4) {
                    atomicAdd(&degb[n0 + wn * 32 + j * 8 + t * 2], c0);
                    atomicAdd(&degb[n0 + wn * 32 + j * 8 + t * 2 + 1], c1);
                }
            }
            __syncthreads();
            float* stage = (float*)sm;                 // 128 x 129 floats
#pragma unroll
            for (int i = 0; i < 4; i++) {
                int rr = wm * 64 + i * 16 + g;
#pragma unroll
                for (int j = 0; j < 4; j++) {
                    int cc = wn * 32 + j * 8 + t * 2;
                    stage[rr * 129 + cc]           = v[i][j][0];
                    stage[rr * 129 + cc + 1]       = v[i][j][1];
                    stage[(rr + 8) * 129 + cc]     = v[i][j][2];
                    stage[(rr + 8) * 129 + cc + 1] = v[i][j][3];
                }
            }
            __syncthreads();
#pragma unroll
            for (int q = 0; q < 16; q++) {
                int idx = tid + q * 256;
                int r = idx >> 5;
                int c4 = (idx & 31) * 4;
                float f0 = stage[(c4 + 0) * 129 + r];
                float f1 = stage[(c4 + 1) * 129 + r];
                float f2 = stage[(c4 + 2) * 129 + r];
                float f3 = stage[(c4 + 3) * 129 + r];
                __half* dst = Ab + (size_t)(n0 + r) * ldo + m0 + c4;
                ((__half2*)dst)[0] = __floats2half2_rn(f0, f1);
                ((__half2*)dst)[1] = __floats2half2_rn(f2, f3);
            }
        }
    } else if (MODE == 2) {
        // g = h@WT row-scale by dinv[global row], transpose -> gT fp16 [b][f][c]
        const float* db = aux;                       // flattened dinv, index m0+row
        __syncthreads();
        float* stage = (float*)sm;                   // 128 x 129 floats
#pragma unroll
        for (int i = 0; i < 4; i++) {
            int rr = wm * 64 + i * 16 + g;
            float d0 = db[m0 + rr], d1 = db[m0 + rr + 8];
#pragma unroll
            for (int j = 0; j < 4; j++) {
                int cc = wn * 32 + j * 8 + t * 2;
                stage[rr * 129 + cc]           = acc[i][j][0] * d0;
                stage[rr * 129 + cc + 1]       = acc[i][j][1] * d0;
                stage[(rr + 8) * 129 + cc]     = acc[i][j][2] * d1;
                stage[(rr + 8) * 129 + cc + 1] = acc[i][j][3] * d1;
            }
        }
        __syncthreads();
        int bb = m0 / C_;
        int cb = m0 % C_;
        __half* ghi = (__half*)out0;
#pragma unroll
        for (int q = 0; q < 16; q++) {
            int idx = tid + q * 256;
            int r = idx >> 5;                         // local f
            int c4 = (idx & 31) * 4;                  // local c, 4-aligned
            float f0 = stage[(c4 + 0) * 129 + r];
            float f1 = stage[(c4 + 1) * 129 + r];
            float f2 = stage[(c4 + 2) * 129 + r];
            float f3 = stage[(c4 + 3) * 129 + r];
            size_t o = ((size_t)bb * F_ + n0 + r) * C_ + cb + c4;
            ((__half2*)(ghi + o))[0] = __floats2half2_rn(f0, f1);
            ((__half2*)(ghi + o))[1] = __floats2half2_rn(f2, f3);
        }
    } else {
        // AH: v = relu(acc * dinv[m] + bias)
        const float* db = aux + (size_t)b * auxBatch;
        float bs = bias[0];
#pragma unroll
        for (int i = 0; i < 4; i++) {
            int r0 = m0 + wm * 64 + i * 16 + g;
            float rs0 = db[r0], rs1 = db[r0 + 8];
#pragma unroll
            for (int j = 0; j < 4; j++) {
                int cl = n0 + wn * 32 + j * 8 + t * 2;
                float v00 = fmaxf(acc[i][j][0] * rs0 + bs, 0.f);
                float v01 = fmaxf(acc[i][j][1] * rs0 + bs, 0.f);
                float v10 = fmaxf(acc[i][j][2] * rs1 + bs, 0.f);
                float v11 = fmaxf(acc[i][j][3] * rs1 + bs, 0.f);
                if (MODE == 1) {
                    __half* o0 = (__half*)out0 + (size_t)b * oBatch;
                    __half* o1 = (__half*)out1 + (size_t)b * oBatch;
                    __half h00 = __float2half_rn(v00), h01 = __float2half_rn(v01);
                    __half h10 = __float2half_rn(v10), h11 = __float2half_rn(v11);
                    *(__half2*)(o0 + (size_t)r0 * ldo + cl)       = __halves2half2(h00, h01);
                    *(__half2*)(o0 + (size_t)(r0 + 8) * ldo + cl) = __halves2half2(h10, h11);
                    *(__half2*)(o1 + (size_t)r0 * ldo + cl) =
                        __floats2half2_rn(v00 - __half2float(h00), v01 - __half2float(h01));
                    *(__half2*)(o1 + (size_t)(r0 + 8) * ldo + cl) =
                        __floats2half2_rn(v10 - __half2float(h10), v11 - __half2float(h11));
                } else {
                    float* o = (float*)out0 + (size_t)b * oBatch;
                    *(float2*)(o + (size_t)r0 * ldo + cl)       = make_float2(v00, v01);
                    *(float2*)(o + (size_t)(r0 + 8) * ldo + cl) = make_float2(v10, v11);
                }
            }
        }
    }
}

// =============================== small kernels ==============================
__global__ void zero_kernel(float* __restrict__ p) {
    p[blockIdx.x * 256 + threadIdx.x] = 0.f;
}

// fused: row inv-norms + fp16 hi/lo split of x
__global__ void norm_split(const float* __restrict__ x, float* __restrict__ invn,
                           __half* __restrict__ hi, __half* __restrict__ lo) {
    int row = blockIdx.x;
    const float* xr = x + (size_t)row * F_;
    float4 v = ((const float4*)xr)[threadIdx.x];
    float s = v.x * v.x + v.y * v.y + v.z * v.z + v.w * v.w;
#pragma unroll
    for (int o = 16; o > 0; o >>= 1) s += __shfl_xor_sync(0xFFFFFFFFu, s, o);
    __shared__ float red[4];
    if ((threadIdx.x & 31) == 0) red[threadIdx.x >> 5] = s;
    __syncthreads();
    if (threadIdx.x == 0)
        invn[row] = 1.0f / sqrtf(red[0] + red[1] + red[2] + red[3]);

    __half h0 = __float2half_rn(v.x), h1 = __float2half_rn(v.y);
    __half h2 = __float2half_rn(v.z), h3 = __float2half_rn(v.w);
    size_t o = (size_t)row * F_ + threadIdx.x * 4;
    *(__half2*)(hi + o)     = __halves2half2(h0, h1);
    *(__half2*)(hi + o + 2) = __halves2half2(h2, h3);
    *(__half2*)(lo + o)     = __floats2half2_rn(v.x - __half2float(h0), v.y - __half2float(h1));
    *(__half2*)(lo + o + 2) = __floats2half2_rn(v.z - __half2float(h2), v.w - __half2float(h3));
}

__global__ void dinv_kernel(const float* __restrict__ deg, float* __restrict__ dinv) {
    int i = blockIdx.x * 256 + threadIdx.x;
    dinv[i] = 1.0f / sqrtf(deg[i]);
}

// W[f,g] -> WT[g,f] split (fp16)
__global__ void wtrans_kernel(const float* __restrict__ W,
                              __half* __restrict__ hi, __half* __restrict__ lo) {
    __shared__ float tsm[32][33];
    int g0 = blockIdx.x * 32, f0 = blockIdx.y * 32;
#pragma unroll
    for (int k = 0; k < 4; k++) {
        int f = f0 + threadIdx.y + k * 8;
        tsm[threadIdx.x][threadIdx.y + k * 8] = W[(size_t)f * F_ + g0 + threadIdx.x];
    }
    __syncthreads();
#pragma unroll
    for (int k = 0; k < 4; k++) {
        int gg = g0 + threadIdx.y + k * 8;
        float v = tsm[threadIdx.y + k * 8][threadIdx.x];
        __half hh = __float2half_rn(v);
        size_t o = (size_t)gg * F_ + f0 + threadIdx.x;
        hi[o] = hh;
        lo[o] = __float2half_rn(v - __half2float(hh));
    }
}

// ============================================================================
extern "C" void kernel_launch(void* const* d_in, const int* in_sizes, int n_in,
                              void* d_out, int out_size) {
    const float* x  = (const float*)d_in[0];
    const float* W1 = (const float*)d_in[1];
    const float* b1 = (const float*)d_in[2];
    const float* W2 = (const float*)d_in[3];
    const float* b2 = (const float*)d_in[4];
    float* out = (float*)d_out;

    __half *pA, *pxhi, *pxlo, *pgT, *ph2hi, *ph2lo, *pWThi, *pWTlo;
    float *pinvn, *pdeg, *pdinv;
    cudaGetSymbolAddress((void**)&pA,    g_A);
    cudaGetSymbolAddress((void**)&pinvn, g_invn);
    cudaGetSymbolAddress((void**)&pdeg,  g_deg);
    cudaGetSymbolAddress((void**)&pdinv, g_dinv);
    cudaGetSymbolAddress((void**)&pxhi,  g_xhi);
    cudaGetSymbolAddress((void**)&pxlo,  g_xlo);
    cudaGetSymbolAddress((void**)&pgT,   g_gT);
    cudaGetSymbolAddress((void**)&ph2hi, g_h2_hi);
    cudaGetSymbolAddress((void**)&ph2lo, g_h2_lo);
    cudaGetSymbolAddress((void**)&pWThi, g_WT_hi);
    cudaGetSymbolAddress((void**)&pWTlo, g_WT_lo);

    const int smem0 = 4 * 3 * (128 * 32 * 2);   // 98304 B (GRAM / HWT)
    const int smem1 = 2 * 3 * (128 * 64 * 2);   // 98304 B (AH: 2 ops, KC=64, 3 stages)
    cudaFuncSetAttribute(mma_gemm<0>, cudaFuncAttributeMaxDynamicSharedMemorySize, smem0);
    cudaFuncSetAttribute(mma_gemm<1>, cudaFuncAttributeMaxDynamicSharedMemorySize, smem1);
    cudaFuncSetAttribute(mma_gemm<2>, cudaFuncAttributeMaxDynamicSharedMemorySize, smem0);
    cudaFuncSetAttribute(mma_gemm<3>, cudaFuncAttributeMaxDynamicSharedMemorySize, smem1);

    const int NBLK = C_ / 128;                       // 16
    const int NTRI = NBLK * (NBLK + 1) / 2;          // 136

    // ---- Laplacian ----
    zero_kernel<<<(B_ * C_) / 256, 256>>>(pdeg);
    norm_split<<<B_ * C_, 128>>>(x, pinvn, pxhi, pxlo);
    mma_gemm<0><<<dim3(NTRI, 1, B_), 256, smem0>>>(
        pxhi, pxlo, pxhi, pxlo, F_, F_, F_,
        (size_t)C_ * F_, (size_t)C_ * F_, pinvn, C_, nullptr,
        pA, nullptr, C_, (size_t)C_ * C_, pdeg);
    dinv_kernel<<<(B_ * C_) / 256, 256>>>(pdeg, pdinv);

    // ---- layer 1: relu(L @ (x @ W1) + b1) ----
    wtrans_kernel<<<dim3(F_ / 32, F_ / 32), dim3(32, 8)>>>(W1, pWThi, pWTlo);
    mma_gemm<2><<<dim3(F_ / 128, (B_ * C_) / 128, 1), 256, smem0>>>(
        pxhi, pxlo, pWThi, pWTlo, F_, F_, F_,
        0, 0, pdinv, 0, nullptr,
        pgT, nullptr, C_, 0, nullptr);
    mma_gemm<1><<<dim3(F_ / 128, C_ / 128, B_), 256, smem1>>>(
        pA, nullptr, pgT, nullptr, C_, C_, C_,
        (size_t)C_ * C_, (size_t)F_ * C_, pdinv, C_, b1,
        ph2hi, ph2lo, F_, (size_t)C_ * F_, nullptr);

    // ---- layer 2: relu(L @ (h2 @ W2) + b2) ----
    wtrans_kernel<<<dim3(F_ / 32, F_ / 32), dim3(32, 8)>>>(W2, pWThi, pWTlo);
    mma_gemm<2><<<dim3(F_ / 128, (B_ * C_) / 128, 1), 256, smem0>>>(
        ph2hi, ph2lo, pWThi, pWTlo, F_, F_, F_,
        0, 0, pdinv, 0, nullptr,
        pgT, nullptr, C_, 0, nullptr);
    mma_gemm<3><<<dim3(F_ / 128, C_ / 128, B_), 256, smem1>>>(
        pA, nullptr, pgT, nullptr, C_, C_, C_,
        (size_t)C_ * C_, (size_t)F_ * C_, pdinv, C_, b2,
        out, nullptr, F_, (size_t)C_ * F_, nullptr);
}

// round 11
// speedup vs baseline: 4.7312x; 1.0814x over previous
#include <cuda_runtime.h>
#include <cuda_fp16.h>
#include <cstdint>
#include <math.h>

#define B_ 8
#define C_ 2048
#define F_ 512
#define THRESH 0.005f

// ---- scratch (device globals: no allocation allowed) ----
__device__ __half g_A[(size_t)B_ * C_ * C_];       // binary adjacency (fp16 0/1)
__device__ float  g_invn[B_ * C_];
__device__ float  g_deg[B_ * C_];
__device__ float  g_dinv[B_ * C_];
__device__ __half g_xhi[(size_t)B_ * C_ * F_];
__device__ __half g_xlo[(size_t)B_ * C_ * F_];
__device__ __half g_gT[(size_t)B_ * F_ * C_];      // (dinv*(h@W))^T  fp16
__device__ __half g_h2_hi[(size_t)B_ * C_ * F_];   // hidden activations split
__device__ __half g_h2_lo[(size_t)B_ * C_ * F_];
__device__ __half g_WT[F_ * F_];                   // W^T single fp16

// =============================== helpers ===============================
__device__ __forceinline__ uint32_t smem_u32(const void* p) {
    uint32_t a;
    asm("{ .reg .u64 t; cvta.to.shared.u64 t, %1; cvt.u32.u64 %0, t; }" : "=r"(a) : "l"(p));
    return a;
}
#define CP_COMMIT() asm volatile("cp.async.commit_group;" ::: "memory")
#define CP_WAIT1()  asm volatile("cp.async.wait_group 1;" ::: "memory")
#define CP_WAIT0()  asm volatile("cp.async.wait_group 0;" ::: "memory")

__device__ __forceinline__ void mma_f16(float c[4], const uint32_t a[4], const uint32_t b[2]) {
    asm volatile(
        "mma.sync.aligned.m16n8k16.row.col.f32.f16.f16.f32 "
        "{%0,%1,%2,%3}, {%4,%5,%6,%7}, {%8,%9}, {%0,%1,%2,%3};"
        : "+f"(c[0]), "+f"(c[1]), "+f"(c[2]), "+f"(c[3])
        : "r"(a[0]), "r"(a[1]), "r"(a[2]), "r"(a[3]), "r"(b[0]), "r"(b[1]));
}
__device__ __forceinline__ void ldsm4(uint32_t r[4], uint32_t addr) {
    asm volatile("ldmatrix.sync.aligned.m8n8.x4.shared.b16 {%0,%1,%2,%3}, [%4];"
        : "=r"(r[0]), "=r"(r[1]), "=r"(r[2]), "=r"(r[3]) : "r"(addr));
}
// swizzled byte offset inside one 128-row tile; KCC = K-chunk width (32 or 64 halves)
template <int KCC>
__device__ __forceinline__ uint32_t swz(int row, int seg) {
    if (KCC == 64) return (uint32_t)(row * 128 + ((seg ^ (row & 7)) << 4));
    return (uint32_t)(row * 64 + ((seg ^ ((row >> 1) & 3)) << 4));
}

// ====================== fp16 mma GEMM (128x128 tile) ======================
// All operands row-major with K contiguous: Aop[m][k] (lda), Bop[n][k] (ldb).
// MODE 0: GRAM (symmetric blocks, KC32): NA=2,NB=2, 3 passes; binarize; mirror; deg
// MODE 2: HWT  (KC32) NA=2,NB=1, 2 passes: g = (xhi+xlo)@WT ; epi: *dinv, transpose->gT
// MODE 1: AH   (KC64) NA=1,NB=1, 1 pass: A@gT ; epi: relu(*dinv[m]+bias) -> split hi/lo
// MODE 3: AH   (KC64) same, epi -> fp32

template <int MODE>
__global__ __launch_bounds__(256, 2) void mma_gemm(
    const __half* __restrict__ a0, const __half* __restrict__ a1,
    const __half* __restrict__ b0, const __half* __restrict__ b1,
    int lda, int ldb, int K,
    size_t aBatch, size_t bBatch,
    const float* __restrict__ aux, int auxBatch,
    const float* __restrict__ bias,
    void* __restrict__ out0, void* __restrict__ out1,
    int ldo, size_t oBatch,
    float* __restrict__ deg)
{
    constexpr bool ISAH = (MODE == 1 || MODE == 3);
    constexpr int NA   = ISAH ? 1 : 2;
    constexpr int NB   = (MODE == 0) ? 2 : 1;
    constexpr int NOPS = NA + NB;
    constexpr int KCC  = ISAH ? 64 : 32;
    constexpr int TB   = 128 * KCC * 2;          // tile bytes
    constexpr int NKS  = KCC / 16;

    int m0, n0, b = blockIdx.z;
    if (MODE == 0) {
        int idx = blockIdx.x, bi = 0;
        while (idx >= (C_ / 128 - bi)) { idx -= (C_ / 128 - bi); bi++; }
        m0 = bi * 128; n0 = (bi + idx) * 128;
    } else {
        m0 = blockIdx.y * 128; n0 = blockIdx.x * 128;
    }

    int tid = threadIdx.x, wid = tid >> 5, lane = tid & 31;
    int wm = wid & 1, wn = wid >> 1;          // warp tile 64x32
    int g = lane >> 2, t = lane & 3;

    const __half* ops[NOPS];
    int ldv[NOPS];
    ops[0] = a0 + (size_t)b * aBatch + (size_t)m0 * lda; ldv[0] = lda;
    if (NA == 2) { ops[1] = a1 + (size_t)b * aBatch + (size_t)m0 * lda; ldv[1] = lda; }
    ops[NA] = b0 + (size_t)b * bBatch + (size_t)n0 * ldb; ldv[NA] = ldb;
    if (NB == 2) { ops[NA + 1] = b1 + (size_t)b * bBatch + (size_t)n0 * ldb; ldv[NA + 1] = ldb; }

    extern __shared__ __half sm[];
    uint32_t smb = smem_u32(sm);

    auto load_tile = [&](int op, int buf, int k0) {
        uint32_t st = smb + (uint32_t)(buf * NOPS + op) * TB;
        const __half* src = ops[op] + k0;
        int ld = ldv[op];
        constexpr int ITER = (128 * KCC / 8) / 256;
#pragma unroll
        for (int i2 = 0; i2 < ITER; i2++) {
            int idx = tid + i2 * 256;
            int row, seg;
            if (KCC == 64) { row = idx >> 3; seg = idx & 7; }
            else           { row = idx >> 2; seg = idx & 3; }
            const __half* gp = src + (size_t)row * ld + seg * 8;
            uint32_t sa = st + swz<KCC>(row, seg);
            asm volatile("cp.async.cg.shared.global [%0], [%1], 16;" :: "r"(sa), "l"(gp) : "memory");
        }
    };

    float acc[4][4][4];
#pragma unroll
    for (int i = 0; i < 4; i++)
#pragma unroll
        for (int j = 0; j < 4; j++)
#pragma unroll
            for (int r = 0; r < 4; r++) acc[i][j][r] = 0.f;

    int a_row = ((lane >> 3) & 1) * 8 + (lane & 7);
    int a_sg  = lane >> 4;
    int b_row = ((lane >> 4) & 1) * 8 + (lane & 7);
    int b_sg  = (lane >> 3) & 1;

    uint32_t afr[NA][4][4];
    uint32_t bfr0[4][2], bfr1[4][2];

    auto compute = [&](int buf) {
        uint32_t tb = smb + (uint32_t)(buf * NOPS) * TB;
#pragma unroll
        for (int ks = 0; ks < NKS; ks++) {
            int segA = 2 * ks + a_sg;
            int segB = 2 * ks + b_sg;
#pragma unroll
            for (int i = 0; i < 4; i++)
                ldsm4(afr[0][i], tb + swz<KCC>(wm * 64 + i * 16 + a_row, segA));
            if (NA == 2) {
#pragma unroll
                for (int i = 0; i < 4; i++)
                    ldsm4(afr[NA - 1][i], tb + TB + swz<KCC>(wm * 64 + i * 16 + a_row, segA));
            }
            uint32_t tB0 = tb + (uint32_t)NA * TB;
            ldsm4(&bfr0[0][0], tB0 + swz<KCC>(wn * 32 + b_row, segB));
            ldsm4(&bfr0[2][0], tB0 + swz<KCC>(wn * 32 + 16 + b_row, segB));
            if (NB == 2) {
                uint32_t tB1 = tB0 + TB;
                ldsm4(&bfr1[0][0], tB1 + swz<KCC>(wn * 32 + b_row, segB));
                ldsm4(&bfr1[2][0], tB1 + swz<KCC>(wn * 32 + 16 + b_row, segB));
            }
#pragma unroll
            for (int i = 0; i < 4; i++)
#pragma unroll
                for (int j = 0; j < 4; j++) mma_f16(acc[i][j], afr[0][i], bfr0[j]);
            if (NA == 2) {
#pragma unroll
                for (int i = 0; i < 4; i++)
#pragma unroll
                    for (int j = 0; j < 4; j++) mma_f16(acc[i][j], afr[NA - 1][i], bfr0[j]);
            }
            if (NB == 2) {
#pragma unroll
                for (int i = 0; i < 4; i++)
#pragma unroll
                    for (int j = 0; j < 4; j++) mma_f16(acc[i][j], afr[0][i], bfr1[j]);
            }
        }
    };

    const int NC = K / KCC;
    for (int op = 0; op < NOPS; op++) load_tile(op, 0, 0);
    CP_COMMIT();
    if (NC > 1) {
        for (int op = 0; op < NOPS; op++) load_tile(op, 1, KCC);
        CP_COMMIT();
    }
    for (int c = 0; c < NC; c++) {
        if (c + 1 < NC) { CP_WAIT1(); } else { CP_WAIT0(); }
        __syncthreads();
        if (c + 2 < NC) {
            for (int op = 0; op < NOPS; op++) load_tile(op, (c + 2) % 3, (c + 2) * KCC);
            CP_COMMIT();
        }
        compute(c % 3);
    }

    // ------------------------------- epilogues -------------------------------
    if (MODE == 0) {
        const float* inb = aux + (size_t)b * auxBatch;
        __half* Ab = (__half*)out0 + (size_t)b * oBatch;
        float* degb = deg + (size_t)b * C_;
        float v[4][4][4];
#pragma unroll
        for (int i = 0; i < 4; i++) {
            int r0 = m0 + wm * 64 + i * 16 + g;
            float rs0 = inb[r0], rs1 = inb[r0 + 8];
#pragma unroll
            for (int j = 0; j < 4; j++) {
                int cl = n0 + wn * 32 + j * 8 + t * 2;
                float j0 = inb[cl], j1 = inb[cl + 1];
                v[i][j][0] = (acc[i][j][0] * rs0 * j0 > THRESH) ? 1.f : 0.f;
                v[i][j][1] = (acc[i][j][1] * rs0 * j1 > THRESH) ? 1.f : 0.f;
                v[i][j][2] = (acc[i][j][2] * rs1 * j0 > THRESH) ? 1.f : 0.f;
                v[i][j][3] = (acc[i][j][3] * rs1 * j1 > THRESH) ? 1.f : 0.f;
                *(__half2*)(Ab + (size_t)r0 * ldo + cl)       = __floats2half2_rn(v[i][j][0], v[i][j][1]);
                *(__half2*)(Ab + (size_t)(r0 + 8) * ldo + cl) = __floats2half2_rn(v[i][j][2], v[i][j][3]);
            }
        }
#pragma unroll
        for (int i = 0; i < 4; i++) {
            float s0 = 0.f, s1 = 0.f;
#pragma unroll
            for (int j = 0; j < 4; j++) {
                s0 += v[i][j][0] + v[i][j][1];
                s1 += v[i][j][2] + v[i][j][3];
            }
            s0 += __shfl_xor_sync(0xFFFFFFFFu, s0, 1); s0 += __shfl_xor_sync(0xFFFFFFFFu, s0, 2);
            s1 += __shfl_xor_sync(0xFFFFFFFFu, s1, 1); s1 += __shfl_xor_sync(0xFFFFFFFFu, s1, 2);
            if (t == 0) {
                atomicAdd(&degb[m0 + wm * 64 + i * 16 + g], s0);
                atomicAdd(&degb[m0 + wm * 64 + i * 16 + g + 8], s1);
            }
        }
        if (m0 != n0) {
#pragma unroll
            for (int j = 0; j < 4; j++) {
                float c0 = 0.f, c1 = 0.f;
#pragma unroll
                for (int i = 0; i < 4; i++) {
                    c0 += v[i][j][0] + v[i][j][2];
                    c1 += v[i][j][1] + v[i][j][3];
                }
                c0 += __shfl_xor_sync(0xFFFFFFFFu, c0, 4); c0 += __shfl_xor_sync(0xFFFFFFFFu, c0, 8); c0 += __shfl_xor_sync(0xFFFFFFFFu, c0, 16);
                c1 += __shfl_xor_sync(0xFFFFFFFFu, c1, 4); c1 += __shfl_xor_sync(0xFFFFFFFFu, c1, 8); c1 += __shfl_xor_sync(0xFFFFFFFFu, c1, 16);
                if (lane < 4) {
                    atomicAdd(&degb[n0 + wn * 32 + j * 8 + t * 2], c0);
                    atomicAdd(&degb[n0 + wn * 32 + j * 8 + t * 2 + 1], c1);
                }
            }
            __syncthreads();
            float* stage = (float*)sm;                 // 128 x 129 floats
#pragma unroll
            for (int i = 0; i < 4; i++) {
                int rr = wm * 64 + i * 16 + g;
#pragma unroll
                for (int j = 0; j < 4; j++) {
                    int cc = wn * 32 + j * 8 + t * 2;
                    stage[rr * 129 + cc]           = v[i][j][0];
                    stage[rr * 129 + cc + 1]       = v[i][j][1];
                    stage[(rr + 8) * 129 + cc]     = v[i][j][2];
                    stage[(rr + 8) * 129 + cc + 1] = v[i][j][3];
                }
            }
            __syncthreads();
#pragma unroll
            for (int q = 0; q < 16; q++) {
                int idx = tid + q * 256;
                int r = idx >> 5;
                int c4 = (idx & 31) * 4;
                float f0 = stage[(c4 + 0) * 129 + r];
                float f1 = stage[(c4 + 1) * 129 + r];
                float f2 = stage[(c4 + 2) * 129 + r];
                float f3 = stage[(c4 + 3) * 129 + r];
                __half* dst = Ab + (size_t)(n0 + r) * ldo + m0 + c4;
                ((__half2*)dst)[0] = __floats2half2_rn(f0, f1);
                ((__half2*)dst)[1] = __floats2half2_rn(f2, f3);
            }
        }
    } else if (MODE == 2) {
        // g = h@WT row-scale by dinv[global row], transpose -> gT fp16 [b][f][c]
        const float* db = aux;                       // flattened dinv, index m0+row
        __syncthreads();
        float* stage = (float*)sm;                   // 128 x 129 floats
#pragma unroll
        for (int i = 0; i < 4; i++) {
            int rr = wm * 64 + i * 16 + g;
            float d0 = db[m0 + rr], d1 = db[m0 + rr + 8];
#pragma unroll
            for (int j = 0; j < 4; j++) {
                int cc = wn * 32 + j * 8 + t * 2;
                stage[rr * 129 + cc]           = acc[i][j][0] * d0;
                stage[rr * 129 + cc + 1]       = acc[i][j][1] * d0;
                stage[(rr + 8) * 129 + cc]     = acc[i][j][2] * d1;
                stage[(rr + 8) * 129 + cc + 1] = acc[i][j][3] * d1;
            }
        }
        __syncthreads();
        int bb = m0 / C_;
        int cb = m0 % C_;
        __half* ghi = (__half*)out0;
#pragma unroll
        for (int q = 0; q < 16; q++) {
            int idx = tid + q * 256;
            int r = idx >> 5;                         // local f
            int c4 = (idx & 31) * 4;                  // local c, 4-aligned
            float f0 = stage[(c4 + 0) * 129 + r];
            float f1 = stage[(c4 + 1) * 129 + r];
            float f2 = stage[(c4 + 2) * 129 + r];
            float f3 = stage[(c4 + 3) * 129 + r];
            size_t o = ((size_t)bb * F_ + n0 + r) * C_ + cb + c4;
            ((__half2*)(ghi + o))[0] = __floats2half2_rn(f0, f1);
            ((__half2*)(ghi + o))[1] = __floats2half2_rn(f2, f3);
        }
    } else {
        // AH: v = relu(acc * dinv[m] + bias)
        const float* db = aux + (size_t)b * auxBatch;
        float bs = bias[0];
#pragma unroll
        for (int i = 0; i < 4; i++) {
            int r0 = m0 + wm * 64 + i * 16 + g;
            float rs0 = db[r0], rs1 = db[r0 + 8];
#pragma unroll
            for (int j = 0; j < 4; j++) {
                int cl = n0 + wn * 32 + j * 8 + t * 2;
                float v00 = fmaxf(acc[i][j][0] * rs0 + bs, 0.f);
                float v01 = fmaxf(acc[i][j][1] * rs0 + bs, 0.f);
                float v10 = fmaxf(acc[i][j][2] * rs1 + bs, 0.f);
                float v11 = fmaxf(acc[i][j][3] * rs1 + bs, 0.f);
                if (MODE == 1) {
                    __half* o0 = (__half*)out0 + (size_t)b * oBatch;
                    __half* o1 = (__half*)out1 + (size_t)b * oBatch;
                    __half h00 = __float2half_rn(v00), h01 = __float2half_rn(v01);
                    __half h10 = __float2half_rn(v10), h11 = __float2half_rn(v11);
                    *(__half2*)(o0 + (size_t)r0 * ldo + cl)       = __halves2half2(h00, h01);
                    *(__half2*)(o0 + (size_t)(r0 + 8) * ldo + cl) = __halves2half2(h10, h11);
                    *(__half2*)(o1 + (size_t)r0 * ldo + cl) =
                        __floats2half2_rn(v00 - __half2float(h00), v01 - __half2float(h01));
                    *(__half2*)(o1 + (size_t)(r0 + 8) * ldo + cl) =
                        __floats2half2_rn(v10 - __half2float(h10), v11 - __half2float(h11));
                } else {
                    float* o = (float*)out0 + (size_t)b * oBatch;
                    *(float2*)(o + (size_t)r0 * ldo + cl)       = make_float2(v00, v01);
                    *(float2*)(o + (size_t)(r0 + 8) * ldo + cl) = make_float2(v10, v11);
                }
            }
        }
    }
}

// =============================== small kernels ==============================
__global__ void zero_kernel(float* __restrict__ p) {
    p[blockIdx.x * 256 + threadIdx.x] = 0.f;
}

// fused: row inv-norms + fp16 hi/lo split of x
__global__ void norm_split(const float* __restrict__ x, float* __restrict__ invn,
                           __half* __restrict__ hi, __half* __restrict__ lo) {
    int row = blockIdx.x;
    const float* xr = x + (size_t)row * F_;
    float4 v = ((const float4*)xr)[threadIdx.x];
    float s = v.x * v.x + v.y * v.y + v.z * v.z + v.w * v.w;
#pragma unroll
    for (int o = 16; o > 0; o >>= 1) s += __shfl_xor_sync(0xFFFFFFFFu, s, o);
    __shared__ float red[4];
    if ((threadIdx.x & 31) == 0) red[threadIdx.x >> 5] = s;
    __syncthreads();
    if (threadIdx.x == 0)
        invn[row] = 1.0f / sqrtf(red[0] + red[1] + red[2] + red[3]);

    __half h0 = __float2half_rn(v.x), h1 = __float2half_rn(v.y);
    __half h2 = __float2half_rn(v.z), h3 = __float2half_rn(v.w);
    size_t o = (size_t)row * F_ + threadIdx.x * 4;
    *(__half2*)(hi + o)     = __halves2half2(h0, h1);
    *(__half2*)(hi + o + 2) = __halves2half2(h2, h3);
    *(__half2*)(lo + o)     = __floats2half2_rn(v.x - __half2float(h0), v.y - __half2float(h1));
    *(__half2*)(lo + o + 2) = __floats2half2_rn(v.z - __half2float(h2), v.w - __half2float(h3));
}

__global__ void dinv_kernel(const float* __restrict__ deg, float* __restrict__ dinv) {
    int i = blockIdx.x * 256 + threadIdx.x;
    dinv[i] = 1.0f / sqrtf(deg[i]);
}

// W[f,g] -> WT[g,f] single fp16
__global__ void wtrans_kernel(const float* __restrict__ W, __half* __restrict__ hi) {
    __shared__ float tsm[32][33];
    int g0 = blockIdx.x * 32, f0 = blockIdx.y * 32;
#pragma unroll
    for (int k = 0; k < 4; k++) {
        int f = f0 + threadIdx.y + k * 8;
        tsm[threadIdx.x][threadIdx.y + k * 8] = W[(size_t)f * F_ + g0 + threadIdx.x];
    }
    __syncthreads();
#pragma unroll
    for (int k = 0; k < 4; k++) {
        int gg = g0 + threadIdx.y + k * 8;
        hi[(size_t)gg * F_ + f0 + threadIdx.x] = __float2half_rn(tsm[threadIdx.y + k * 8][threadIdx.x]);
    }
}

// ============================================================================
extern "C" void kernel_launch(void* const* d_in, const int* in_sizes, int n_in,
                              void* d_out, int out_size) {
    const float* x  = (const float*)d_in[0];
    const float* W1 = (const float*)d_in[1];
    const float* b1 = (const float*)d_in[2];
    const float* W2 = (const float*)d_in[3];
    const float* b2 = (const float*)d_in[4];
    float* out = (float*)d_out;

    __half *pA, *pxhi, *pxlo, *pgT, *ph2hi, *ph2lo, *pWT;
    float *pinvn, *pdeg, *pdinv;
    cudaGetSymbolAddress((void**)&pA,    g_A);
    cudaGetSymbolAddress((void**)&pinvn, g_invn);
    cudaGetSymbolAddress((void**)&pdeg,  g_deg);
    cudaGetSymbolAddress((void**)&pdinv, g_dinv);
    cudaGetSymbolAddress((void**)&pxhi,  g_xhi);
    cudaGetSymbolAddress((void**)&pxlo,  g_xlo);
    cudaGetSymbolAddress((void**)&pgT,   g_gT);
    cudaGetSymbolAddress((void**)&ph2hi, g_h2_hi);
    cudaGetSymbolAddress((void**)&ph2lo, g_h2_lo);
    cudaGetSymbolAddress((void**)&pWT,   g_WT);

    const int smem0 = 4 * 3 * (128 * 32 * 2);   // 98304 B (GRAM: 4 ops)
    const int smem2 = 3 * 3 * (128 * 32 * 2);   // 73728 B (HWT: 3 ops)
    const int smem1 = 2 * 3 * (128 * 64 * 2);   // 98304 B (AH: 2 ops, KC=64)
    cudaFuncSetAttribute(mma_gemm<0>, cudaFuncAttributeMaxDynamicSharedMemorySize, smem0);
    cudaFuncSetAttribute(mma_gemm<1>, cudaFuncAttributeMaxDynamicSharedMemorySize, smem1);
    cudaFuncSetAttribute(mma_gemm<2>, cudaFuncAttributeMaxDynamicSharedMemorySize, smem2);
    cudaFuncSetAttribute(mma_gemm<3>, cudaFuncAttributeMaxDynamicSharedMemorySize, smem1);

    const int NBLK = C_ / 128;                       // 16
    const int NTRI = NBLK * (NBLK + 1) / 2;          // 136

    // ---- Laplacian ----
    zero_kernel<<<(B_ * C_) / 256, 256>>>(pdeg);
    norm_split<<<B_ * C_, 128>>>(x, pinvn, pxhi, pxlo);
    mma_gemm<0><<<dim3(NTRI, 1, B_), 256, smem0>>>(
        pxhi, pxlo, pxhi, pxlo, F_, F_, F_,
        (size_t)C_ * F_, (size_t)C_ * F_, pinvn, C_, nullptr,
        pA, nullptr, C_, (size_t)C_ * C_, pdeg);
    dinv_kernel<<<(B_ * C_) / 256, 256>>>(pdeg, pdinv);

    // ---- layer 1: relu(L @ (x @ W1) + b1) ----
    wtrans_kernel<<<dim3(F_ / 32, F_ / 32), dim3(32, 8)>>>(W1, pWT);
    mma_gemm<2><<<dim3(F_ / 128, (B_ * C_) / 128, 1), 256, smem2>>>(
        pxhi, pxlo, pWT, nullptr, F_, F_, F_,
        0, 0, pdinv, 0, nullptr,
        pgT, nullptr, C_, 0, nullptr);
    mma_gemm<1><<<dim3(F_ / 128, C_ / 128, B_), 256, smem1>>>(
        pA, nullptr, pgT, nullptr, C_, C_, C_,
        (size_t)C_ * C_, (size_t)F_ * C_, pdinv, C_, b1,
        ph2hi, ph2lo, F_, (size_t)C_ * F_, nullptr);

    // ---- layer 2: relu(L @ (h2 @ W2) + b2) ----
    wtrans_kernel<<<dim3(F_ / 32, F_ / 32), dim3(32, 8)>>>(W2, pWT);
    mma_gemm<2><<<dim3(F_ / 128, (B_ * C_) / 128, 1), 256, smem2>>>(
        ph2hi, ph2lo, pWT, nullptr, F_, F_, F_,
        0, 0, pdinv, 0, nullptr,
        pgT, nullptr, C_, 0, nullptr);
    mma_gemm<3><<<dim3(F_ / 128, C_ / 128, B_), 256, smem1>>>(
        pA, nullptr, pgT, nullptr, C_, C_, C_,
        (size_t)C_ * C_, (size_t)F_ * C_, pdinv, C_, b2,
        out, nullptr, F_, (size_t)C_ * F_, nullptr);
}

// round 12
// speedup vs baseline: 5.2490x; 1.1094x over previous
#include <cuda_runtime.h>
#include <cuda_fp16.h>
#include <cstdint>
#include <math.h>

#define B_ 8
#define C_ 2048
#define F_ 512
#define THRESH 0.005f

// ---- scratch (device globals: no allocation allowed) ----
__device__ __half g_A[(size_t)B_ * C_ * C_];       // binary adjacency (fp16 0/1)
__device__ float  g_invn[B_ * C_];
__device__ float  g_deg[B_ * C_];
__device__ float  g_dinv[B_ * C_];
__device__ __half g_xhi[(size_t)B_ * C_ * F_];
__device__ __half g_xlo[(size_t)B_ * C_ * F_];
__device__ __half g_gT[(size_t)B_ * F_ * C_];      // (dinv*(h@W))^T  fp16
__device__ __half g_h2[(size_t)B_ * C_ * F_];      // hidden activations fp16
__device__ __half g_WT[F_ * F_];                   // W^T single fp16

// =============================== helpers ===============================
__device__ __forceinline__ uint32_t smem_u32(const void* p) {
    uint32_t a;
    asm("{ .reg .u64 t; cvta.to.shared.u64 t, %1; cvt.u32.u64 %0, t; }" : "=r"(a) : "l"(p));
    return a;
}
#define CP_COMMIT() asm volatile("cp.async.commit_group;" ::: "memory")
#define CP_WAIT1()  asm volatile("cp.async.wait_group 1;" ::: "memory")
#define CP_WAIT0()  asm volatile("cp.async.wait_group 0;" ::: "memory")

__device__ __forceinline__ void mma_f16(float c[4], const uint32_t a[4], const uint32_t b[2]) {
    asm volatile(
        "mma.sync.aligned.m16n8k16.row.col.f32.f16.f16.f32 "
        "{%0,%1,%2,%3}, {%4,%5,%6,%7}, {%8,%9}, {%0,%1,%2,%3};"
        : "+f"(c[0]), "+f"(c[1]), "+f"(c[2]), "+f"(c[3])
        : "r"(a[0]), "r"(a[1]), "r"(a[2]), "r"(a[3]), "r"(b[0]), "r"(b[1]));
}
__device__ __forceinline__ void ldsm4(uint32_t r[4], uint32_t addr) {
    asm volatile("ldmatrix.sync.aligned.m8n8.x4.shared.b16 {%0,%1,%2,%3}, [%4];"
        : "=r"(r[0]), "=r"(r[1]), "=r"(r[2]), "=r"(r[3]) : "r"(addr));
}
// swizzled byte offset inside one 128-row tile; KCC = K-chunk width (32 or 64 halves)
template <int KCC>
__device__ __forceinline__ uint32_t swz(int row, int seg) {
    if (KCC == 64) return (uint32_t)(row * 128 + ((seg ^ (row & 7)) << 4));
    return (uint32_t)(row * 64 + ((seg ^ ((row >> 1) & 3)) << 4));
}

// ====================== fp16 mma GEMM (128x128 tile) ======================
// All operands row-major with K contiguous: Aop[m][k] (lda), Bop[n][k] (ldb).
// MODE 0: GRAM (symmetric blocks, KC32): NA=2,NB=2, 3 passes; binarize; mirror; deg
// MODE 2: HWT  (KC64) NA=1,NB=1: g = h@WT ; epi: *dinv[row], transpose -> gT fp16
// MODE 1: AH   (KC64) NA=1,NB=1: A@gT     ; epi: relu(*dinv[m]+bias) -> fp16
// MODE 3: AH   (KC64) same, epi -> fp32

template <int MODE>
__global__ __launch_bounds__(256, 2) void mma_gemm(
    const __half* __restrict__ a0, const __half* __restrict__ a1,
    const __half* __restrict__ b0, const __half* __restrict__ b1,
    int lda, int ldb, int K,
    size_t aBatch, size_t bBatch,
    const float* __restrict__ aux, int auxBatch,
    const float* __restrict__ bias,
    void* __restrict__ out0,
    int ldo, size_t oBatch,
    float* __restrict__ deg)
{
    constexpr int NA   = (MODE == 0) ? 2 : 1;
    constexpr int NB   = (MODE == 0) ? 2 : 1;
    constexpr int NOPS = NA + NB;
    constexpr int KCC  = (MODE == 0) ? 32 : 64;
    constexpr int TB   = 128 * KCC * 2;          // tile bytes
    constexpr int NKS  = KCC / 16;

    int m0, n0, b = blockIdx.z;
    if (MODE == 0) {
        int idx = blockIdx.x, bi = 0;
        while (idx >= (C_ / 128 - bi)) { idx -= (C_ / 128 - bi); bi++; }
        m0 = bi * 128; n0 = (bi + idx) * 128;
    } else {
        m0 = blockIdx.y * 128; n0 = blockIdx.x * 128;
    }

    int tid = threadIdx.x, wid = tid >> 5, lane = tid & 31;
    int wm = wid & 1, wn = wid >> 1;          // warp tile 64x32
    int g = lane >> 2, t = lane & 3;

    const __half* ops[NOPS];
    int ldv[NOPS];
    ops[0] = a0 + (size_t)b * aBatch + (size_t)m0 * lda; ldv[0] = lda;
    if (NA == 2) { ops[1] = a1 + (size_t)b * aBatch + (size_t)m0 * lda; ldv[1] = lda; }
    ops[NA] = b0 + (size_t)b * bBatch + (size_t)n0 * ldb; ldv[NA] = ldb;
    if (NB == 2) { ops[NA + 1] = b1 + (size_t)b * bBatch + (size_t)n0 * ldb; ldv[NA + 1] = ldb; }

    extern __shared__ __half sm[];
    uint32_t smb = smem_u32(sm);

    auto load_tile = [&](int op, int buf, int k0) {
        uint32_t st = smb + (uint32_t)(buf * NOPS + op) * TB;
        const __half* src = ops[op] + k0;
        int ld = ldv[op];
        constexpr int ITER = (128 * KCC / 8) / 256;
#pragma unroll
        for (int i2 = 0; i2 < ITER; i2++) {
            int idx = tid + i2 * 256;
            int row, seg;
            if (KCC == 64) { row = idx >> 3; seg = idx & 7; }
            else           { row = idx >> 2; seg = idx & 3; }
            const __half* gp = src + (size_t)row * ld + seg * 8;
            uint32_t sa = st + swz<KCC>(row, seg);
            asm volatile("cp.async.cg.shared.global [%0], [%1], 16;" :: "r"(sa), "l"(gp) : "memory");
        }
    };

    float acc[4][4][4];
#pragma unroll
    for (int i = 0; i < 4; i++)
#pragma unroll
        for (int j = 0; j < 4; j++)
#pragma unroll
            for (int r = 0; r < 4; r++) acc[i][j][r] = 0.f;

    int a_row = ((lane >> 3) & 1) * 8 + (lane & 7);
    int a_sg  = lane >> 4;
    int b_row = ((lane >> 4) & 1) * 8 + (lane & 7);
    int b_sg  = (lane >> 3) & 1;

    uint32_t afr[NA][4][4];
    uint32_t bfr0[4][2], bfr1[4][2];

    auto compute = [&](int buf) {
        uint32_t tb = smb + (uint32_t)(buf * NOPS) * TB;
#pragma unroll
        for (int ks = 0; ks < NKS; ks++) {
            int segA = 2 * ks + a_sg;
            int segB = 2 * ks + b_sg;
#pragma unroll
            for (int i = 0; i < 4; i++)
                ldsm4(afr[0][i], tb + swz<KCC>(wm * 64 + i * 16 + a_row, segA));
            if (NA == 2) {
#pragma unroll
                for (int i = 0; i < 4; i++)
                    ldsm4(afr[NA - 1][i], tb + TB + swz<KCC>(wm * 64 + i * 16 + a_row, segA));
            }
            uint32_t tB0 = tb + (uint32_t)NA * TB;
            ldsm4(&bfr0[0][0], tB0 + swz<KCC>(wn * 32 + b_row, segB));
            ldsm4(&bfr0[2][0], tB0 + swz<KCC>(wn * 32 + 16 + b_row, segB));
            if (NB == 2) {
                uint32_t tB1 = tB0 + TB;
                ldsm4(&bfr1[0][0], tB1 + swz<KCC>(wn * 32 + b_row, segB));
                ldsm4(&bfr1[2][0], tB1 + swz<KCC>(wn * 32 + 16 + b_row, segB));
            }
#pragma unroll
            for (int i = 0; i < 4; i++)
#pragma unroll
                for (int j = 0; j < 4; j++) mma_f16(acc[i][j], afr[0][i], bfr0[j]);
            if (NA == 2) {
#pragma unroll
                for (int i = 0; i < 4; i++)
#pragma unroll
                    for (int j = 0; j < 4; j++) mma_f16(acc[i][j], afr[NA - 1][i], bfr0[j]);
            }
            if (NB == 2) {
#pragma unroll
                for (int i = 0; i < 4; i++)
#pragma unroll
                    for (int j = 0; j < 4; j++) mma_f16(acc[i][j], afr[0][i], bfr1[j]);
            }
        }
    };

    const int NC = K / KCC;
    for (int op = 0; op < NOPS; op++) load_tile(op, 0, 0);
    CP_COMMIT();
    if (NC > 1) {
        for (int op = 0; op < NOPS; op++) load_tile(op, 1, KCC);
        CP_COMMIT();
    }
    for (int c = 0; c < NC; c++) {
        if (c + 1 < NC) { CP_WAIT1(); } else { CP_WAIT0(); }
        __syncthreads();
        if (c + 2 < NC) {
            for (int op = 0; op < NOPS; op++) load_tile(op, (c + 2) % 3, (c + 2) * KCC);
            CP_COMMIT();
        }
        compute(c % 3);
    }

    // ------------------------------- epilogues -------------------------------
    if (MODE == 0) {
        const float* inb = aux + (size_t)b * auxBatch;
        __half* Ab = (__half*)out0 + (size_t)b * oBatch;
        float* degb = deg + (size_t)b * C_;
        float v[4][4][4];
#pragma unroll
        for (int i = 0; i < 4; i++) {
            int r0 = m0 + wm * 64 + i * 16 + g;
            float rs0 = inb[r0], rs1 = inb[r0 + 8];
#pragma unroll
            for (int j = 0; j < 4; j++) {
                int cl = n0 + wn * 32 + j * 8 + t * 2;
                float j0 = inb[cl], j1 = inb[cl + 1];
                v[i][j][0] = (acc[i][j][0] * rs0 * j0 > THRESH) ? 1.f : 0.f;
                v[i][j][1] = (acc[i][j][1] * rs0 * j1 > THRESH) ? 1.f : 0.f;
                v[i][j][2] = (acc[i][j][2] * rs1 * j0 > THRESH) ? 1.f : 0.f;
                v[i][j][3] = (acc[i][j][3] * rs1 * j1 > THRESH) ? 1.f : 0.f;
                *(__half2*)(Ab + (size_t)r0 * ldo + cl)       = __floats2half2_rn(v[i][j][0], v[i][j][1]);
                *(__half2*)(Ab + (size_t)(r0 + 8) * ldo + cl) = __floats2half2_rn(v[i][j][2], v[i][j][3]);
            }
        }
#pragma unroll
        for (int i = 0; i < 4; i++) {
            float s0 = 0.f, s1 = 0.f;
#pragma unroll
            for (int j = 0; j < 4; j++) {
                s0 += v[i][j][0] + v[i][j][1];
                s1 += v[i][j][2] + v[i][j][3];
            }
            s0 += __shfl_xor_sync(0xFFFFFFFFu, s0, 1); s0 += __shfl_xor_sync(0xFFFFFFFFu, s0, 2);
            s1 += __shfl_xor_sync(0xFFFFFFFFu, s1, 1); s1 += __shfl_xor_sync(0xFFFFFFFFu, s1, 2);
            if (t == 0) {
                atomicAdd(&degb[m0 + wm * 64 + i * 16 + g], s0);
                atomicAdd(&degb[m0 + wm * 64 + i * 16 + g + 8], s1);
            }
        }
        if (m0 != n0) {
#pragma unroll
            for (int j = 0; j < 4; j++) {
                float c0 = 0.f, c1 = 0.f;
#pragma unroll
                for (int i = 0; i < 4; i++) {
                    c0 += v[i][j][0] + v[i][j][2];
                    c1 += v[i][j][1] + v[i][j][3];
                }
                c0 += __shfl_xor_sync(0xFFFFFFFFu, c0, 4); c0 += __shfl_xor_sync(0xFFFFFFFFu, c0, 8); c0 += __shfl_xor_sync(0xFFFFFFFFu, c0, 16);
                c1 += __shfl_xor_sync(0xFFFFFFFFu, c1, 4); c1 += __shfl_xor_sync(0xFFFFFFFFu, c1, 8); c1 += __shfl_xor_sync(0xFFFFFFFFu, c1, 16);
                if (lane < 4) {
                    atomicAdd(&degb[n0 + wn * 32 + j * 8 + t * 2], c0);
                    atomicAdd(&degb[n0 + wn * 32 + j * 8 + t * 2 + 1], c1);
                }
            }
            __syncthreads();
            float* stage = (float*)sm;                 // 128 x 129 floats
#pragma unroll
            for (int i = 0; i < 4; i++) {
                int rr = wm * 64 + i * 16 + g;
#pragma unroll
                for (int j = 0; j < 4; j++) {
                    int cc = wn * 32 + j * 8 + t * 2;
                    stage[rr * 129 + cc]           = v[i][j][0];
                    stage[rr * 129 + cc + 1]       = v[i][j][1];
                    stage[(rr + 8) * 129 + cc]     = v[i][j][2];
                    stage[(rr + 8) * 129 + cc + 1] = v[i][j][3];
                }
            }
            __syncthreads();
#pragma unroll
            for (int q = 0; q < 16; q++) {
                int idx = tid + q * 256;
                int r = idx >> 5;
                int c4 = (idx & 31) * 4;
                float f0 = stage[(c4 + 0) * 129 + r];
                float f1 = stage[(c4 + 1) * 129 + r];
                float f2 = stage[(c4 + 2) * 129 + r];
                float f3 = stage[(c4 + 3) * 129 + r];
                __half* dst = Ab + (size_t)(n0 + r) * ldo + m0 + c4;
                ((__half2*)dst)[0] = __floats2half2_rn(f0, f1);
                ((__half2*)dst)[1] = __floats2half2_rn(f2, f3);
            }
        }
    } else if (MODE == 2) {
        // g = h@WT row-scale by dinv[global row], transpose -> gT fp16 [b][f][c]
        const float* db = aux;                       // flattened dinv, index m0+row
        __syncthreads();
        float* stage = (float*)sm;                   // 128 x 129 floats
#pragma unroll
        for (int i = 0; i < 4; i++) {
            int rr = wm * 64 + i * 16 + g;
            float d0 = db[m0 + rr], d1 = db[m0 + rr + 8];
#pragma unroll
            for (int j = 0; j < 4; j++) {
                int cc = wn * 32 + j * 8 + t * 2;
                stage[rr * 129 + cc]           = acc[i][j][0] * d0;
                stage[rr * 129 + cc + 1]       = acc[i][j][1] * d0;
                stage[(rr + 8) * 129 + cc]     = acc[i][j][2] * d1;
                stage[(rr + 8) * 129 + cc + 1] = acc[i][j][3] * d1;
            }
        }
        __syncthreads();
        int bb = m0 / C_;
        int cb = m0 % C_;
        __half* ghi = (__half*)out0;
#pragma unroll
        for (int q = 0; q < 16; q++) {
            int idx = tid + q * 256;
            int r = idx >> 5;                         // local f
            int c4 = (idx & 31) * 4;                  // local c, 4-aligned
            float f0 = stage[(c4 + 0) * 129 + r];
            float f1 = stage[(c4 + 1) * 129 + r];
            float f2 = stage[(c4 + 2) * 129 + r];
            float f3 = stage[(c4 + 3) * 129 + r];
            size_t o = ((size_t)bb * F_ + n0 + r) * C_ + cb + c4;
            ((__half2*)(ghi + o))[0] = __floats2half2_rn(f0, f1);
            ((__half2*)(ghi + o))[1] = __floats2half2_rn(f2, f3);
        }
    } else {
        // AH: v = relu(acc * dinv[m] + bias)
        const float* db = aux + (size_t)b * auxBatch;
        float bs = bias[0];
#pragma unroll
        for (int i = 0; i < 4; i++) {
            int r0 = m0 + wm * 64 + i * 16 + g;
            float rs0 = db[r0], rs1 = db[r0 + 8];
#pragma unroll
            for (int j = 0; j < 4; j++) {
                int cl = n0 + wn * 32 + j * 8 + t * 2;
                float v00 = fmaxf(acc[i][j][0] * rs0 + bs, 0.f);
                float v01 = fmaxf(acc[i][j][1] * rs0 + bs, 0.f);
                float v10 = fmaxf(acc[i][j][2] * rs1 + bs, 0.f);
                float v11 = fmaxf(acc[i][j][3] * rs1 + bs, 0.f);
                if (MODE == 1) {
                    __half* o0 = (__half*)out0 + (size_t)b * oBatch;
                    *(__half2*)(o0 + (size_t)r0 * ldo + cl)       = __floats2half2_rn(v00, v01);
                    *(__half2*)(o0 + (size_t)(r0 + 8) * ldo + cl) = __floats2half2_rn(v10, v11);
                } else {
                    float* o = (float*)out0 + (size_t)b * oBatch;
                    *(float2*)(o + (size_t)r0 * ldo + cl)       = make_float2(v00, v01);
                    *(float2*)(o + (size_t)(r0 + 8) * ldo + cl) = make_float2(v10, v11);
                }
            }
        }
    }
}

// =============================== small kernels ==============================
__global__ void zero_kernel(float* __restrict__ p) {
    p[blockIdx.x * 256 + threadIdx.x] = 0.f;
}

// fused: row inv-norms + fp16 hi/lo split of x
__global__ void norm_split(const float* __restrict__ x, float* __restrict__ invn,
                           __half* __restrict__ hi, __half* __restrict__ lo) {
    int row = blockIdx.x;
    const float* xr = x + (size_t)row * F_;
    float4 v = ((const float4*)xr)[threadIdx.x];
    float s = v.x * v.x + v.y * v.y + v.z * v.z + v.w * v.w;
#pragma unroll
    for (int o = 16; o > 0; o >>= 1) s += __shfl_xor_sync(0xFFFFFFFFu, s, o);
    __shared__ float red[4];
    if ((threadIdx.x & 31) == 0) red[threadIdx.x >> 5] = s;
    __syncthreads();
    if (threadIdx.x == 0)
        invn[row] = 1.0f / sqrtf(red[0] + red[1] + red[2] + red[3]);

    __half h0 = __float2half_rn(v.x), h1 = __float2half_rn(v.y);
    __half h2 = __float2half_rn(v.z), h3 = __float2half_rn(v.w);
    size_t o = (size_t)row * F_ + threadIdx.x * 4;
    *(__half2*)(hi + o)     = __halves2half2(h0, h1);
    *(__half2*)(hi + o + 2) = __halves2half2(h2, h3);
    *(__half2*)(lo + o)     = __floats2half2_rn(v.x - __half2float(h0), v.y - __half2float(h1));
    *(__half2*)(lo + o + 2) = __floats2half2_rn(v.z - __half2float(h2), v.w - __half2float(h3));
}

__global__ void dinv_kernel(const float* __restrict__ deg, float* __restrict__ dinv) {
    int i = blockIdx.x * 256 + threadIdx.x;
    dinv[i] = 1.0f / sqrtf(deg[i]);
}

// W[f,g] -> WT[g,f] single fp16
__global__ void wtrans_kernel(const float* __restrict__ W, __half* __restrict__ hi) {
    __shared__ float tsm[32][33];
    int g0 = blockIdx.x * 32, f0 = blockIdx.y * 32;
#pragma unroll
    for (int k = 0; k < 4; k++) {
        int f = f0 + threadIdx.y + k * 8;
        tsm[threadIdx.x][threadIdx.y + k * 8] = W[(size_t)f * F_ + g0 + threadIdx.x];
    }
    __syncthreads();
#pragma unroll
    for (int k = 0; k < 4; k++) {
        int gg = g0 + threadIdx.y + k * 8;
        hi[(size_t)gg * F_ + f0 + threadIdx.x] = __float2half_rn(tsm[threadIdx.y + k * 8][threadIdx.x]);
    }
}

// ============================================================================
extern "C" void kernel_launch(void* const* d_in, const int* in_sizes, int n_in,
                              void* d_out, int out_size) {
    const float* x  = (const float*)d_in[0];
    const float* W1 = (const float*)d_in[1];
    const float* b1 = (const float*)d_in[2];
    const float* W2 = (const float*)d_in[3];
    const float* b2 = (const float*)d_in[4];
    float* out = (float*)d_out;

    __half *pA, *pxhi, *pxlo, *pgT, *ph2, *pWT;
    float *pinvn, *pdeg, *pdinv;
    cudaGetSymbolAddress((void**)&pA,    g_A);
    cudaGetSymbolAddress((void**)&pinvn, g_invn);
    cudaGetSymbolAddress((void**)&pdeg,  g_deg);
    cudaGetSymbolAddress((void**)&pdinv, g_dinv);
    cudaGetSymbolAddress((void**)&pxhi,  g_xhi);
    cudaGetSymbolAddress((void**)&pxlo,  g_xlo);
    cudaGetSymbolAddress((void**)&pgT,   g_gT);
    cudaGetSymbolAddress((void**)&ph2,   g_h2);
    cudaGetSymbolAddress((void**)&pWT,   g_WT);

    const int smem0 = 4 * 3 * (128 * 32 * 2);   // 98304 B (GRAM: 4 ops, KC32)
    const int smem1 = 2 * 3 * (128 * 64 * 2);   // 98304 B (HWT/AH: 2 ops, KC64)
    cudaFuncSetAttribute(mma_gemm<0>, cudaFuncAttributeMaxDynamicSharedMemorySize, smem0);
    cudaFuncSetAttribute(mma_gemm<1>, cudaFuncAttributeMaxDynamicSharedMemorySize, smem1);
    cudaFuncSetAttribute(mma_gemm<2>, cudaFuncAttributeMaxDynamicSharedMemorySize, smem1);
    cudaFuncSetAttribute(mma_gemm<3>, cudaFuncAttributeMaxDynamicSharedMemorySize, smem1);

    const int NBLK = C_ / 128;                       // 16
    const int NTRI = NBLK * (NBLK + 1) / 2;          // 136

    // ---- Laplacian ----
    zero_kernel<<<(B_ * C_) / 256, 256>>>(pdeg);
    norm_split<<<B_ * C_, 128>>>(x, pinvn, pxhi, pxlo);
    mma_gemm<0><<<dim3(NTRI, 1, B_), 256, smem0>>>(
        pxhi, pxlo, pxhi, pxlo, F_, F_, F_,
        (size_t)C_ * F_, (size_t)C_ * F_, pinvn, C_, nullptr,
        pA, C_, (size_t)C_ * C_, pdeg);
    dinv_kernel<<<(B_ * C_) / 256, 256>>>(pdeg, pdinv);

    // ---- layer 1: relu(L @ (x @ W1) + b1) ----
    wtrans_kernel<<<dim3(F_ / 32, F_ / 32), dim3(32, 8)>>>(W1, pWT);
    mma_gemm<2><<<dim3(F_ / 128, (B_ * C_) / 128, 1), 256, smem1>>>(
        pxhi, nullptr, pWT, nullptr, F_, F_, F_,
        0, 0, pdinv, 0, nullptr,
        pgT, C_, 0, nullptr);
    mma_gemm<1><<<dim3(F_ / 128, C_ / 128, B_), 256, smem1>>>(
        pA, nullptr, pgT, nullptr, C_, C_, C_,
        (size_t)C_ * C_, (size_t)F_ * C_, pdinv, C_, b1,
        ph2, F_, (size_t)C_ * F_, nullptr);

    // ---- layer 2: relu(L @ (h2 @ W2) + b2) ----
    wtrans_kernel<<<dim3(F_ / 32, F_ / 32), dim3(32, 8)>>>(W2, pWT);
    mma_gemm<2><<<dim3(F_ / 128, (B_ * C_) / 128, 1), 256, smem1>>>(
        ph2, nullptr, pWT, nullptr, F_, F_, F_,
        0, 0, pdinv, 0, nullptr,
        pgT, C_, 0, nullptr);
    mma_gemm<3><<<dim3(F_ / 128, C_ / 128, B_), 256, smem1>>>(
        pA, nullptr, pgT, nullptr, C_, C_, C_,
        (size_t)C_ * C_, (size_t)F_ * C_, pdinv, C_, b2,
        out, F_, (size_t)C_ * F_, nullptr);
}

// round 13
// speedup vs baseline: 5.2937x; 1.0085x over previous
#include <cuda_runtime.h>
#include <cuda_fp16.h>
#include <cstdint>
#include <math.h>

#define B_ 8
#define C_ 2048
#define F_ 512
#define THRESH 0.005f

// ---- scratch (device globals: no allocation allowed) ----
__device__ __half g_A[(size_t)B_ * C_ * C_];       // binary adjacency (fp16 0/1)
__device__ float  g_invn[B_ * C_];
__device__ float  g_deg[B_ * C_];
__device__ float  g_dinv[B_ * C_];
__device__ __half g_xhi[(size_t)B_ * C_ * F_];
__device__ __half g_xlo[(size_t)B_ * C_ * F_];
__device__ __half g_gT[(size_t)B_ * F_ * C_];      // (dinv*(h@W))^T  fp16
__device__ __half g_h2[(size_t)B_ * C_ * F_];      // hidden activations fp16
__device__ __half g_WT[F_ * F_];                   // W^T single fp16

// =============================== helpers ===============================
__device__ __forceinline__ uint32_t smem_u32(const void* p) {
    uint32_t a;
    asm("{ .reg .u64 t; cvta.to.shared.u64 t, %1; cvt.u32.u64 %0, t; }" : "=r"(a) : "l"(p));
    return a;
}
#define CP_COMMIT() asm volatile("cp.async.commit_group;" ::: "memory")
#define CP_WAIT1()  asm volatile("cp.async.wait_group 1;" ::: "memory")
#define CP_WAIT0()  asm volatile("cp.async.wait_group 0;" ::: "memory")

__device__ __forceinline__ void mma_f16(float c[4], const uint32_t a[4], const uint32_t b[2]) {
    asm volatile(
        "mma.sync.aligned.m16n8k16.row.col.f32.f16.f16.f32 "
        "{%0,%1,%2,%3}, {%4,%5,%6,%7}, {%8,%9}, {%0,%1,%2,%3};"
        : "+f"(c[0]), "+f"(c[1]), "+f"(c[2]), "+f"(c[3])
        : "r"(a[0]), "r"(a[1]), "r"(a[2]), "r"(a[3]), "r"(b[0]), "r"(b[1]));
}
__device__ __forceinline__ void ldsm4(uint32_t r[4], uint32_t addr) {
    asm volatile("ldmatrix.sync.aligned.m8n8.x4.shared.b16 {%0,%1,%2,%3}, [%4];"
        : "=r"(r[0]), "=r"(r[1]), "=r"(r[2]), "=r"(r[3]) : "r"(addr));
}
// swizzled byte offset inside one 128-row tile; KCC = K-chunk width (32 or 64 halves)
template <int KCC>
__device__ __forceinline__ uint32_t swz(int row, int seg) {
    if (KCC == 64) return (uint32_t)(row * 128 + ((seg ^ (row & 7)) << 4));
    return (uint32_t)(row * 64 + ((seg ^ ((row >> 1) & 3)) << 4));
}

// ====================== fp16 mma GEMM (128x128 tile) ======================
// All operands row-major with K contiguous: Aop[m][k] (lda), Bop[n][k] (ldb).
// MODE 0: GRAM (symmetric blocks, KC32): NA=2,NB=2, 3 passes; binarize; mirror; deg
// MODE 2: HWT  (KC64) NA=1,NB=1: g = h@WT ; epi: *dinv[row], transpose -> gT fp16
// MODE 1: AH   (KC64) NA=1,NB=1: A@gT     ; epi: relu(*dinv[m]+bias) -> fp16
// MODE 3: AH   (KC64) same, epi -> fp32

template <int MODE>
__global__ __launch_bounds__(256, 2) void mma_gemm(
    const __half* __restrict__ a0, const __half* __restrict__ a1,
    const __half* __restrict__ b0, const __half* __restrict__ b1,
    int lda, int ldb, int K,
    size_t aBatch, size_t bBatch,
    const float* __restrict__ aux, int auxBatch,
    const float* __restrict__ bias,
    void* __restrict__ out0,
    int ldo, size_t oBatch,
    float* __restrict__ deg)
{
    constexpr int NA   = (MODE == 0) ? 2 : 1;
    constexpr int NB   = (MODE == 0) ? 2 : 1;
    constexpr int NOPS = NA + NB;
    constexpr int KCC  = (MODE == 0) ? 32 : 64;
    constexpr int TB   = 128 * KCC * 2;          // tile bytes
    constexpr int NKS  = KCC / 16;

    int m0, n0, b = blockIdx.z;
    if (MODE == 0) {
        int idx = blockIdx.x, bi = 0;
        while (idx >= (C_ / 128 - bi)) { idx -= (C_ / 128 - bi); bi++; }
        m0 = bi * 128; n0 = (bi + idx) * 128;
    } else {
        m0 = blockIdx.y * 128; n0 = blockIdx.x * 128;
    }

    int tid = threadIdx.x, wid = tid >> 5, lane = tid & 31;
    int wm = wid & 1, wn = wid >> 1;          // warp tile 64x32
    int g = lane >> 2, t = lane & 3;

    const __half* ops[NOPS];
    int ldv[NOPS];
    ops[0] = a0 + (size_t)b * aBatch + (size_t)m0 * lda; ldv[0] = lda;
    if (NA == 2) { ops[1] = a1 + (size_t)b * aBatch + (size_t)m0 * lda; ldv[1] = lda; }
    ops[NA] = b0 + (size_t)b * bBatch + (size_t)n0 * ldb; ldv[NA] = ldb;
    if (NB == 2) { ops[NA + 1] = b1 + (size_t)b * bBatch + (size_t)n0 * ldb; ldv[NA + 1] = ldb; }

    extern __shared__ __half sm[];
    uint32_t smb = smem_u32(sm);

    auto load_tile = [&](int op, int buf, int k0) {
        uint32_t st = smb + (uint32_t)(buf * NOPS + op) * TB;
        const __half* src = ops[op] + k0;
        int ld = ldv[op];
        constexpr int ITER = (128 * KCC / 8) / 256;
#pragma unroll
        for (int i2 = 0; i2 < ITER; i2++) {
            int idx = tid + i2 * 256;
            int row, seg;
            if (KCC == 64) { row = idx >> 3; seg = idx & 7; }
            else           { row = idx >> 2; seg = idx & 3; }
            const __half* gp = src + (size_t)row * ld + seg * 8;
            uint32_t sa = st + swz<KCC>(row, seg);
            asm volatile("cp.async.cg.shared.global [%0], [%1], 16;" :: "r"(sa), "l"(gp) : "memory");
        }
    };

    float acc[4][4][4];
#pragma unroll
    for (int i = 0; i < 4; i++)
#pragma unroll
        for (int j = 0; j < 4; j++)
#pragma unroll
            for (int r = 0; r < 4; r++) acc[i][j][r] = 0.f;

    int a_row = ((lane >> 3) & 1) * 8 + (lane & 7);
    int a_sg  = lane >> 4;
    int b_row = ((lane >> 4) & 1) * 8 + (lane & 7);
    int b_sg  = (lane >> 3) & 1;

    // --- GRAM path frags ---
    uint32_t afr[NA][4][4];
    uint32_t bfr0[4][2], bfr1[4][2];

    // compute for NOPS==4 (GRAM): original schedule
    auto compute4 = [&](int buf) {
        uint32_t tb = smb + (uint32_t)(buf * NOPS) * TB;
#pragma unroll
        for (int ks = 0; ks < NKS; ks++) {
            int segA = 2 * ks + a_sg;
            int segB = 2 * ks + b_sg;
#pragma unroll
            for (int i = 0; i < 4; i++)
                ldsm4(afr[0][i], tb + swz<KCC>(wm * 64 + i * 16 + a_row, segA));
#pragma unroll
            for (int i = 0; i < 4; i++)
                ldsm4(afr[NA - 1][i], tb + TB + swz<KCC>(wm * 64 + i * 16 + a_row, segA));
            uint32_t tB0 = tb + (uint32_t)NA * TB;
            ldsm4(&bfr0[0][0], tB0 + swz<KCC>(wn * 32 + b_row, segB));
            ldsm4(&bfr0[2][0], tB0 + swz<KCC>(wn * 32 + 16 + b_row, segB));
            uint32_t tB1 = tB0 + TB;
            ldsm4(&bfr1[0][0], tB1 + swz<KCC>(wn * 32 + b_row, segB));
            ldsm4(&bfr1[2][0], tB1 + swz<KCC>(wn * 32 + 16 + b_row, segB));
#pragma unroll
            for (int i = 0; i < 4; i++)
#pragma unroll
                for (int j = 0; j < 4; j++) mma_f16(acc[i][j], afr[0][i], bfr0[j]);
#pragma unroll
            for (int i = 0; i < 4; i++)
#pragma unroll
                for (int j = 0; j < 4; j++) mma_f16(acc[i][j], afr[NA - 1][i], bfr0[j]);
#pragma unroll
            for (int i = 0; i < 4; i++)
#pragma unroll
                for (int j = 0; j < 4; j++) mma_f16(acc[i][j], afr[0][i], bfr1[j]);
        }
    };

    // compute for NOPS==2 (AH/HWT): intra-chunk frag double-buffering
    uint32_t a2[2][4][4];
    uint32_t b2[2][4][2];
    auto compute2 = [&](int buf) {
        uint32_t tb = smb + (uint32_t)(buf * NOPS) * TB;
        uint32_t tB0 = tb + TB;
        // preload k-step 0
        {
            int segA = a_sg, segB = b_sg;
#pragma unroll
            for (int i = 0; i < 4; i++)
                ldsm4(a2[0][i], tb + swz<KCC>(wm * 64 + i * 16 + a_row, segA));
            ldsm4(&b2[0][0][0], tB0 + swz<KCC>(wn * 32 + b_row, segB));
            ldsm4(&b2[0][2][0], tB0 + swz<KCC>(wn * 32 + 16 + b_row, segB));
        }
#pragma unroll
        for (int ks = 0; ks < NKS; ks++) {
            int cur = ks & 1, nxt = cur ^ 1;
            if (ks + 1 < NKS) {
                int segA = 2 * (ks + 1) + a_sg;
                int segB = 2 * (ks + 1) + b_sg;
#pragma unroll
                for (int i = 0; i < 4; i++)
                    ldsm4(a2[nxt][i], tb + swz<KCC>(wm * 64 + i * 16 + a_row, segA));
                ldsm4(&b2[nxt][0][0], tB0 + swz<KCC>(wn * 32 + b_row, segB));
                ldsm4(&b2[nxt][2][0], tB0 + swz<KCC>(wn * 32 + 16 + b_row, segB));
            }
#pragma unroll
            for (int i = 0; i < 4; i++)
#pragma unroll
                for (int j = 0; j < 4; j++) mma_f16(acc[i][j], a2[cur][i], b2[cur][j]);
        }
    };

    const int NC = K / KCC;
    for (int op = 0; op < NOPS; op++) load_tile(op, 0, 0);
    CP_COMMIT();
    if (NC > 1) {
        for (int op = 0; op < NOPS; op++) load_tile(op, 1, KCC);
        CP_COMMIT();
    }
    for (int c = 0; c < NC; c++) {
        if (c + 1 < NC) { CP_WAIT1(); } else { CP_WAIT0(); }
        __syncthreads();
        if (c + 2 < NC) {
            for (int op = 0; op < NOPS; op++) load_tile(op, (c + 2) % 3, (c + 2) * KCC);
            CP_COMMIT();
        }
        if (NOPS == 2) compute2(c % 3);
        else           compute4(c % 3);
    }

    // ------------------------------- epilogues -------------------------------
    if (MODE == 0) {
        const float* inb = aux + (size_t)b * auxBatch;
        __half* Ab = (__half*)out0 + (size_t)b * oBatch;
        float* degb = deg + (size_t)b * C_;
        float v[4][4][4];
#pragma unroll
        for (int i = 0; i < 4; i++) {
            int r0 = m0 + wm * 64 + i * 16 + g;
            float rs0 = inb[r0], rs1 = inb[r0 + 8];
#pragma unroll
            for (int j = 0; j < 4; j++) {
                int cl = n0 + wn * 32 + j * 8 + t * 2;
                float j0 = inb[cl], j1 = inb[cl + 1];
                v[i][j][0] = (acc[i][j][0] * rs0 * j0 > THRESH) ? 1.f : 0.f;
                v[i][j][1] = (acc[i][j][1] * rs0 * j1 > THRESH) ? 1.f : 0.f;
                v[i][j][2] = (acc[i][j][2] * rs1 * j0 > THRESH) ? 1.f : 0.f;
                v[i][j][3] = (acc[i][j][3] * rs1 * j1 > THRESH) ? 1.f : 0.f;
                *(__half2*)(Ab + (size_t)r0 * ldo + cl)       = __floats2half2_rn(v[i][j][0], v[i][j][1]);
                *(__half2*)(Ab + (size_t)(r0 + 8) * ldo + cl) = __floats2half2_rn(v[i][j][2], v[i][j][3]);
            }
        }
#pragma unroll
        for (int i = 0; i < 4; i++) {
            float s0 = 0.f, s1 = 0.f;
#pragma unroll
            for (int j = 0; j < 4; j++) {
                s0 += v[i][j][0] + v[i][j][1];
                s1 += v[i][j][2] + v[i][j][3];
            }
            s0 += __shfl_xor_sync(0xFFFFFFFFu, s0, 1); s0 += __shfl_xor_sync(0xFFFFFFFFu, s0, 2);
            s1 += __shfl_xor_sync(0xFFFFFFFFu, s1, 1); s1 += __shfl_xor_sync(0xFFFFFFFFu, s1, 2);
            if (t == 0) {
                atomicAdd(&degb[m0 + wm * 64 + i * 16 + g], s0);
                atomicAdd(&degb[m0 + wm * 64 + i * 16 + g + 8], s1);
            }
        }
        if (m0 != n0) {
#pragma unroll
            for (int j = 0; j < 4; j++) {
                float c0 = 0.f, c1 = 0.f;
#pragma unroll
                for (int i = 0; i < 4; i++) {
                    c0 += v[i][j][0] + v[i][j][2];
                    c1 += v[i][j][1] + v[i][j][3];
                }
                c0 += __shfl_xor_sync(0xFFFFFFFFu, c0, 4); c0 += __shfl_xor_sync(0xFFFFFFFFu, c0, 8); c0 += __shfl_xor_sync(0xFFFFFFFFu, c0, 16);
                c1 += __shfl_xor_sync(0xFFFFFFFFu, c1, 4); c1 += __shfl_xor_sync(0xFFFFFFFFu, c1, 8); c1 += __shfl_xor_sync(0xFFFFFFFFu, c1, 16);
                if (lane < 4) {
                    atomicAdd(&degb[n0 + wn * 32 + j * 8 + t * 2], c0);
                    atomicAdd(&degb[n0 + wn * 32 + j * 8 + t * 2 + 1], c1);
                }
            }
            __syncthreads();
            float* stage = (float*)sm;                 // 128 x 129 floats
#pragma unroll
            for (int i = 0; i < 4; i++) {
                int rr = wm * 64 + i * 16 + g;
#pragma unroll
                for (int j = 0; j < 4; j++) {
                    int cc = wn * 32 + j * 8 + t * 2;
                    stage[rr * 129 + cc]           = v[i][j][0];
                    stage[rr * 129 + cc + 1]       = v[i][j][1];
                    stage[(rr + 8) * 129 + cc]     = v[i][j][2];
                    stage[(rr + 8) * 129 + cc + 1] = v[i][j][3];
                }
            }
            __syncthreads();
#pragma unroll
            for (int q = 0; q < 16; q++) {
                int idx = tid + q * 256;
                int r = idx >> 5;
                int c4 = (idx & 31) * 4;
                float f0 = stage[(c4 + 0) * 129 + r];
                float f1 = stage[(c4 + 1) * 129 + r];
                float f2 = stage[(c4 + 2) * 129 + r];
                float f3 = stage[(c4 + 3) * 129 + r];
                __half* dst = Ab + (size_t)(n0 + r) * ldo + m0 + c4;
                ((__half2*)dst)[0] = __floats2half2_rn(f0, f1);
                ((__half2*)dst)[1] = __floats2half2_rn(f2, f3);
            }
        }
    } else if (MODE == 2) {
        // g = h@WT row-scale by dinv[global row], transpose -> gT fp16 [b][f][c]
        const float* db = aux;                       // flattened dinv, index m0+row
        __syncthreads();
        float* stage = (float*)sm;                   // 128 x 129 floats
#pragma unroll
        for (int i = 0; i < 4; i++) {
            int rr = wm * 64 + i * 16 + g;
            float d0 = db[m0 + rr], d1 = db[m0 + rr + 8];
#pragma unroll
            for (int j = 0; j < 4; j++) {
                int cc = wn * 32 + j * 8 + t * 2;
                stage[rr * 129 + cc]           = acc[i][j][0] * d0;
                stage[rr * 129 + cc + 1]       = acc[i][j][1] * d0;
                stage[(rr + 8) * 129 + cc]     = acc[i][j][2] * d1;
                stage[(rr + 8) * 129 + cc + 1] = acc[i][j][3] * d1;
            }
        }
        __syncthreads();
        int bb = m0 / C_;
        int cb = m0 % C_;
        __half* ghi = (__half*)out0;
#pragma unroll
        for (int q = 0; q < 16; q++) {
            int idx = tid + q * 256;
            int r = idx >> 5;                         // local f
            int c4 = (idx & 31) * 4;                  // local c, 4-aligned
            float f0 = stage[(c4 + 0) * 129 + r];
            float f1 = stage[(c4 + 1) * 129 + r];
            float f2 = stage[(c4 + 2) * 129 + r];
            float f3 = stage[(c4 + 3) * 129 + r];
            size_t o = ((size_t)bb * F_ + n0 + r) * C_ + cb + c4;
            ((__half2*)(ghi + o))[0] = __floats2half2_rn(f0, f1);
            ((__half2*)(ghi + o))[1] = __floats2half2_rn(f2, f3);
        }
    } else {
        // AH: v = relu(acc * dinv[m] + bias)
        const float* db = aux + (size_t)b * auxBatch;
        float bs = bias[0];
#pragma unroll
        for (int i = 0; i < 4; i++) {
            int r0 = m0 + wm * 64 + i * 16 + g;
            float rs0 = db[r0], rs1 = db[r0 + 8];
#pragma unroll
            for (int j = 0; j < 4; j++) {
                int cl = n0 + wn * 32 + j * 8 + t * 2;
                float v00 = fmaxf(acc[i][j][0] * rs0 + bs, 0.f);
                float v01 = fmaxf(acc[i][j][1] * rs0 + bs, 0.f);
                float v10 = fmaxf(acc[i][j][2] * rs1 + bs, 0.f);
                float v11 = fmaxf(acc[i][j][3] * rs1 + bs, 0.f);
                if (MODE == 1) {
                    __half* o0 = (__half*)out0 + (size_t)b * oBatch;
                    *(__half2*)(o0 + (size_t)r0 * ldo + cl)       = __floats2half2_rn(v00, v01);
                    *(__half2*)(o0 + (size_t)(r0 + 8) * ldo + cl) = __floats2half2_rn(v10, v11);
                } else {
                    float* o = (float*)out0 + (size_t)b * oBatch;
                    *(float2*)(o + (size_t)r0 * ldo + cl)       = make_float2(v00, v01);
                    *(float2*)(o + (size_t)(r0 + 8) * ldo + cl) = make_float2(v10, v11);
                }
            }
        }
    }
}

// =============================== small kernels ==============================
__global__ void zero_kernel(float* __restrict__ p) {
    p[blockIdx.x * 256 + threadIdx.x] = 0.f;
}

// fused: row inv-norms + fp16 hi/lo split of x
__global__ void norm_split(const float* __restrict__ x, float* __restrict__ invn,
                           __half* __restrict__ hi, __half* __restrict__ lo) {
    int row = blockIdx.x;
    const float* xr = x + (size_t)row * F_;
    float4 v = ((const float4*)xr)[threadIdx.x];
    float s = v.x * v.x + v.y * v.y + v.z * v.z + v.w * v.w;
#pragma unroll
    for (int o = 16; o > 0; o >>= 1) s += __shfl_xor_sync(0xFFFFFFFFu, s, o);
    __shared__ float red[4];
    if ((threadIdx.x & 31) == 0) red[threadIdx.x >> 5] = s;
    __syncthreads();
    if (threadIdx.x == 0)
        invn[row] = 1.0f / sqrtf(red[0] + red[1] + red[2] + red[3]);

    __half h0 = __float2half_rn(v.x), h1 = __float2half_rn(v.y);
    __half h2 = __float2half_rn(v.z), h3 = __float2half_rn(v.w);
    size_t o = (size_t)row * F_ + threadIdx.x * 4;
    *(__half2*)(hi + o)     = __halves2half2(h0, h1);
    *(__half2*)(hi + o + 2) = __halves2half2(h2, h3);
    *(__half2*)(lo + o)     = __floats2half2_rn(v.x - __half2float(h0), v.y - __half2float(h1));
    *(__half2*)(lo + o + 2) = __floats2half2_rn(v.z - __half2float(h2), v.w - __half2float(h3));
}

__global__ void dinv_kernel(const float* __restrict__ deg, float* __restrict__ dinv) {
    int i = blockIdx.x * 256 + threadIdx.x;
    dinv[i] = 1.0f / sqrtf(deg[i]);
}

// W[f,g] -> WT[g,f] single fp16
__global__ void wtrans_kernel(const float* __restrict__ W, __half* __restrict__ hi) {
    __shared__ float tsm[32][33];
    int g0 = blockIdx.x * 32, f0 = blockIdx.y * 32;
#pragma unroll
    for (int k = 0; k < 4; k++) {
        int f = f0 + threadIdx.y + k * 8;
        tsm[threadIdx.x][threadIdx.y + k * 8] = W[(size_t)f * F_ + g0 + threadIdx.x];
    }
    __syncthreads();
#pragma unroll
    for (int k = 0; k < 4; k++) {
        int gg = g0 + threadIdx.y + k * 8;
        hi[(size_t)gg * F_ + f0 + threadIdx.x] = __float2half_rn(tsm[threadIdx.y + k * 8][threadIdx.x]);
    }
}

// ============================================================================
extern "C" void kernel_launch(void* const* d_in, const int* in_sizes, int n_in,
                              void* d_out, int out_size) {
    const float* x  = (const float*)d_in[0];
    const float* W1 = (const float*)d_in[1];
    const float* b1 = (const float*)d_in[2];
    const float* W2 = (const float*)d_in[3];
    const float* b2 = (const float*)d_in[4];
    float* out = (float*)d_out;

    __half *pA, *pxhi, *pxlo, *pgT, *ph2, *pWT;
    float *pinvn, *pdeg, *pdinv;
    cudaGetSymbolAddress((void**)&pA,    g_A);
    cudaGetSymbolAddress((void**)&pinvn, g_invn);
    cudaGetSymbolAddress((void**)&pdeg,  g_deg);
    cudaGetSymbolAddress((void**)&pdinv, g_dinv);
    cudaGetSymbolAddress((void**)&pxhi,  g_xhi);
    cudaGetSymbolAddress((void**)&pxlo,  g_xlo);
    cudaGetSymbolAddress((void**)&pgT,   g_gT);
    cudaGetSymbolAddress((void**)&ph2,   g_h2);
    cudaGetSymbolAddress((void**)&pWT,   g_WT);

    const int smem0 = 4 * 3 * (128 * 32 * 2);   // 98304 B (GRAM: 4 ops, KC32)
    const int smem1 = 2 * 3 * (128 * 64 * 2);   // 98304 B (HWT/AH: 2 ops, KC64)
    cudaFuncSetAttribute(mma_gemm<0>, cudaFuncAttributeMaxDynamicSharedMemorySize, smem0);
    cudaFuncSetAttribute(mma_gemm<1>, cudaFuncAttributeMaxDynamicSharedMemorySize, smem1);
    cudaFuncSetAttribute(mma_gemm<2>, cudaFuncAttributeMaxDynamicSharedMemorySize, smem1);
    cudaFuncSetAttribute(mma_gemm<3>, cudaFuncAttributeMaxDynamicSharedMemorySize, smem1);

    const int NBLK = C_ / 128;                       // 16
    const int NTRI = NBLK * (NBLK + 1) / 2;          // 136

    // ---- Laplacian ----
    zero_kernel<<<(B_ * C_) / 256, 256>>>(pdeg);
    norm_split<<<B_ * C_, 128>>>(x, pinvn, pxhi, pxlo);
    mma_gemm<0><<<dim3(NTRI, 1, B_), 256, smem0>>>(
        pxhi, pxlo, pxhi, pxlo, F_, F_, F_,
        (size_t)C_ * F_, (size_t)C_ * F_, pinvn, C_, nullptr,
        pA, C_, (size_t)C_ * C_, pdeg);
    dinv_kernel<<<(B_ * C_) / 256, 256>>>(pdeg, pdinv);

    // ---- layer 1: relu(L @ (x @ W1) + b1) ----
    wtrans_kernel<<<dim3(F_ / 32, F_ / 32), dim3(32, 8)>>>(W1, pWT);
    mma_gemm<2><<<dim3(F_ / 128, (B_ * C_) / 128, 1), 256, smem1>>>(
        pxhi, nullptr, pWT, nullptr, F_, F_, F_,
        0, 0, pdinv, 0, nullptr,
        pgT, C_, 0, nullptr);
    mma_gemm<1><<<dim3(F_ / 128, C_ / 128, B_), 256, smem1>>>(
        pA, nullptr, pgT, nullptr, C_, C_, C_,
        (size_t)C_ * C_, (size_t)F_ * C_, pdinv, C_, b1,
        ph2, F_, (size_t)C_ * F_, nullptr);

    // ---- layer 2: relu(L @ (h2 @ W2) + b2) ----
    wtrans_kernel<<<dim3(F_ / 32, F_ / 32), dim3(32, 8)>>>(W2, pWT);
    mma_gemm<2><<<dim3(F_ / 128, (B_ * C_) / 128, 1), 256, smem1>>>(
        ph2, nullptr, pWT, nullptr, F_, F_, F_,
        0, 0, pdinv, 0, nullptr,
        pgT, C_, 0, nullptr);
    mma_gemm<3><<<dim3(F_ / 128, C_ / 128, B_), 256, smem1>>>(
        pA, nullptr, pgT, nullptr, C_, C_, C_,
        (size_t)C_ * C_, (size_t)F_ * C_, pdinv, C_, b2,
        out, F_, (size_t)C_ * F_, nullptr);
}

// round 14
// speedup vs baseline: 5.3444x; 1.0096x over previous
#include <cuda_runtime.h>
#include <cuda_fp16.h>
#include <cstdint>
#include <math.h>

#define B_ 8
#define C_ 2048
#define F_ 512
#define THRESH 0.005f

// ---- scratch (device globals: no allocation allowed) ----
__device__ __half g_A[(size_t)B_ * C_ * C_];       // binary adjacency (fp16 0/1)
__device__ float  g_invn[B_ * C_];
__device__ float  g_deg[B_ * C_];
__device__ float  g_dinv[B_ * C_];
__device__ __half g_xhi[(size_t)B_ * C_ * F_];
__device__ __half g_xlo[(size_t)B_ * C_ * F_];
__device__ __half g_gT[(size_t)B_ * F_ * C_];      // (dinv*(h@W))^T  fp16
__device__ __half g_h2[(size_t)B_ * C_ * F_];      // hidden activations fp16
__device__ __half g_WT1[F_ * F_];                  // W1^T fp16
__device__ __half g_WT2[F_ * F_];                  // W2^T fp16

// =============================== helpers ===============================
__device__ __forceinline__ uint32_t smem_u32(const void* p) {
    uint32_t a;
    asm("{ .reg .u64 t; cvta.to.shared.u64 t, %1; cvt.u32.u64 %0, t; }" : "=r"(a) : "l"(p));
    return a;
}
#define CP_COMMIT() asm volatile("cp.async.commit_group;" ::: "memory")
#define CP_WAIT1()  asm volatile("cp.async.wait_group 1;" ::: "memory")
#define CP_WAIT0()  asm volatile("cp.async.wait_group 0;" ::: "memory")

__device__ __forceinline__ void mma_f16(float c[4], const uint32_t a[4], const uint32_t b[2]) {
    asm volatile(
        "mma.sync.aligned.m16n8k16.row.col.f32.f16.f16.f32 "
        "{%0,%1,%2,%3}, {%4,%5,%6,%7}, {%8,%9}, {%0,%1,%2,%3};"
        : "+f"(c[0]), "+f"(c[1]), "+f"(c[2]), "+f"(c[3])
        : "r"(a[0]), "r"(a[1]), "r"(a[2]), "r"(a[3]), "r"(b[0]), "r"(b[1]));
}
__device__ __forceinline__ void ldsm4(uint32_t r[4], uint32_t addr) {
    asm volatile("ldmatrix.sync.aligned.m8n8.x4.shared.b16 {%0,%1,%2,%3}, [%4];"
        : "=r"(r[0]), "=r"(r[1]), "=r"(r[2]), "=r"(r[3]) : "r"(addr));
}
// swizzled byte offset inside one 128-row tile; KCC = K-chunk width (32 or 64 halves)
template <int KCC>
__device__ __forceinline__ uint32_t swz(int row, int seg) {
    if (KCC == 64) return (uint32_t)(row * 128 + ((seg ^ (row & 7)) << 4));
    return (uint32_t)(row * 64 + ((seg ^ ((row >> 1) & 3)) << 4));
}

// ====================== fp16 mma GEMM (128x128 tile) ======================
// All operands row-major with K contiguous: Aop[m][k] (lda), Bop[n][k] (ldb).
// MODE 0: GRAM (symmetric blocks, KC32): NA=2,NB=2, 3 passes; binarize; mirror; deg
//         diagonal blocks alias B tiles to A tiles (identical data, half the loads)
// MODE 2: HWT  (KC64) NA=1,NB=1: g = h@WT ; epi: *dinv[row], transpose -> gT fp16
// MODE 1: AH   (KC64) NA=1,NB=1: A@gT     ; epi: relu(*dinv[m]+bias) -> fp16
// MODE 3: AH   (KC64) same, epi -> fp32

template <int MODE>
__global__ __launch_bounds__(256, 2) void mma_gemm(
    const __half* __restrict__ a0, const __half* __restrict__ a1,
    const __half* __restrict__ b0, const __half* __restrict__ b1,
    int lda, int ldb, int K,
    size_t aBatch, size_t bBatch,
    const float* __restrict__ aux, int auxBatch,
    const float* __restrict__ bias,
    void* __restrict__ out0,
    int ldo, size_t oBatch,
    float* __restrict__ deg)
{
    constexpr int NA   = (MODE == 0) ? 2 : 1;
    constexpr int NB   = (MODE == 0) ? 2 : 1;
    constexpr int NOPS = NA + NB;
    constexpr int KCC  = (MODE == 0) ? 32 : 64;
    constexpr int TB   = 128 * KCC * 2;          // tile bytes
    constexpr int NKS  = KCC / 16;

    int m0, n0, b = blockIdx.z;
    if (MODE == 0) {
        int idx = blockIdx.x, bi = 0;
        while (idx >= (C_ / 128 - bi)) { idx -= (C_ / 128 - bi); bi++; }
        m0 = bi * 128; n0 = (bi + idx) * 128;
    } else {
        m0 = blockIdx.y * 128; n0 = blockIdx.x * 128;
    }
    const bool diag = (MODE == 0) && (m0 == n0);
    const int nload = diag ? NA : NOPS;          // diagonal: skip B tile loads

    int tid = threadIdx.x, wid = tid >> 5, lane = tid & 31;
    int wm = wid & 1, wn = wid >> 1;          // warp tile 64x32
    int g = lane >> 2, t = lane & 3;

    const __half* ops[NOPS];
    int ldv[NOPS];
    ops[0] = a0 + (size_t)b * aBatch + (size_t)m0 * lda; ldv[0] = lda;
    if (NA == 2) { ops[1] = a1 + (size_t)b * aBatch + (size_t)m0 * lda; ldv[1] = lda; }
    ops[NA] = b0 + (size_t)b * bBatch + (size_t)n0 * ldb; ldv[NA] = ldb;
    if (NB == 2) { ops[NA + 1] = b1 + (size_t)b * bBatch + (size_t)n0 * ldb; ldv[NA + 1] = ldb; }

    extern __shared__ __half sm[];
    uint32_t smb = smem_u32(sm);

    auto load_tile = [&](int op, int buf, int k0) {
        uint32_t st = smb + (uint32_t)(buf * NOPS + op) * TB;
        const __half* src = ops[op] + k0;
        int ld = ldv[op];
        constexpr int ITER = (128 * KCC / 8) / 256;
#pragma unroll
        for (int i2 = 0; i2 < ITER; i2++) {
            int idx = tid + i2 * 256;
            int row, seg;
            if (KCC == 64) { row = idx >> 3; seg = idx & 7; }
            else           { row = idx >> 2; seg = idx & 3; }
            const __half* gp = src + (size_t)row * ld + seg * 8;
            uint32_t sa = st + swz<KCC>(row, seg);
            asm volatile("cp.async.cg.shared.global [%0], [%1], 16;" :: "r"(sa), "l"(gp) : "memory");
        }
    };

    float acc[4][4][4];
#pragma unroll
    for (int i = 0; i < 4; i++)
#pragma unroll
        for (int j = 0; j < 4; j++)
#pragma unroll
            for (int r = 0; r < 4; r++) acc[i][j][r] = 0.f;

    int a_row = ((lane >> 3) & 1) * 8 + (lane & 7);
    int a_sg  = lane >> 4;
    int b_row = ((lane >> 4) & 1) * 8 + (lane & 7);
    int b_sg  = (lane >> 3) & 1;

    // --- GRAM path frags ---
    uint32_t afr[NA][4][4];
    uint32_t bfr0[4][2], bfr1[4][2];

    // compute for NOPS==4 (GRAM)
    auto compute4 = [&](int buf) {
        uint32_t tb = smb + (uint32_t)(buf * NOPS) * TB;
        uint32_t tB0 = tb + (diag ? 0u : 2u * TB);     // alias B->A on diagonal
        uint32_t tB1 = tb + (diag ? 1u : 3u) * TB;
#pragma unroll
        for (int ks = 0; ks < NKS; ks++) {
            int segA = 2 * ks + a_sg;
            int segB = 2 * ks + b_sg;
#pragma unroll
            for (int i = 0; i < 4; i++)
                ldsm4(afr[0][i], tb + swz<KCC>(wm * 64 + i * 16 + a_row, segA));
#pragma unroll
            for (int i = 0; i < 4; i++)
                ldsm4(afr[NA - 1][i], tb + TB + swz<KCC>(wm * 64 + i * 16 + a_row, segA));
            ldsm4(&bfr0[0][0], tB0 + swz<KCC>(wn * 32 + b_row, segB));
            ldsm4(&bfr0[2][0], tB0 + swz<KCC>(wn * 32 + 16 + b_row, segB));
            ldsm4(&bfr1[0][0], tB1 + swz<KCC>(wn * 32 + b_row, segB));
            ldsm4(&bfr1[2][0], tB1 + swz<KCC>(wn * 32 + 16 + b_row, segB));
#pragma unroll
            for (int i = 0; i < 4; i++)
#pragma unroll
                for (int j = 0; j < 4; j++) mma_f16(acc[i][j], afr[0][i], bfr0[j]);
#pragma unroll
            for (int i = 0; i < 4; i++)
#pragma unroll
                for (int j = 0; j < 4; j++) mma_f16(acc[i][j], afr[NA - 1][i], bfr0[j]);
#pragma unroll
            for (int i = 0; i < 4; i++)
#pragma unroll
                for (int j = 0; j < 4; j++) mma_f16(acc[i][j], afr[0][i], bfr1[j]);
        }
    };

    // compute for NOPS==2 (AH/HWT): intra-chunk frag double-buffering
    uint32_t a2[2][4][4];
    uint32_t b2[2][4][2];
    auto compute2 = [&](int buf) {
        uint32_t tb = smb + (uint32_t)(buf * NOPS) * TB;
        uint32_t tB0 = tb + TB;
        {
            int segA = a_sg, segB = b_sg;
#pragma unroll
            for (int i = 0; i < 4; i++)
                ldsm4(a2[0][i], tb + swz<KCC>(wm * 64 + i * 16 + a_row, segA));
            ldsm4(&b2[0][0][0], tB0 + swz<KCC>(wn * 32 + b_row, segB));
            ldsm4(&b2[0][2][0], tB0 + swz<KCC>(wn * 32 + 16 + b_row, segB));
        }
#pragma unroll
        for (int ks = 0; ks < NKS; ks++) {
            int cur = ks & 1, nxt = cur ^ 1;
            if (ks + 1 < NKS) {
                int segA = 2 * (ks + 1) + a_sg;
                int segB = 2 * (ks + 1) + b_sg;
#pragma unroll
                for (int i = 0; i < 4; i++)
                    ldsm4(a2[nxt][i], tb + swz<KCC>(wm * 64 + i * 16 + a_row, segA));
                ldsm4(&b2[nxt][0][0], tB0 + swz<KCC>(wn * 32 + b_row, segB));
                ldsm4(&b2[nxt][2][0], tB0 + swz<KCC>(wn * 32 + 16 + b_row, segB));
            }
#pragma unroll
            for (int i = 0; i < 4; i++)
#pragma unroll
                for (int j = 0; j < 4; j++) mma_f16(acc[i][j], a2[cur][i], b2[cur][j]);
        }
    };

    const int NC = K / KCC;
    for (int op = 0; op < nload; op++) load_tile(op, 0, 0);
    CP_COMMIT();
    if (NC > 1) {
        for (int op = 0; op < nload; op++) load_tile(op, 1, KCC);
        CP_COMMIT();
    }
    for (int c = 0; c < NC; c++) {
        if (c + 1 < NC) { CP_WAIT1(); } else { CP_WAIT0(); }
        __syncthreads();
        if (c + 2 < NC) {
            for (int op = 0; op < nload; op++) load_tile(op, (c + 2) % 3, (c + 2) * KCC);
            CP_COMMIT();
        }
        if (NOPS == 2) compute2(c % 3);
        else           compute4(c % 3);
    }

    // ------------------------------- epilogues -------------------------------
    if (MODE == 0) {
        const float* inb = aux + (size_t)b * auxBatch;
        __half* Ab = (__half*)out0 + (size_t)b * oBatch;
        float* degb = deg + (size_t)b * C_;
        float v[4][4][4];
#pragma unroll
        for (int i = 0; i < 4; i++) {
            int r0 = m0 + wm * 64 + i * 16 + g;
            float rs0 = inb[r0], rs1 = inb[r0 + 8];
#pragma unroll
            for (int j = 0; j < 4; j++) {
                int cl = n0 + wn * 32 + j * 8 + t * 2;
                float j0 = inb[cl], j1 = inb[cl + 1];
                v[i][j][0] = (acc[i][j][0] * rs0 * j0 > THRESH) ? 1.f : 0.f;
                v[i][j][1] = (acc[i][j][1] * rs0 * j1 > THRESH) ? 1.f : 0.f;
                v[i][j][2] = (acc[i][j][2] * rs1 * j0 > THRESH) ? 1.f : 0.f;
                v[i][j][3] = (acc[i][j][3] * rs1 * j1 > THRESH) ? 1.f : 0.f;
                *(__half2*)(Ab + (size_t)r0 * ldo + cl)       = __floats2half2_rn(v[i][j][0], v[i][j][1]);
                *(__half2*)(Ab + (size_t)(r0 + 8) * ldo + cl) = __floats2half2_rn(v[i][j][2], v[i][j][3]);
            }
        }
#pragma unroll
        for (int i = 0; i < 4; i++) {
            float s0 = 0.f, s1 = 0.f;
#pragma unroll
            for (int j = 0; j < 4; j++) {
                s0 += v[i][j][0] + v[i][j][1];
                s1 += v[i][j][2] + v[i][j][3];
            }
            s0 += __shfl_xor_sync(0xFFFFFFFFu, s0, 1); s0 += __shfl_xor_sync(0xFFFFFFFFu, s0, 2);
            s1 += __shfl_xor_sync(0xFFFFFFFFu, s1, 1); s1 += __shfl_xor_sync(0xFFFFFFFFu, s1, 2);
            if (t == 0) {
                atomicAdd(&degb[m0 + wm * 64 + i * 16 + g], s0);
                atomicAdd(&degb[m0 + wm * 64 + i * 16 + g + 8], s1);
            }
        }
        if (m0 != n0) {
#pragma unroll
            for (int j = 0; j < 4; j++) {
                float c0 = 0.f, c1 = 0.f;
#pragma unroll
                for (int i = 0; i < 4; i++) {
                    c0 += v[i][j][0] + v[i][j][2];
                    c1 += v[i][j][1] + v[i][j][3];
                }
                c0 += __shfl_xor_sync(0xFFFFFFFFu, c0, 4); c0 += __shfl_xor_sync(0xFFFFFFFFu, c0, 8); c0 += __shfl_xor_sync(0xFFFFFFFFu, c0, 16);
                c1 += __shfl_xor_sync(0xFFFFFFFFu, c1, 4); c1 += __shfl_xor_sync(0xFFFFFFFFu, c1, 8); c1 += __shfl_xor_sync(0xFFFFFFFFu, c1, 16);
                if (lane < 4) {
                    atomicAdd(&degb[n0 + wn * 32 + j * 8 + t * 2], c0);
                    atomicAdd(&degb[n0 + wn * 32 + j * 8 + t * 2 + 1], c1);
                }
            }
            __syncthreads();
            float* stage = (float*)sm;                 // 128 x 129 floats
#pragma unroll
            for (int i = 0; i < 4; i++) {
                int rr = wm * 64 + i * 16 + g;
#pragma unroll
                for (int j = 0; j < 4; j++) {
                    int cc = wn * 32 + j * 8 + t * 2;
                    stage[rr * 129 + cc]           = v[i][j][0];
                    stage[rr * 129 + cc + 1]       = v[i][j][1];
                    stage[(rr + 8) * 129 + cc]     = v[i][j][2];
                    stage[(rr + 8) * 129 + cc + 1] = v[i][j][3];
                }
            }
            __syncthreads();
#pragma unroll
            for (int q = 0; q < 16; q++) {
                int idx = tid + q * 256;
                int r = idx >> 5;
                int c4 = (idx & 31) * 4;
                float f0 = stage[(c4 + 0) * 129 + r];
                float f1 = stage[(c4 + 1) * 129 + r];
                float f2 = stage[(c4 + 2) * 129 + r];
                float f3 = stage[(c4 + 3) * 129 + r];
                __half* dst = Ab + (size_t)(n0 + r) * ldo + m0 + c4;
                ((__half2*)dst)[0] = __floats2half2_rn(f0, f1);
                ((__half2*)dst)[1] = __floats2half2_rn(f2, f3);
            }
        }
    } else if (MODE == 2) {
        // g = h@WT row-scale by dinv[global row], transpose -> gT fp16 [b][f][c]
        const float* db = aux;                       // flattened dinv, index m0+row
        __syncthreads();
        float* stage = (float*)sm;                   // 128 x 129 floats
#pragma unroll
        for (int i = 0; i < 4; i++) {
            int rr = wm * 64 + i * 16 + g;
            float d0 = db[m0 + rr], d1 = db[m0 + rr + 8];
#pragma unroll
            for (int j = 0; j < 4; j++) {
                int cc = wn * 32 + j * 8 + t * 2;
                stage[rr * 129 + cc]           = acc[i][j][0] * d0;
                stage[rr * 129 + cc + 1]       = acc[i][j][1] * d0;
                stage[(rr + 8) * 129 + cc]     = acc[i][j][2] * d1;
                stage[(rr + 8) * 129 + cc + 1] = acc[i][j][3] * d1;
            }
        }
        __syncthreads();
        int bb = m0 / C_;
        int cb = m0 % C_;
        __half* ghi = (__half*)out0;
#pragma unroll
        for (int q = 0; q < 16; q++) {
            int idx = tid + q * 256;
            int r = idx >> 5;                         // local f
            int c4 = (idx & 31) * 4;                  // local c, 4-aligned
            float f0 = stage[(c4 + 0) * 129 + r];
            float f1 = stage[(c4 + 1) * 129 + r];
            float f2 = stage[(c4 + 2) * 129 + r];
            float f3 = stage[(c4 + 3) * 129 + r];
            size_t o = ((size_t)bb * F_ + n0 + r) * C_ + cb + c4;
            ((__half2*)(ghi + o))[0] = __floats2half2_rn(f0, f1);
            ((__half2*)(ghi + o))[1] = __floats2half2_rn(f2, f3);
        }
    } else {
        // AH: v = relu(acc * dinv[m] + bias)
        const float* db = aux + (size_t)b * auxBatch;
        float bs = bias[0];
#pragma unroll
        for (int i = 0; i < 4; i++) {
            int r0 = m0 + wm * 64 + i * 16 + g;
            float rs0 = db[r0], rs1 = db[r0 + 8];
#pragma unroll
            for (int j = 0; j < 4; j++) {
                int cl = n0 + wn * 32 + j * 8 + t * 2;
                float v00 = fmaxf(acc[i][j][0] * rs0 + bs, 0.f);
                float v01 = fmaxf(acc[i][j][1] * rs0 + bs, 0.f);
                float v10 = fmaxf(acc[i][j][2] * rs1 + bs, 0.f);
                float v11 = fmaxf(acc[i][j][3] * rs1 + bs, 0.f);
                if (MODE == 1) {
                    __half* o0 = (__half*)out0 + (size_t)b * oBatch;
                    *(__half2*)(o0 + (size_t)r0 * ldo + cl)       = __floats2half2_rn(v00, v01);
                    *(__half2*)(o0 + (size_t)(r0 + 8) * ldo + cl) = __floats2half2_rn(v10, v11);
                } else {
                    float* o = (float*)out0 + (size_t)b * oBatch;
                    *(float2*)(o + (size_t)r0 * ldo + cl)       = make_float2(v00, v01);
                    *(float2*)(o + (size_t)(r0 + 8) * ldo + cl) = make_float2(v10, v11);
                }
            }
        }
    }
}

// =============================== small kernels ==============================
// fused: row inv-norms + fp16 hi/lo split of x + deg zeroing
__global__ void norm_split(const float* __restrict__ x, float* __restrict__ invn,
                           __half* __restrict__ hi, __half* __restrict__ lo,
                           float* __restrict__ deg) {
    int row = blockIdx.x;
    const float* xr = x + (size_t)row * F_;
    float4 v = ((const float4*)xr)[threadIdx.x];
    float s = v.x * v.x + v.y * v.y + v.z * v.z + v.w * v.w;
#pragma unroll
    for (int o = 16; o > 0; o >>= 1) s += __shfl_xor_sync(0xFFFFFFFFu, s, o);
    __shared__ float red[4];
    if ((threadIdx.x & 31) == 0) red[threadIdx.x >> 5] = s;
    __syncthreads();
    if (threadIdx.x == 0) {
        invn[row] = 1.0f / sqrtf(red[0] + red[1] + red[2] + red[3]);
        deg[row] = 0.f;
    }

    __half h0 = __float2half_rn(v.x), h1 = __float2half_rn(v.y);
    __half h2 = __float2half_rn(v.z), h3 = __float2half_rn(v.w);
    size_t o = (size_t)row * F_ + threadIdx.x * 4;
    *(__half2*)(hi + o)     = __halves2half2(h0, h1);
    *(__half2*)(hi + o + 2) = __halves2half2(h2, h3);
    *(__half2*)(lo + o)     = __floats2half2_rn(v.x - __half2float(h0), v.y - __half2float(h1));
    *(__half2*)(lo + o + 2) = __floats2half2_rn(v.z - __half2float(h2), v.w - __half2float(h3));
}

__global__ void dinv_kernel(const float* __restrict__ deg, float* __restrict__ dinv) {
    int i = blockIdx.x * 256 + threadIdx.x;
    dinv[i] = 1.0f / sqrtf(deg[i]);
}

// W[f,g] -> WT[g,f] single fp16
__global__ void wtrans_kernel(const float* __restrict__ W, __half* __restrict__ hi) {
    __shared__ float tsm[32][33];
    int g0 = blockIdx.x * 32, f0 = blockIdx.y * 32;
#pragma unroll
    for (int k = 0; k < 4; k++) {
        int f = f0 + threadIdx.y + k * 8;
        tsm[threadIdx.x][threadIdx.y + k * 8] = W[(size_t)f * F_ + g0 + threadIdx.x];
    }
    __syncthreads();
#pragma unroll
    for (int k = 0; k < 4; k++) {
        int gg = g0 + threadIdx.y + k * 8;
        hi[(size_t)gg * F_ + f0 + threadIdx.x] = __float2half_rn(tsm[threadIdx.y + k * 8][threadIdx.x]);
    }
}

// ============================================================================
extern "C" void kernel_launch(void* const* d_in, const int* in_sizes, int n_in,
                              void* d_out, int out_size) {
    const float* x  = (const float*)d_in[0];
    const float* W1 = (const float*)d_in[1];
    const float* b1 = (const float*)d_in[2];
    const float* W2 = (const float*)d_in[3];
    const float* b2 = (const float*)d_in[4];
    float* out = (float*)d_out;

    __half *pA, *pxhi, *pxlo, *pgT, *ph2, *pWT1, *pWT2;
    float *pinvn, *pdeg, *pdinv;
    cudaGetSymbolAddress((void**)&pA,    g_A);
    cudaGetSymbolAddress((void**)&pinvn, g_invn);
    cudaGetSymbolAddress((void**)&pdeg,  g_deg);
    cudaGetSymbolAddress((void**)&pdinv, g_dinv);
    cudaGetSymbolAddress((void**)&pxhi,  g_xhi);
    cudaGetSymbolAddress((void**)&pxlo,  g_xlo);
    cudaGetSymbolAddress((void**)&pgT,   g_gT);
    cudaGetSymbolAddress((void**)&ph2,   g_h2);
    cudaGetSymbolAddress((void**)&pWT1,  g_WT1);
    cudaGetSymbolAddress((void**)&pWT2,  g_WT2);

    const int smem0 = 4 * 3 * (128 * 32 * 2);   // 98304 B (GRAM: 4 ops, KC32)
    const int smem1 = 2 * 3 * (128 * 64 * 2);   // 98304 B (HWT/AH: 2 ops, KC64)
    cudaFuncSetAttribute(mma_gemm<0>, cudaFuncAttributeMaxDynamicSharedMemorySize, smem0);
    cudaFuncSetAttribute(mma_gemm<1>, cudaFuncAttributeMaxDynamicSharedMemorySize, smem1);
    cudaFuncSetAttribute(mma_gemm<2>, cudaFuncAttributeMaxDynamicSharedMemorySize, smem1);
    cudaFuncSetAttribute(mma_gemm<3>, cudaFuncAttributeMaxDynamicSharedMemorySize, smem1);

    const int NBLK = C_ / 128;                       // 16
    const int NTRI = NBLK * (NBLK + 1) / 2;          // 136

    // ---- input-only preprocessing (no cross dependencies) ----
    wtrans_kernel<<<dim3(F_ / 32, F_ / 32), dim3(32, 8)>>>(W1, pWT1);
    wtrans_kernel<<<dim3(F_ / 32, F_ / 32), dim3(32, 8)>>>(W2, pWT2);
    norm_split<<<B_ * C_, 128>>>(x, pinvn, pxhi, pxlo, pdeg);

    // ---- Laplacian ----
    mma_gemm<0><<<dim3(NTRI, 1, B_), 256, smem0>>>(
        pxhi, pxlo, pxhi, pxlo, F_, F_, F_,
        (size_t)C_ * F_, (size_t)C_ * F_, pinvn, C_, nullptr,
        pA, C_, (size_t)C_ * C_, pdeg);
    dinv_kernel<<<(B_ * C_) / 256, 256>>>(pdeg, pdinv);

    // ---- layer 1: relu(L @ (x @ W1) + b1) ----
    mma_gemm<2><<<dim3(F_ / 128, (B_ * C_) / 128, 1), 256, smem1>>>(
        pxhi, nullptr, pWT1, nullptr, F_, F_, F_,
        0, 0, pdinv, 0, nullptr,
        pgT, C_, 0, nullptr);
    mma_gemm<1><<<dim3(F_ / 128, C_ / 128, B_), 256, smem1>>>(
        pA, nullptr, pgT, nullptr, C_, C_, C_,
        (size_t)C_ * C_, (size_t)F_ * C_, pdinv, C_, b1,
        ph2, F_, (size_t)C_ * F_, nullptr);

    // ---- layer 2: relu(L @ (h2 @ W2) + b2) ----
    mma_gemm<2><<<dim3(F_ / 128, (B_ * C_) / 128, 1), 256, smem1>>>(
        ph2, nullptr, pWT2, nullptr, F_, F_, F_,
        0, 0, pdinv, 0, nullptr,
        pgT, C_, 0, nullptr);
    mma_gemm<3><<<dim3(F_ / 128, C_ / 128, B_), 256, smem1>>>(
        pA, nullptr, pgT, nullptr, C_, C_, C_,
        (size_t)C_ * C_, (size_t)F_ * C_, pdinv, C_, b2,
        out, F_, (size_t)C_ * F_, nullptr);
}